// round 4
// baseline (speedup 1.0000x reference)
#include <cuda_runtime.h>
#include <math.h>

#define NB 256
#define NR 1152
#define NC2 10
#define NO 16
#define NI 8

typedef unsigned long long u64;

// ------------- packed f32x2 helpers -------------
__device__ __forceinline__ u64 fma2(u64 a, u64 b, u64 c) {
    u64 d;
    asm("fma.rn.f32x2 %0, %1, %2, %3;" : "=l"(d) : "l"(a), "l"(b), "l"(c));
    return d;
}
__device__ __forceinline__ u64 pk2(float v) {           // (v, v)
    u64 r;
    asm("mov.b64 %0, {%1, %1};" : "=l"(r) : "f"(v));
    return r;
}
__device__ __forceinline__ u64 f2pk(float lo, float hi) {
    return (u64)__float_as_uint(lo) | ((u64)__float_as_uint(hi) << 32);
}
__device__ __forceinline__ float f2lo(u64 v) { return __uint_as_float((unsigned)v); }
__device__ __forceinline__ float f2hi(u64 v) { return __uint_as_float((unsigned)(v >> 32)); }

// ------------- scratch (device globals) -------------
__device__ float g_pool1[(size_t)NB * 64 * 38 * 38];
__device__ float g_pool2[(size_t)NB * 128 * 20 * 20];
__device__ u64   g_wT2[(size_t)10368 * 128];           // packed (oc, oc+128) prim weights [k][t]
__device__ float g_uraw[(size_t)NB * 9216];
__device__ float g_u[(size_t)NB * 9216];
__device__ float g_uhat[(size_t)NB * NR * NC2 * NO];
__device__ float g_bij[NR * NC2];
__device__ float g_cij[NR * NC2];
__device__ float g_v[NB * NC2 * NO];

// ------------- zero b_ij -------------
__global__ void k_zero() {
    int i = blockIdx.x * blockDim.x + threadIdx.x;
    if (i < NR * NC2) g_bij[i] = 0.f;
}

// ------------- conv1(3->64,3x3,valid)+ReLU+maxpool(2,2,pad1) -------------
__global__ void __launch_bounds__(256) k_conv1pool(const float* __restrict__ data,
                                                   const float* __restrict__ w1,
                                                   const float* __restrict__ b1) {
    int idx = blockIdx.x * blockDim.x + threadIdx.x;   // B*1444 threads
    int p = idx % 1444;
    int b = idx / 1444;
    int pj = p / 38, pi = p % 38;
    int y0 = 2 * pj - 1, x0 = 2 * pi - 1;

    float iv[3][4][4];
#pragma unroll
    for (int ic = 0; ic < 3; ic++)
#pragma unroll
        for (int dy = 0; dy < 4; dy++) {
            int yy = y0 + dy;
#pragma unroll
            for (int dx = 0; dx < 4; dx++) {
                int xx = x0 + dx;
                float v = 0.f;
                if (yy >= 0 && yy < 76 && xx >= 0 && xx < 76)
                    v = data[((size_t)(b * 3 + ic) * 76 + yy) * 76 + xx];
                iv[ic][dy][dx] = v;
            }
        }

    bool rv0 = (y0 >= 0), rv1 = (y0 + 1 <= 73);
    bool cv0 = (x0 >= 0), cv1 = (x0 + 1 <= 73);
    size_t obase = (size_t)b * 64 * 1444 + (size_t)pj * 38 + pi;

#pragma unroll 1
    for (int oc = 0; oc < 64; oc++) {
        const float* wp = w1 + oc * 27;
        float s00 = 0.f, s01 = 0.f, s10 = 0.f, s11 = 0.f;
#pragma unroll
        for (int k = 0; k < 27; k++) {
            int ic = k / 9, r = (k / 3) % 3, c2 = k % 3;
            float w = __ldg(wp + k);
            s00 = fmaf(iv[ic][r][c2],         w, s00);
            s01 = fmaf(iv[ic][r][c2 + 1],     w, s01);
            s10 = fmaf(iv[ic][r + 1][c2],     w, s10);
            s11 = fmaf(iv[ic][r + 1][c2 + 1], w, s11);
        }
        float bo = __ldg(b1 + oc);
        float m = 0.f;
        if (rv0 && cv0) m = fmaxf(m, s00 + bo);
        if (rv0 && cv1) m = fmaxf(m, s01 + bo);
        if (rv1 && cv0) m = fmaxf(m, s10 + bo);
        if (rv1 && cv1) m = fmaxf(m, s11 + bo);
        g_pool1[obase + (size_t)oc * 1444] = m;
    }
}

// ------------- conv2(64->128,3x3,pad1)+ReLU+maxpool(2,2,pad1), f32x2 -------------
// block (64,4): tx = oc pair (tx, tx+64), ty = conv row r0+ty with r0 = 4*bx-1.
// Each block produces pool rows p0=2*bx, p0+1 for all 128 oc of one image.
__global__ void __launch_bounds__(256) k_conv2pool(const float* __restrict__ w2,
                                                   const float* __restrict__ b2) {
    __shared__ __align__(16) float sm[11136];          // 44.5 KB
    float* s_in = sm;                                  // 8*6*40 = 1920 floats
    u64*   s_w2 = (u64*)(sm + 1920);                   // 72*64 packed weights

    int b = blockIdx.y;
    int r0 = (int)blockIdx.x * 4 - 1;
    int tx = threadIdx.x;
    int ty = threadIdx.y;
    int tid = ty * 64 + tx;
    int row = r0 + ty;
    bool rowok = (row >= 0 && row < 38);

    u64 acc2[38];
#pragma unroll
    for (int x = 0; x < 38; x++) acc2[x] = 0ull;

#pragma unroll 1
    for (int ic0 = 0; ic0 < 64; ic0 += 8) {
        __syncthreads();
        for (int i = tid; i < 1920; i += 256) {
            int ic = i / 240, rem = i % 240;
            int rr = rem / 40, cc = rem % 40;
            int gr = r0 - 1 + rr, gc = cc - 1;
            float vv = 0.f;
            if (gr >= 0 && gr < 38 && gc >= 0 && gc < 38)
                vv = g_pool1[(((size_t)b * 64 + ic0 + ic) * 38 + gr) * 38 + gc];
            s_in[i] = vv;
        }
        for (int i = tid; i < 4608; i += 256) {
            int k = i >> 6, j = i & 63;
            s_w2[i] = f2pk(w2[(size_t)j * 576 + ic0 * 9 + k],
                           w2[(size_t)(j + 64) * 576 + ic0 * 9 + k]);
        }
        __syncthreads();

        if (rowok) {
#pragma unroll 1
            for (int icl = 0; icl < 8; icl++) {
#pragma unroll
                for (int ky = 0; ky < 3; ky++) {
                    const float* irow = s_in + icl * 240 + (ty + ky) * 40;
                    const u64* wr = s_w2 + (icl * 9 + ky * 3) * 64;
                    u64 w0 = wr[tx], w1 = wr[64 + tx], w2p = wr[128 + tx];
                    u64 pv0 = pk2(irow[0]), pv1 = pk2(irow[1]);
#pragma unroll
                    for (int x = 0; x < 38; x++) {
                        u64 pv2 = pk2(irow[x + 2]);
                        acc2[x] = fma2(pv2, w2p, fma2(pv1, w1, fma2(pv0, w0, acc2[x])));
                        pv0 = pv1; pv1 = pv2;
                    }
                }
            }
        }
    }

    // ---- fused maxpool (2,2,pad1): stage relu'd rows in smem, pool, store ----
    float bA = __ldg(b2 + tx), bB = __ldg(b2 + tx + 64);
    float* s_pool = sm;                                // 4*38*64 = 9728 floats
    int p0 = (int)blockIdx.x * 2;

#pragma unroll 1
    for (int half = 0; half < 2; half++) {
        __syncthreads();
        float bb = half ? bB : bA;
#pragma unroll
        for (int x = 0; x < 38; x++) {
            float v = half ? f2hi(acc2[x]) : f2lo(acc2[x]);
            s_pool[(ty * 38 + x) * 64 + tx] = rowok ? fmaxf(v + bb, 0.f) : 0.f;
        }
        __syncthreads();
        for (int j = tid; j < 2560; j += 256) {
            int pi = j % 20;
            int pr = (j / 20) & 1;
            int oc = j / 40;
            int x0 = 2 * pi - 1;
            int tA = 2 * pr, tB = 2 * pr + 1;          // local conv rows for pool row p0+pr
            float m = 0.f;
            if (x0 >= 0)
                m = fmaxf(m, fmaxf(s_pool[(tA * 38 + x0) * 64 + oc],
                                   s_pool[(tB * 38 + x0) * 64 + oc]));
            if (x0 + 1 <= 37)
                m = fmaxf(m, fmaxf(s_pool[(tA * 38 + x0 + 1) * 64 + oc],
                                   s_pool[(tB * 38 + x0 + 1) * 64 + oc]));
            g_pool2[((size_t)(b * 128 + oc + half * 64) * 20 + p0 + pr) * 20 + pi] = m;
        }
    }
}

// ------------- pack prim weights: (oc, oc+128) pairs, [k][t] -------------
__global__ void k_wT2(const float* __restrict__ pw) {
    int i = blockIdx.x * blockDim.x + threadIdx.x;     // 10368*128 threads
    int k = i >> 7, t = i & 127;
    g_wT2[i] = f2pk(pw[(size_t)t * 10368 + k], pw[(size_t)(t + 128) * 10368 + k]);
}

// ------------- PrimaryCaps conv (128->256, 9x9, s2, 6x6 out), f32x2 -------------
// grid (B, 2): blockIdx.y selects sj rows [3*y, 3*y+2]. 128 threads, 2 oc each.
__global__ void __launch_bounds__(128) k_prim(const float* __restrict__ pb) {
    __shared__ float s_in[16 * 260];                   // 16 ic x 13 rows x 20 cols
    int b = blockIdx.x;
    int sj0 = blockIdx.y * 3;
    int t = threadIdx.x;

    u64 acc2[18];
#pragma unroll
    for (int s = 0; s < 18; s++) acc2[s] = 0ull;

#pragma unroll 1
    for (int ic0 = 0; ic0 < 128; ic0 += 16) {
        __syncthreads();
        for (int i = t; i < 4160; i += 128) {
            int ic = i / 260, rem = i % 260;
            int rr = rem / 20, cc = rem % 20;
            s_in[i] = g_pool2[((size_t)(b * 128 + ic0 + ic) * 20 + 2 * sj0 + rr) * 20 + cc];
        }
        __syncthreads();

#pragma unroll 1
        for (int icl = 0; icl < 16; icl++) {
#pragma unroll 1
            for (int ky = 0; ky < 9; ky++) {
                const u64* wp = g_wT2 + ((size_t)(ic0 + icl) * 81 + ky * 9) * 128 + t;
                u64 w[9];
#pragma unroll
                for (int kx = 0; kx < 9; kx++) w[kx] = wp[(size_t)kx * 128];
#pragma unroll
                for (int sl = 0; sl < 3; sl++) {
                    const float* rp = s_in + icl * 260 + (2 * sl + ky) * 20;
                    u64 pv[19];
#pragma unroll
                    for (int x = 0; x < 19; x++) pv[x] = pk2(rp[x]);
#pragma unroll
                    for (int si = 0; si < 6; si++)
#pragma unroll
                        for (int kx = 0; kx < 9; kx++)
                            acc2[sl * 6 + si] = fma2(pv[2 * si + kx], w[kx], acc2[sl * 6 + si]);
                }
            }
        }
    }

    float b0 = __ldg(pb + t), b1 = __ldg(pb + t + 128);
    float* o0 = g_uraw + (size_t)b * 9216 + t * 36 + sj0 * 6;
    float* o1 = g_uraw + (size_t)b * 9216 + (t + 128) * 36 + sj0 * 6;
#pragma unroll
    for (int j = 0; j < 18; j++) {
        o0[j] = f2lo(acc2[j]) + b0;
        o1[j] = f2hi(acc2[j]) + b1;
    }
}

// ------------- squash u over groups of 8 -------------
__global__ void k_squash() {
    int idx = blockIdx.x * blockDim.x + threadIdx.x;
    if (idx >= NB * NR) return;
    const float4* p = (const float4*)(g_uraw + (size_t)idx * 8);
    float4 a = p[0], c = p[1];
    float sn = a.x*a.x + a.y*a.y + a.z*a.z + a.w*a.w +
               c.x*c.x + c.y*c.y + c.z*c.z + c.w*c.w;
    float f = sqrtf(sn) / (1.0f + sn);
    float4* o = (float4*)(g_u + (size_t)idx * 8);
    a.x*=f; a.y*=f; a.z*=f; a.w*=f; c.x*=f; c.y*=f; c.z*=f; c.w*=f;
    o[0] = a; o[1] = c;
}

// ------------- u_hat[b,r,c,o] = sum_i W[r,c,o,i]*u[b,r,i] -------------
__global__ void __launch_bounds__(160) k_uhat(const float* __restrict__ W) {
    __shared__ float sWT[1280];
    int r = blockIdx.x;
    int t = threadIdx.x;
    for (int j = t; j < 1280; j += 160)
        sWT[j] = W[(size_t)r * 1280 + (j % 160) * 8 + j / 160];
    __syncthreads();

    float w0 = sWT[0*160+t], w1 = sWT[1*160+t], w2 = sWT[2*160+t], w3 = sWT[3*160+t];
    float w4 = sWT[4*160+t], w5 = sWT[5*160+t], w6 = sWT[6*160+t], w7 = sWT[7*160+t];

#pragma unroll 4
    for (int b = 0; b < NB; b++) {
        const float4* up = (const float4*)(g_u + (size_t)b * 9216 + r * 8);
        float4 ua = up[0], ub = up[1];
        float acc = ua.x*w0 + ua.y*w1 + ua.z*w2 + ua.w*w3
                  + ub.x*w4 + ub.y*w5 + ub.z*w6 + ub.w*w7;
        g_uhat[((size_t)b * NR + r) * 160 + t] = acc;
    }
}

// ------------- softmax over routes per class -------------
__global__ void k_softmax() {
    __shared__ float sred[128];
    int c = blockIdx.x;
    int t = threadIdx.x;
    float mx = -1e30f;
    for (int r = t; r < NR; r += 128) mx = fmaxf(mx, g_bij[r * NC2 + c]);
    sred[t] = mx; __syncthreads();
    for (int st = 64; st >= 1; st >>= 1) { if (t < st) sred[t] = fmaxf(sred[t], sred[t + st]); __syncthreads(); }
    mx = sred[0]; __syncthreads();
    float sm = 0.f;
    for (int r = t; r < NR; r += 128) sm += expf(g_bij[r * NC2 + c] - mx);
    sred[t] = sm; __syncthreads();
    for (int st = 64; st >= 1; st >>= 1) { if (t < st) sred[t] += sred[t + st]; __syncthreads(); }
    float inv = 1.0f / sred[0];
    for (int r = t; r < NR; r += 128)
        g_cij[r * NC2 + c] = expf(g_bij[r * NC2 + c] - mx) * inv;
}

// ------------- s_j + squash -> v -------------
__global__ void __launch_bounds__(256) k_sj(float* out) {
    __shared__ float sred[256];
    int b = blockIdx.x, c = blockIdx.y;
    int t = threadIdx.x;
    int o = t & 15, rg = t >> 4;
    float acc = 0.f;
    for (int r = rg; r < NR; r += 16) {
        float cij = __ldg(g_cij + r * NC2 + c);
        acc = fmaf(cij, g_uhat[(((size_t)b * NR + r) * NC2 + c) * 16 + o], acc);
    }
    sred[t] = acc; __syncthreads();
    for (int st = 8; st >= 1; st >>= 1) {
        if (rg < st) sred[t] += sred[t + st * 16];
        __syncthreads();
    }
    if (rg == 0) {
        float s = sred[o];
        float v = s * fabsf(s) / (1.0f + s * s);
        g_v[(b * NC2 + c) * 16 + o] = v;
        if (out) out[(b * NC2 + c) * 16 + o] = v;
    }
}

// ------------- a_ij accumulate into b_ij -------------
__global__ void __launch_bounds__(128) k_aij() {
    __shared__ float sred[128];
    int r = blockIdx.x, c = blockIdx.y;
    int t = threadIdx.x;
    int o = t & 15, bg = t >> 4;
    float acc = 0.f;
    for (int b = bg; b < NB; b += 8)
        acc = fmaf(g_uhat[(((size_t)b * NR + r) * NC2 + c) * 16 + o],
                   __ldg(g_v + (b * NC2 + c) * 16 + o), acc);
    sred[t] = acc; __syncthreads();
    for (int st = 64; st >= 1; st >>= 1) { if (t < st) sred[t] += sred[t + st]; __syncthreads(); }
    if (t == 0) g_bij[r * NC2 + c] += sred[0] * (1.0f / NB);
}

// ------------- classifiers -------------
__global__ void __launch_bounds__(128) k_cls(const float* __restrict__ w1,
                                             const float* __restrict__ b1,
                                             const float* __restrict__ w2,
                                             const float* __restrict__ b2,
                                             float* out) {
    __shared__ float sfeat[160];
    __shared__ float sred[128];
    int b = blockIdx.x, k = blockIdx.y;
    int t = threadIdx.x;
    for (int j = t; j < 160; j += 128) sfeat[j] = g_v[b * 160 + j];
    __syncthreads();

    float val = 0.f;
    if (t < 100) {
        float acc = __ldg(b1 + k * 100 + t);
        const float* wp = w1 + (size_t)k * 16000 + t;
#pragma unroll 4
        for (int f = 0; f < 160; f++)
            acc = fmaf(sfeat[f], wp[f * 100], acc);
        acc = fmaxf(acc, 0.f);
        val = acc * __ldg(w2 + k * 100 + t);
    }
    sred[t] = val; __syncthreads();
    for (int st = 64; st >= 1; st >>= 1) { if (t < st) sred[t] += sred[t + st]; __syncthreads(); }
    if (t == 0) {
        float logit = sred[0] + __ldg(b2 + k);
        out[40960 + b * NC2 + k] = 1.0f / (1.0f + expf(-logit));
    }
}

extern "C" void kernel_launch(void* const* d_in, const int* in_sizes, int n_in,
                              void* d_out, int out_size) {
    const float* data    = (const float*)d_in[0];
    const float* conv1_w = (const float*)d_in[1];
    const float* conv1_b = (const float*)d_in[2];
    const float* conv2_w = (const float*)d_in[3];
    const float* conv2_b = (const float*)d_in[4];
    const float* prim_w  = (const float*)d_in[5];
    const float* prim_b  = (const float*)d_in[6];
    const float* W       = (const float*)d_in[7];
    const float* cls_w1  = (const float*)d_in[8];
    const float* cls_b1  = (const float*)d_in[9];
    const float* cls_w2  = (const float*)d_in[10];
    const float* cls_b2  = (const float*)d_in[11];
    float* out = (float*)d_out;

    k_zero<<<45, 256>>>();
    k_conv1pool<<<1444, 256>>>(data, conv1_w, conv1_b);
    k_conv2pool<<<dim3(10, NB), dim3(64, 4)>>>(conv2_w, conv2_b);
    k_wT2<<<5184, 256>>>(prim_w);
    k_prim<<<dim3(NB, 2), 128>>>(prim_b);
    k_squash<<<(NB * NR + 255) / 256, 256>>>();
    k_uhat<<<NR, 160>>>(W);

    for (int it = 0; it < 3; it++) {
        k_softmax<<<NC2, 128>>>();
        k_sj<<<dim3(NB, NC2), 256>>>(it == 2 ? out : nullptr);
        if (it < 2) k_aij<<<dim3(NR, NC2), 128>>>();
    }
    k_cls<<<dim3(NB, NC2), 128>>>(cls_w1, cls_b1, cls_w2, cls_b2, out);
}

// round 6
// speedup vs baseline: 1.1219x; 1.1219x over previous
#include <cuda_runtime.h>
#include <cuda_bf16.h>
#include <math.h>
#include <stdint.h>

#define NB 256
#define NR 1152
#define NC2 10
typedef unsigned long long u64;

__device__ __forceinline__ u64 fma2(u64 a, u64 b, u64 c) {
    u64 d; asm("fma.rn.f32x2 %0, %1, %2, %3;" : "=l"(d) : "l"(a), "l"(b), "l"(c)); return d;
}
__device__ __forceinline__ u64 pk2(float v) {
    u64 r; asm("mov.b64 %0, {%1, %1};" : "=l"(r) : "f"(v)); return r;
}
__device__ __forceinline__ u64 f2pk(float lo, float hi) {
    return (u64)__float_as_uint(lo) | ((u64)__float_as_uint(hi) << 32);
}
__device__ __forceinline__ float f2lo(u64 v) { return __uint_as_float((unsigned)v); }
__device__ __forceinline__ float f2hi(u64 v) { return __uint_as_float((unsigned)(v >> 32)); }

__device__ __forceinline__ void mma16816(float* d, unsigned a0, unsigned a1, unsigned a2, unsigned a3,
                                         unsigned b0, unsigned b1) {
    asm volatile("mma.sync.aligned.m16n8k16.row.col.f32.bf16.bf16.f32 "
        "{%0,%1,%2,%3}, {%4,%5,%6,%7}, {%8,%9}, {%0,%1,%2,%3};"
        : "+f"(d[0]), "+f"(d[1]), "+f"(d[2]), "+f"(d[3])
        : "r"(a0), "r"(a1), "r"(a2), "r"(a3), "r"(b0), "r"(b1));
}
__device__ __forceinline__ void bfsplit(float f, __nv_bfloat16& h, __nv_bfloat16& l) {
    h = __float2bfloat16(f);
    l = __float2bfloat16(f - __bfloat162float(h));
}

// ---- scratch ----
__device__ float g_pool1[(size_t)NB * 64 * 1444];
__device__ float g_c2[(size_t)NB * 1444 * 128];      // conv2 out [b][p][oc]
__device__ float g_pool2[(size_t)NB * 128 * 400];    // channel-major
__device__ u64   g_wT2[(size_t)10368 * 128];
__device__ float g_uraw[(size_t)NB * 9216];
__device__ float g_u[(size_t)NB * 9216];
__device__ float g_uhat[(size_t)NB * NR * NC2 * 16];
__device__ float g_bij[NR * NC2];
__device__ float g_cij[NR * NC2];
__device__ float g_v[NB * NC2 * 16];

__global__ void k_zero() {
    int i = blockIdx.x * blockDim.x + threadIdx.x;
    if (i < NR * NC2) g_bij[i] = 0.f;
}

// ---- conv1+relu+pool ----
__global__ void __launch_bounds__(256) k_conv1pool(const float* __restrict__ data,
                                                   const float* __restrict__ w1,
                                                   const float* __restrict__ b1) {
    int idx = blockIdx.x * blockDim.x + threadIdx.x;
    int p = idx % 1444, b = idx / 1444;
    int pj = p / 38, pi = p % 38;
    int y0 = 2 * pj - 1, x0 = 2 * pi - 1;
    float iv[3][4][4];
#pragma unroll
    for (int ic = 0; ic < 3; ic++)
#pragma unroll
        for (int dy = 0; dy < 4; dy++) {
            int yy = y0 + dy;
#pragma unroll
            for (int dx = 0; dx < 4; dx++) {
                int xx = x0 + dx;
                float v = 0.f;
                if (yy >= 0 && yy < 76 && xx >= 0 && xx < 76)
                    v = data[((size_t)(b * 3 + ic) * 76 + yy) * 76 + xx];
                iv[ic][dy][dx] = v;
            }
        }
    bool rv0 = (y0 >= 0), rv1 = (y0 + 1 <= 73), cv0 = (x0 >= 0), cv1 = (x0 + 1 <= 73);
    size_t obase = (size_t)b * 64 * 1444 + (size_t)pj * 38 + pi;
#pragma unroll 1
    for (int oc = 0; oc < 64; oc++) {
        const float* wp = w1 + oc * 27;
        float s00 = 0.f, s01 = 0.f, s10 = 0.f, s11 = 0.f;
#pragma unroll
        for (int k = 0; k < 27; k++) {
            int ic = k / 9, r = (k / 3) % 3, c2 = k % 3;
            float w = __ldg(wp + k);
            s00 = fmaf(iv[ic][r][c2], w, s00);
            s01 = fmaf(iv[ic][r][c2 + 1], w, s01);
            s10 = fmaf(iv[ic][r + 1][c2], w, s10);
            s11 = fmaf(iv[ic][r + 1][c2 + 1], w, s11);
        }
        float bo = __ldg(b1 + oc), m = 0.f;
        if (rv0 && cv0) m = fmaxf(m, s00 + bo);
        if (rv0 && cv1) m = fmaxf(m, s01 + bo);
        if (rv1 && cv0) m = fmaxf(m, s10 + bo);
        if (rv1 && cv1) m = fmaxf(m, s11 + bo);
        g_pool1[obase + (size_t)oc * 1444] = m;
    }
}

// ---- conv2 via mma.sync bf16x3 (implicit im2col GEMM) ----
// block: M=128 positions x N=128 oc, K=576 in 18 chunks of 32. 8 warps x 16 rows.
#define LDA 40
__global__ void __launch_bounds__(256) k_conv2mma(const float* __restrict__ w2,
                                                  const float* __restrict__ b2) {
    __shared__ __nv_bfloat16 sAh[128 * LDA], sAl[128 * LDA], sBh[128 * LDA], sBl[128 * LDA];
    int tid = threadIdx.x;
    int w = tid >> 5, lane = tid & 31;
    int g = lane >> 2, tg = lane & 3;
    int bb = blockIdx.y, strip = blockIdx.x;

    float acc[16][4];
#pragma unroll
    for (int n = 0; n < 16; n++)
#pragma unroll
        for (int q = 0; q < 4; q++) acc[n][q] = 0.f;

    int pA = strip * 128 + (tid & 127);
    int yA = pA / 38, xA = pA % 38;
    bool pvA = pA < 1444;

#pragma unroll 1
    for (int kc = 0; kc < 18; kc++) {
        __syncthreads();
        if (tid < 128) {                       // A: im2col row m = tid, 32 k's
            int k0 = kc * 32, ic = k0 / 9, r = k0 - ic * 9;
            int ky = r / 3, kx = r - ky * 3;
            const float* src = g_pool1 + ((size_t)bb * 64 + ic) * 1444;
            int m = tid;
#pragma unroll 1
            for (int kk = 0; kk < 32; kk++) {
                int yy = yA + ky - 1, xx = xA + kx - 1;
                float f = 0.f;
                if (pvA && yy >= 0 && yy < 38 && xx >= 0 && xx < 38) f = src[yy * 38 + xx];
                __nv_bfloat16 h, l; bfsplit(f, h, l);
                sAh[m * LDA + kk] = h;
                sAl[m * LDA + kk] = l;
                if (++kx == 3) { kx = 0; if (++ky == 3) { ky = 0; ic++; src += 1444; } }
            }
        } else {                               // B: weights K-major
            int n = tid - 128;
            const float* ws = w2 + (size_t)n * 576 + kc * 32;
#pragma unroll
            for (int gq = 0; gq < 8; gq++) {
                float4 f4 = __ldg((const float4*)(ws + gq * 4));
                float ff[4] = {f4.x, f4.y, f4.z, f4.w};
#pragma unroll
                for (int q = 0; q < 4; q++) {
                    __nv_bfloat16 h, l; bfsplit(ff[q], h, l);
                    sBh[n * LDA + gq * 4 + q] = h;
                    sBl[n * LDA + gq * 4 + q] = l;
                }
            }
        }
        __syncthreads();

#pragma unroll
        for (int ks = 0; ks < 2; ks++) {
            int arow = (w * 16 + g) * LDA + ks * 16 + tg * 2;
            unsigned ah0 = *(const unsigned*)(sAh + arow);
            unsigned ah1 = *(const unsigned*)(sAh + arow + 8 * LDA);
            unsigned ah2 = *(const unsigned*)(sAh + arow + 8);
            unsigned ah3 = *(const unsigned*)(sAh + arow + 8 * LDA + 8);
            unsigned al0 = *(const unsigned*)(sAl + arow);
            unsigned al1 = *(const unsigned*)(sAl + arow + 8 * LDA);
            unsigned al2 = *(const unsigned*)(sAl + arow + 8);
            unsigned al3 = *(const unsigned*)(sAl + arow + 8 * LDA + 8);
#pragma unroll
            for (int nt = 0; nt < 16; nt++) {
                int brow = (nt * 8 + g) * LDA + ks * 16 + tg * 2;
                unsigned bh0 = *(const unsigned*)(sBh + brow);
                unsigned bh1 = *(const unsigned*)(sBh + brow + 8);
                unsigned bl0 = *(const unsigned*)(sBl + brow);
                unsigned bl1 = *(const unsigned*)(sBl + brow + 8);
                mma16816(acc[nt], ah0, ah1, ah2, ah3, bh0, bh1);
                mma16816(acc[nt], al0, al1, al2, al3, bh0, bh1);
                mma16816(acc[nt], ah0, ah1, ah2, ah3, bl0, bl1);
            }
        }
    }

    // epilogue: bias + relu, store [b][p][oc]
    int p0 = strip * 128 + w * 16 + g;
    int p1 = p0 + 8;
#pragma unroll
    for (int nt = 0; nt < 16; nt++) {
        int col = nt * 8 + tg * 2;
        float bc0 = __ldg(b2 + col), bc1 = __ldg(b2 + col + 1);
        if (p0 < 1444) {
            float2 o; o.x = fmaxf(acc[nt][0] + bc0, 0.f); o.y = fmaxf(acc[nt][1] + bc1, 0.f);
            *(float2*)(g_c2 + ((size_t)bb * 1444 + p0) * 128 + col) = o;
        }
        if (p1 < 1444) {
            float2 o; o.x = fmaxf(acc[nt][2] + bc0, 0.f); o.y = fmaxf(acc[nt][3] + bc1, 0.f);
            *(float2*)(g_c2 + ((size_t)bb * 1444 + p1) * 128 + col) = o;
        }
    }
}

// ---- maxpool [b][p][oc] -> channel-major g_pool2 ----
__global__ void __launch_bounds__(256) k_pool2n() {
    __shared__ float s[16 * 129];
    int b = blockIdx.y, t0 = blockIdx.x;
    int tid = threadIdx.x;
    for (int i = tid; i < 2048; i += 256) {
        int p2l = i >> 7, oc = i & 127;
        int p2 = t0 * 16 + p2l;
        int pj = p2 / 20, pi = p2 % 20;
        int y0 = 2 * pj - 1, x0 = 2 * pi - 1;
        float m = 0.f;
#pragma unroll
        for (int dy = 0; dy < 2; dy++) {
            int y = y0 + dy; if (y < 0 || y > 37) continue;
#pragma unroll
            for (int dx = 0; dx < 2; dx++) {
                int x = x0 + dx; if (x < 0 || x > 37) continue;
                m = fmaxf(m, g_c2[((size_t)b * 1444 + y * 38 + x) * 128 + oc]);
            }
        }
        s[p2l * 129 + oc] = m;
    }
    __syncthreads();
    for (int i = tid; i < 2048; i += 256) {
        int oc = i >> 4, p2l = i & 15;
        g_pool2[((size_t)(b * 128 + oc)) * 400 + t0 * 16 + p2l] = s[p2l * 129 + oc];
    }
}

__global__ void k_wT2(const float* __restrict__ pw) {
    int i = blockIdx.x * blockDim.x + threadIdx.x;
    int k = i >> 7, t = i & 127;
    g_wT2[i] = f2pk(pw[(size_t)t * 10368 + k], pw[(size_t)(t + 128) * 10368 + k]);
}

// ---- PrimaryCaps conv, scalar ----
__global__ void __launch_bounds__(128) k_prim(const float* __restrict__ pb) {
    __shared__ float s_in[16 * 260];
    int b = blockIdx.x, sj0 = blockIdx.y * 3, t = threadIdx.x;
    u64 acc2[18];
#pragma unroll
    for (int s = 0; s < 18; s++) acc2[s] = 0ull;
#pragma unroll 1
    for (int ic0 = 0; ic0 < 128; ic0 += 16) {
        __syncthreads();
        for (int i = t; i < 4160; i += 128) {
            int ic = i / 260, rem = i % 260;
            s_in[i] = g_pool2[((size_t)(b * 128 + ic0 + ic) * 20 + 2 * sj0 + rem / 20) * 20 + rem % 20];
        }
        __syncthreads();
#pragma unroll 1
        for (int icl = 0; icl < 16; icl++) {
#pragma unroll 1
            for (int ky = 0; ky < 9; ky++) {
                const u64* wp = g_wT2 + ((size_t)(ic0 + icl) * 81 + ky * 9) * 128 + t;
                u64 w[9];
#pragma unroll
                for (int kx = 0; kx < 9; kx++) w[kx] = wp[(size_t)kx * 128];
#pragma unroll
                for (int sl = 0; sl < 3; sl++) {
                    const float* rp = s_in + icl * 260 + (2 * sl + ky) * 20;
                    u64 pv[19];
#pragma unroll
                    for (int x = 0; x < 19; x++) pv[x] = pk2(rp[x]);
#pragma unroll
                    for (int si = 0; si < 6; si++)
#pragma unroll
                        for (int kx = 0; kx < 9; kx++)
                            acc2[sl * 6 + si] = fma2(pv[2 * si + kx], w[kx], acc2[sl * 6 + si]);
                }
            }
        }
    }
    float b0 = __ldg(pb + t), b1 = __ldg(pb + t + 128);
    float* o0 = g_uraw + (size_t)b * 9216 + t * 36 + sj0 * 6;
    float* o1 = g_uraw + (size_t)b * 9216 + (t + 128) * 36 + sj0 * 6;
#pragma unroll
    for (int j = 0; j < 18; j++) { o0[j] = f2lo(acc2[j]) + b0; o1[j] = f2hi(acc2[j]) + b1; }
}

__global__ void k_squash() {
    int idx = blockIdx.x * blockDim.x + threadIdx.x;
    if (idx >= NB * NR) return;
    const float4* p = (const float4*)(g_uraw + (size_t)idx * 8);
    float4 a = p[0], c = p[1];
    float sn = a.x*a.x + a.y*a.y + a.z*a.z + a.w*a.w + c.x*c.x + c.y*c.y + c.z*c.z + c.w*c.w;
    float f = sqrtf(sn) / (1.0f + sn);
    float4* o = (float4*)(g_u + (size_t)idx * 8);
    a.x*=f; a.y*=f; a.z*=f; a.w*=f; c.x*=f; c.y*=f; c.z*=f; c.w*=f;
    o[0] = a; o[1] = c;
}

__global__ void __launch_bounds__(160) k_uhat(const float* __restrict__ W) {
    __shared__ float sWT[1280];
    int r = blockIdx.x, t = threadIdx.x;
    for (int j = t; j < 1280; j += 160)
        sWT[j] = W[(size_t)r * 1280 + (j % 160) * 8 + j / 160];
    __syncthreads();
    float w0 = sWT[t], w1 = sWT[160+t], w2 = sWT[320+t], w3 = sWT[480+t];
    float w4 = sWT[640+t], w5 = sWT[800+t], w6 = sWT[960+t], w7 = sWT[1120+t];
#pragma unroll 4
    for (int b = 0; b < NB; b++) {
        const float4* up = (const float4*)(g_u + (size_t)b * 9216 + r * 8);
        float4 ua = up[0], ub = up[1];
        g_uhat[((size_t)b * NR + r) * 160 + t] =
            ua.x*w0 + ua.y*w1 + ua.z*w2 + ua.w*w3 + ub.x*w4 + ub.y*w5 + ub.z*w6 + ub.w*w7;
    }
}

__global__ void k_softmax() {
    __shared__ float sred[128];
    int c = blockIdx.x, t = threadIdx.x;
    float mx = -1e30f;
    for (int r = t; r < NR; r += 128) mx = fmaxf(mx, g_bij[r * NC2 + c]);
    sred[t] = mx; __syncthreads();
    for (int st = 64; st >= 1; st >>= 1) { if (t < st) sred[t] = fmaxf(sred[t], sred[t + st]); __syncthreads(); }
    mx = sred[0]; __syncthreads();
    float sm = 0.f;
    for (int r = t; r < NR; r += 128) sm += expf(g_bij[r * NC2 + c] - mx);
    sred[t] = sm; __syncthreads();
    for (int st = 64; st >= 1; st >>= 1) { if (t < st) sred[t] += sred[t + st]; __syncthreads(); }
    float inv = 1.0f / sred[0];
    for (int r = t; r < NR; r += 128)
        g_cij[r * NC2 + c] = expf(g_bij[r * NC2 + c] - mx) * inv;
}

__global__ void __launch_bounds__(256) k_sj(float* out) {
    __shared__ float sred[256];
    int b = blockIdx.x, c = blockIdx.y, t = threadIdx.x;
    int o = t & 15, rg = t >> 4;
    float acc = 0.f;
    for (int r = rg; r < NR; r += 16)
        acc = fmaf(__ldg(g_cij + r * NC2 + c), g_uhat[(((size_t)b * NR + r) * NC2 + c) * 16 + o], acc);
    sred[t] = acc; __syncthreads();
    for (int st = 8; st >= 1; st >>= 1) { if (rg < st) sred[t] += sred[t + st * 16]; __syncthreads(); }
    if (rg == 0) {
        float s = sred[o];
        float v = s * fabsf(s) / (1.0f + s * s);
        g_v[(b * NC2 + c) * 16 + o] = v;
        if (out) out[(b * NC2 + c) * 16 + o] = v;
    }
}

__global__ void __launch_bounds__(128) k_aij() {
    __shared__ float sred[128];
    int r = blockIdx.x, c = blockIdx.y, t = threadIdx.x;
    int o = t & 15, bg = t >> 4;
    float acc = 0.f;
    for (int b = bg; b < NB; b += 8)
        acc = fmaf(g_uhat[(((size_t)b * NR + r) * NC2 + c) * 16 + o],
                   __ldg(g_v + (b * NC2 + c) * 16 + o), acc);
    sred[t] = acc; __syncthreads();
    for (int st = 64; st >= 1; st >>= 1) { if (t < st) sred[t] += sred[t + st]; __syncthreads(); }
    if (t == 0) g_bij[r * NC2 + c] += sred[0] * (1.0f / NB);
}

__global__ void __launch_bounds__(128) k_cls(const float* __restrict__ w1,
                                             const float* __restrict__ b1,
                                             const float* __restrict__ w2,
                                             const float* __restrict__ b2,
                                             float* out) {
    __shared__ float sfeat[160];
    __shared__ float sred[128];
    int b = blockIdx.x, k = blockIdx.y, t = threadIdx.x;
    for (int j = t; j < 160; j += 128) sfeat[j] = g_v[b * 160 + j];
    __syncthreads();
    float val = 0.f;
    if (t < 100) {
        float acc = __ldg(b1 + k * 100 + t);
        const float* wp = w1 + (size_t)k * 16000 + t;
#pragma unroll 4
        for (int f = 0; f < 160; f++) acc = fmaf(sfeat[f], wp[f * 100], acc);
        val = fmaxf(acc, 0.f) * __ldg(w2 + k * 100 + t);
    }
    sred[t] = val; __syncthreads();
    for (int st = 64; st >= 1; st >>= 1) { if (t < st) sred[t] += sred[t + st]; __syncthreads(); }
    if (t == 0)
        out[40960 + b * NC2 + k] = 1.0f / (1.0f + expf(-(sred[0] + __ldg(b2 + k))));
}

extern "C" void kernel_launch(void* const* d_in, const int* in_sizes, int n_in,
                              void* d_out, int out_size) {
    const float* data    = (const float*)d_in[0];
    const float* conv1_w = (const float*)d_in[1];
    const float* conv1_b = (const float*)d_in[2];
    const float* conv2_w = (const float*)d_in[3];
    const float* conv2_b = (const float*)d_in[4];
    const float* prim_w  = (const float*)d_in[5];
    const float* prim_b  = (const float*)d_in[6];
    const float* W       = (const float*)d_in[7];
    const float* cls_w1  = (const float*)d_in[8];
    const float* cls_b1  = (const float*)d_in[9];
    const float* cls_w2  = (const float*)d_in[10];
    const float* cls_b2  = (const float*)d_in[11];
    float* out = (float*)d_out;

    k_zero<<<45, 256>>>();
    k_conv1pool<<<1444, 256>>>(data, conv1_w, conv1_b);
    k_conv2mma<<<dim3(12, NB), 256>>>(conv2_w, conv2_b);
    k_pool2n<<<dim3(25, NB), 256>>>();
    k_wT2<<<5184, 256>>>(prim_w);
    k_prim<<<dim3(NB, 2), 128>>>(prim_b);
    k_squash<<<(NB * NR + 255) / 256, 256>>>();
    k_uhat<<<NR, 160>>>(W);

    for (int it = 0; it < 3; it++) {
        k_softmax<<<NC2, 128>>>();
        k_sj<<<dim3(NB, NC2), 256>>>(it == 2 ? out : nullptr);
        if (it < 2) k_aij<<<dim3(NR, NC2), 128>>>();
    }
    k_cls<<<dim3(NB, NC2), 128>>>(cls_w1, cls_b1, cls_w2, cls_b2, out);
}

// round 7
// speedup vs baseline: 1.1257x; 1.0034x over previous
#include <cuda_runtime.h>
#include <cuda_bf16.h>
#include <math.h>
#include <stdint.h>

#define NB 256
#define NR 1152
#define NC2 10
typedef unsigned long long u64;

__device__ __forceinline__ void mma16816(float* d, unsigned a0, unsigned a1, unsigned a2, unsigned a3,
                                         unsigned b0, unsigned b1) {
    asm volatile("mma.sync.aligned.m16n8k16.row.col.f32.bf16.bf16.f32 "
        "{%0,%1,%2,%3}, {%4,%5,%6,%7}, {%8,%9}, {%0,%1,%2,%3};"
        : "+f"(d[0]), "+f"(d[1]), "+f"(d[2]), "+f"(d[3])
        : "r"(a0), "r"(a1), "r"(a2), "r"(a3), "r"(b0), "r"(b1));
}
__device__ __forceinline__ void bfsplit(float f, __nv_bfloat16& h, __nv_bfloat16& l) {
    h = __float2bfloat16(f);
    l = __float2bfloat16(f - __bfloat162float(h));
}

// ---- scratch ----
__device__ __nv_bfloat16 g_p1h[(size_t)NB * 64 * 1444];   // conv1 out hi/lo [b][ic][p]
__device__ __nv_bfloat16 g_p1l[(size_t)NB * 64 * 1444];
__device__ float g_c2[(size_t)NB * 1444 * 128];           // conv2 out [b][p][oc]
__device__ __nv_bfloat16 g_p2h[(size_t)NB * 128 * 400];   // pool2 hi/lo, channel-major
__device__ __nv_bfloat16 g_p2l[(size_t)NB * 128 * 400];
__device__ __nv_bfloat16 g_w2h[128 * 576];                // conv2 weights hi/lo
__device__ __nv_bfloat16 g_w2l[128 * 576];
__device__ __nv_bfloat16 g_pwh[(size_t)256 * 10368];      // prim weights hi/lo
__device__ __nv_bfloat16 g_pwl[(size_t)256 * 10368];
__device__ float g_uraw[(size_t)NB * 9216];
__device__ float g_u[(size_t)NB * 9216];
__device__ float g_uhat[(size_t)NB * NR * NC2 * 16];
__device__ float g_bij[NR * NC2];
__device__ float g_cij[NR * NC2];
__device__ float g_v[NB * NC2 * 16];

__global__ void k_zero() {
    int i = blockIdx.x * blockDim.x + threadIdx.x;
    if (i < NR * NC2) g_bij[i] = 0.f;
}

// ---- weight pre-conversion ----
__global__ void k_cvt_w2(const float* __restrict__ w2) {
    int i = blockIdx.x * blockDim.x + threadIdx.x;     // 73728
    if (i >= 128 * 576) return;
    __nv_bfloat16 h, l; bfsplit(w2[i], h, l);
    g_w2h[i] = h; g_w2l[i] = l;
}
__global__ void k_cvt_pw(const float* __restrict__ pw) {
    int i = blockIdx.x * blockDim.x + threadIdx.x;     // 2654208
    __nv_bfloat16 h, l; bfsplit(pw[i], h, l);
    g_pwh[i] = h; g_pwl[i] = l;
}

// ---- conv1+relu+pool, bf16 hi/lo output ----
__global__ void __launch_bounds__(256) k_conv1pool(const float* __restrict__ data,
                                                   const float* __restrict__ w1,
                                                   const float* __restrict__ b1) {
    int idx = blockIdx.x * blockDim.x + threadIdx.x;
    int p = idx % 1444, b = idx / 1444;
    int pj = p / 38, pi = p % 38;
    int y0 = 2 * pj - 1, x0 = 2 * pi - 1;
    float iv[3][4][4];
#pragma unroll
    for (int ic = 0; ic < 3; ic++)
#pragma unroll
        for (int dy = 0; dy < 4; dy++) {
            int yy = y0 + dy;
#pragma unroll
            for (int dx = 0; dx < 4; dx++) {
                int xx = x0 + dx;
                float v = 0.f;
                if (yy >= 0 && yy < 76 && xx >= 0 && xx < 76)
                    v = data[((size_t)(b * 3 + ic) * 76 + yy) * 76 + xx];
                iv[ic][dy][dx] = v;
            }
        }
    bool rv0 = (y0 >= 0), rv1 = (y0 + 1 <= 73), cv0 = (x0 >= 0), cv1 = (x0 + 1 <= 73);
    size_t obase = (size_t)b * 64 * 1444 + (size_t)pj * 38 + pi;
#pragma unroll 1
    for (int oc = 0; oc < 64; oc++) {
        const float* wp = w1 + oc * 27;
        float s00 = 0.f, s01 = 0.f, s10 = 0.f, s11 = 0.f;
#pragma unroll
        for (int k = 0; k < 27; k++) {
            int ic = k / 9, r = (k / 3) % 3, c2 = k % 3;
            float w = __ldg(wp + k);
            s00 = fmaf(iv[ic][r][c2], w, s00);
            s01 = fmaf(iv[ic][r][c2 + 1], w, s01);
            s10 = fmaf(iv[ic][r + 1][c2], w, s10);
            s11 = fmaf(iv[ic][r + 1][c2 + 1], w, s11);
        }
        float bo = __ldg(b1 + oc), m = 0.f;
        if (rv0 && cv0) m = fmaxf(m, s00 + bo);
        if (rv0 && cv1) m = fmaxf(m, s01 + bo);
        if (rv1 && cv0) m = fmaxf(m, s10 + bo);
        if (rv1 && cv1) m = fmaxf(m, s11 + bo);
        __nv_bfloat16 h, l; bfsplit(m, h, l);
        g_p1h[obase + (size_t)oc * 1444] = h;
        g_p1l[obase + (size_t)oc * 1444] = l;
    }
}

// ---- conv2 via mma.sync bf16x3 ----
#define LDA 40
__global__ void __launch_bounds__(256) k_conv2mma(const float* __restrict__ b2) {
    __shared__ __nv_bfloat16 sAh[128 * LDA], sAl[128 * LDA], sBh[128 * LDA], sBl[128 * LDA];
    int tid = threadIdx.x;
    int w = tid >> 5, lane = tid & 31;
    int g = lane >> 2, tg = lane & 3;
    int bb = blockIdx.y, strip = blockIdx.x;

    float acc[16][4];
#pragma unroll
    for (int n = 0; n < 16; n++)
#pragma unroll
        for (int q = 0; q < 4; q++) acc[n][q] = 0.f;

    int pA = strip * 128 + (tid & 127);
    int yA = pA / 38, xA = pA % 38;
    bool pvA = pA < 1444;

#pragma unroll 1
    for (int kc = 0; kc < 18; kc++) {
        __syncthreads();
        if (tid < 128) {                       // A: im2col, pre-split bf16
            int k0 = kc * 32, ic = k0 / 9, r = k0 - ic * 9;
            int ky = r / 3, kx = r - ky * 3;
            const __nv_bfloat16* sh = g_p1h + ((size_t)bb * 64 + ic) * 1444;
            const __nv_bfloat16* sl = g_p1l + ((size_t)bb * 64 + ic) * 1444;
            int m = tid;
#pragma unroll 1
            for (int kk = 0; kk < 32; kk++) {
                int yy = yA + ky - 1, xx = xA + kx - 1;
                bool ok = pvA && yy >= 0 && yy < 38 && xx >= 0 && xx < 38;
                sAh[m * LDA + kk] = ok ? sh[yy * 38 + xx] : __nv_bfloat16(0.f);
                sAl[m * LDA + kk] = ok ? sl[yy * 38 + xx] : __nv_bfloat16(0.f);
                if (++kx == 3) { kx = 0; if (++ky == 3) { ky = 0; sh += 1444; sl += 1444; } }
            }
        } else {                               // B: pre-split weights, vector copy
            int n = tid - 128;
            const uint4* wh = (const uint4*)(g_w2h + (size_t)n * 576 + kc * 32);
            const uint4* wl = (const uint4*)(g_w2l + (size_t)n * 576 + kc * 32);
            uint4* dh = (uint4*)(sBh + n * LDA);
            uint4* dl = (uint4*)(sBl + n * LDA);
#pragma unroll
            for (int q = 0; q < 4; q++) { dh[q] = wh[q]; dl[q] = wl[q]; }
        }
        __syncthreads();

#pragma unroll
        for (int ks = 0; ks < 2; ks++) {
            int arow = (w * 16 + g) * LDA + ks * 16 + tg * 2;
            unsigned ah0 = *(const unsigned*)(sAh + arow);
            unsigned ah1 = *(const unsigned*)(sAh + arow + 8 * LDA);
            unsigned ah2 = *(const unsigned*)(sAh + arow + 8);
            unsigned ah3 = *(const unsigned*)(sAh + arow + 8 * LDA + 8);
            unsigned al0 = *(const unsigned*)(sAl + arow);
            unsigned al1 = *(const unsigned*)(sAl + arow + 8 * LDA);
            unsigned al2 = *(const unsigned*)(sAl + arow + 8);
            unsigned al3 = *(const unsigned*)(sAl + arow + 8 * LDA + 8);
#pragma unroll
            for (int nt = 0; nt < 16; nt++) {
                int brow = (nt * 8 + g) * LDA + ks * 16 + tg * 2;
                unsigned bh0 = *(const unsigned*)(sBh + brow);
                unsigned bh1 = *(const unsigned*)(sBh + brow + 8);
                unsigned bl0 = *(const unsigned*)(sBl + brow);
                unsigned bl1 = *(const unsigned*)(sBl + brow + 8);
                mma16816(acc[nt], ah0, ah1, ah2, ah3, bh0, bh1);
                mma16816(acc[nt], al0, al1, al2, al3, bh0, bh1);
                mma16816(acc[nt], ah0, ah1, ah2, ah3, bl0, bl1);
            }
        }
    }

    int p0 = strip * 128 + w * 16 + g;
    int p1 = p0 + 8;
#pragma unroll
    for (int nt = 0; nt < 16; nt++) {
        int col = nt * 8 + tg * 2;
        float bc0 = __ldg(b2 + col), bc1 = __ldg(b2 + col + 1);
        if (p0 < 1444) {
            float2 o; o.x = fmaxf(acc[nt][0] + bc0, 0.f); o.y = fmaxf(acc[nt][1] + bc1, 0.f);
            *(float2*)(g_c2 + ((size_t)bb * 1444 + p0) * 128 + col) = o;
        }
        if (p1 < 1444) {
            float2 o; o.x = fmaxf(acc[nt][2] + bc0, 0.f); o.y = fmaxf(acc[nt][3] + bc1, 0.f);
            *(float2*)(g_c2 + ((size_t)bb * 1444 + p1) * 128 + col) = o;
        }
    }
}

// ---- maxpool [b][p][oc] -> channel-major bf16 hi/lo ----
__global__ void __launch_bounds__(256) k_pool2n() {
    __shared__ float s[16 * 129];
    int b = blockIdx.y, t0 = blockIdx.x;
    int tid = threadIdx.x;
    for (int i = tid; i < 2048; i += 256) {
        int p2l = i >> 7, oc = i & 127;
        int p2 = t0 * 16 + p2l;
        int pj = p2 / 20, pi = p2 % 20;
        int y0 = 2 * pj - 1, x0 = 2 * pi - 1;
        float m = 0.f;
#pragma unroll
        for (int dy = 0; dy < 2; dy++) {
            int y = y0 + dy; if (y < 0 || y > 37) continue;
#pragma unroll
            for (int dx = 0; dx < 2; dx++) {
                int x = x0 + dx; if (x < 0 || x > 37) continue;
                m = fmaxf(m, g_c2[((size_t)b * 1444 + y * 38 + x) * 128 + oc]);
            }
        }
        s[p2l * 129 + oc] = m;
    }
    __syncthreads();
    for (int i = tid; i < 2048; i += 256) {
        int oc = i >> 4, p2l = i & 15;
        __nv_bfloat16 h, l; bfsplit(s[p2l * 129 + oc], h, l);
        size_t o = ((size_t)(b * 128 + oc)) * 400 + t0 * 16 + p2l;
        g_p2h[o] = h; g_p2l[o] = l;
    }
}

// ---- PrimaryCaps via mma.sync bf16x3: M=9216 (B*36), N=256 (2 halves), K=10368 ----
__global__ void __launch_bounds__(256) k_primmma(const float* __restrict__ pb) {
    __shared__ __nv_bfloat16 sAh[128 * LDA], sAl[128 * LDA], sBh[128 * LDA], sBl[128 * LDA];
    int tid = threadIdx.x;
    int w = tid >> 5, lane = tid & 31;
    int g = lane >> 2, tg = lane & 3;
    int mb = blockIdx.x;        // 0..71
    int ny = blockIdx.y;        // 0..1 (N half)

    float acc[16][4];
#pragma unroll
    for (int n = 0; n < 16; n++)
#pragma unroll
        for (int q = 0; q < 4; q++) acc[n][q] = 0.f;

    // A row for staging threads
    int mA = mb * 128 + (tid & 127);
    int bA = mA / 36, posA = mA % 36;
    int sjA = posA / 6, siA = posA % 6;
    const __nv_bfloat16* p2hB = g_p2h + (size_t)bA * 51200;
    const __nv_bfloat16* p2lB = g_p2l + (size_t)bA * 51200;

#pragma unroll 1
    for (int kc = 0; kc < 324; kc++) {
        __syncthreads();
        if (tid < 128) {
            int k0 = kc * 32;
            int ic = k0 / 81, r = k0 - ic * 81;
            int ky = r / 9, kx = r - ky * 9;
            int off = ic * 400 + (2 * sjA + ky) * 20 + 2 * siA + kx;
            int m = tid;
#pragma unroll 1
            for (int kk = 0; kk < 32; kk++) {
                sAh[m * LDA + kk] = p2hB[off];
                sAl[m * LDA + kk] = p2lB[off];
                if (++kx == 9) {
                    kx = 0;
                    if (++ky == 9) { ky = 0; off += 232; }   // -8 -160 +400
                    else off += 12;                           // -8 +20
                } else off++;
            }
        } else {
            int n = tid - 128;
            const uint4* wh = (const uint4*)(g_pwh + (size_t)(ny * 128 + n) * 10368 + kc * 32);
            const uint4* wl = (const uint4*)(g_pwl + (size_t)(ny * 128 + n) * 10368 + kc * 32);
            uint4* dh = (uint4*)(sBh + n * LDA);
            uint4* dl = (uint4*)(sBl + n * LDA);
#pragma unroll
            for (int q = 0; q < 4; q++) { dh[q] = wh[q]; dl[q] = wl[q]; }
        }
        __syncthreads();

#pragma unroll
        for (int ks = 0; ks < 2; ks++) {
            int arow = (w * 16 + g) * LDA + ks * 16 + tg * 2;
            unsigned ah0 = *(const unsigned*)(sAh + arow);
            unsigned ah1 = *(const unsigned*)(sAh + arow + 8 * LDA);
            unsigned ah2 = *(const unsigned*)(sAh + arow + 8);
            unsigned ah3 = *(const unsigned*)(sAh + arow + 8 * LDA + 8);
            unsigned al0 = *(const unsigned*)(sAl + arow);
            unsigned al1 = *(const unsigned*)(sAl + arow + 8 * LDA);
            unsigned al2 = *(const unsigned*)(sAl + arow + 8);
            unsigned al3 = *(const unsigned*)(sAl + arow + 8 * LDA + 8);
#pragma unroll
            for (int nt = 0; nt < 16; nt++) {
                int brow = (nt * 8 + g) * LDA + ks * 16 + tg * 2;
                unsigned bh0 = *(const unsigned*)(sBh + brow);
                unsigned bh1 = *(const unsigned*)(sBh + brow + 8);
                unsigned bl0 = *(const unsigned*)(sBl + brow);
                unsigned bl1 = *(const unsigned*)(sBl + brow + 8);
                mma16816(acc[nt], ah0, ah1, ah2, ah3, bh0, bh1);
                mma16816(acc[nt], al0, al1, al2, al3, bh0, bh1);
                mma16816(acc[nt], ah0, ah1, ah2, ah3, bl0, bl1);
            }
        }
    }

    // epilogue: u_raw[b][oc*36 + pos] = acc + pb[oc]
    int m0 = mb * 128 + w * 16 + g;
    int m1 = m0 + 8;
    int b0 = m0 / 36, pos0 = m0 % 36;
    int b1i = m1 / 36, pos1 = m1 % 36;
#pragma unroll
    for (int nt = 0; nt < 16; nt++) {
        int col = ny * 128 + nt * 8 + tg * 2;
        float bc0 = __ldg(pb + col), bc1 = __ldg(pb + col + 1);
        g_uraw[(size_t)b0 * 9216 + (size_t)col * 36 + pos0] = acc[nt][0] + bc0;
        g_uraw[(size_t)b0 * 9216 + (size_t)(col + 1) * 36 + pos0] = acc[nt][1] + bc1;
        g_uraw[(size_t)b1i * 9216 + (size_t)col * 36 + pos1] = acc[nt][2] + bc0;
        g_uraw[(size_t)b1i * 9216 + (size_t)(col + 1) * 36 + pos1] = acc[nt][3] + bc1;
    }
}

__global__ void k_squash() {
    int idx = blockIdx.x * blockDim.x + threadIdx.x;
    if (idx >= NB * NR) return;
    const float4* p = (const float4*)(g_uraw + (size_t)idx * 8);
    float4 a = p[0], c = p[1];
    float sn = a.x*a.x + a.y*a.y + a.z*a.z + a.w*a.w + c.x*c.x + c.y*c.y + c.z*c.z + c.w*c.w;
    float f = sqrtf(sn) / (1.0f + sn);
    float4* o = (float4*)(g_u + (size_t)idx * 8);
    a.x*=f; a.y*=f; a.z*=f; a.w*=f; c.x*=f; c.y*=f; c.z*=f; c.w*=f;
    o[0] = a; o[1] = c;
}

__global__ void __launch_bounds__(160) k_uhat(const float* __restrict__ W) {
    __shared__ float sWT[1280];
    int r = blockIdx.x, t = threadIdx.x;
    for (int j = t; j < 1280; j += 160)
        sWT[j] = W[(size_t)r * 1280 + (j % 160) * 8 + j / 160];
    __syncthreads();
    float w0 = sWT[t], w1 = sWT[160+t], w2 = sWT[320+t], w3 = sWT[480+t];
    float w4 = sWT[640+t], w5 = sWT[800+t], w6 = sWT[960+t], w7 = sWT[1120+t];
#pragma unroll 4
    for (int b = 0; b < NB; b++) {
        const float4* up = (const float4*)(g_u + (size_t)b * 9216 + r * 8);
        float4 ua = up[0], ub = up[1];
        g_uhat[((size_t)b * NR + r) * 160 + t] =
            ua.x*w0 + ua.y*w1 + ua.z*w2 + ua.w*w3 + ub.x*w4 + ub.y*w5 + ub.z*w6 + ub.w*w7;
    }
}

__global__ void k_softmax() {
    __shared__ float sred[128];
    int c = blockIdx.x, t = threadIdx.x;
    float mx = -1e30f;
    for (int r = t; r < NR; r += 128) mx = fmaxf(mx, g_bij[r * NC2 + c]);
    sred[t] = mx; __syncthreads();
    for (int st = 64; st >= 1; st >>= 1) { if (t < st) sred[t] = fmaxf(sred[t], sred[t + st]); __syncthreads(); }
    mx = sred[0]; __syncthreads();
    float sm = 0.f;
    for (int r = t; r < NR; r += 128) sm += expf(g_bij[r * NC2 + c] - mx);
    sred[t] = sm; __syncthreads();
    for (int st = 64; st >= 1; st >>= 1) { if (t < st) sred[t] += sred[t + st]; __syncthreads(); }
    float inv = 1.0f / sred[0];
    for (int r = t; r < NR; r += 128)
        g_cij[r * NC2 + c] = expf(g_bij[r * NC2 + c] - mx) * inv;
}

__global__ void __launch_bounds__(256) k_sj(float* out) {
    __shared__ float sred[256];
    int b = blockIdx.x, c = blockIdx.y, t = threadIdx.x;
    int o = t & 15, rg = t >> 4;
    float acc = 0.f;
    for (int r = rg; r < NR; r += 16)
        acc = fmaf(__ldg(g_cij + r * NC2 + c), g_uhat[(((size_t)b * NR + r) * NC2 + c) * 16 + o], acc);
    sred[t] = acc; __syncthreads();
    for (int st = 8; st >= 1; st >>= 1) { if (rg < st) sred[t] += sred[t + st * 16]; __syncthreads(); }
    if (rg == 0) {
        float s = sred[o];
        float v = s * fabsf(s) / (1.0f + s * s);
        g_v[(b * NC2 + c) * 16 + o] = v;
        if (out) out[(b * NC2 + c) * 16 + o] = v;
    }
}

__global__ void __launch_bounds__(128) k_aij() {
    __shared__ float sred[128];
    int r = blockIdx.x, c = blockIdx.y, t = threadIdx.x;
    int o = t & 15, bg = t >> 4;
    float acc = 0.f;
    for (int b = bg; b < NB; b += 8)
        acc = fmaf(g_uhat[(((size_t)b * NR + r) * NC2 + c) * 16 + o],
                   __ldg(g_v + (b * NC2 + c) * 16 + o), acc);
    sred[t] = acc; __syncthreads();
    for (int st = 64; st >= 1; st >>= 1) { if (t < st) sred[t] += sred[t + st]; __syncthreads(); }
    if (t == 0) g_bij[r * NC2 + c] += sred[0] * (1.0f / NB);
}

__global__ void __launch_bounds__(128) k_cls(const float* __restrict__ w1,
                                             const float* __restrict__ b1,
                                             const float* __restrict__ w2,
                                             const float* __restrict__ b2,
                                             float* out) {
    __shared__ float sfeat[160];
    __shared__ float sred[128];
    int b = blockIdx.x, k = blockIdx.y, t = threadIdx.x;
    for (int j = t; j < 160; j += 128) sfeat[j] = g_v[b * 160 + j];
    __syncthreads();
    float val = 0.f;
    if (t < 100) {
        float acc = __ldg(b1 + k * 100 + t);
        const float* wp = w1 + (size_t)k * 16000 + t;
#pragma unroll 4
        for (int f = 0; f < 160; f++) acc = fmaf(sfeat[f], wp[f * 100], acc);
        val = fmaxf(acc, 0.f) * __ldg(w2 + k * 100 + t);
    }
    sred[t] = val; __syncthreads();
    for (int st = 64; st >= 1; st >>= 1) { if (t < st) sred[t] += sred[t + st]; __syncthreads(); }
    if (t == 0)
        out[40960 + b * NC2 + k] = 1.0f / (1.0f + expf(-(sred[0] + __ldg(b2 + k))));
}

extern "C" void kernel_launch(void* const* d_in, const int* in_sizes, int n_in,
                              void* d_out, int out_size) {
    const float* data    = (const float*)d_in[0];
    const float* conv1_w = (const float*)d_in[1];
    const float* conv1_b = (const float*)d_in[2];
    const float* conv2_w = (const float*)d_in[3];
    const float* conv2_b = (const float*)d_in[4];
    const float* prim_w  = (const float*)d_in[5];
    const float* prim_b  = (const float*)d_in[6];
    const float* W       = (const float*)d_in[7];
    const float* cls_w1  = (const float*)d_in[8];
    const float* cls_b1  = (const float*)d_in[9];
    const float* cls_w2  = (const float*)d_in[10];
    const float* cls_b2  = (const float*)d_in[11];
    float* out = (float*)d_out;

    k_zero<<<45, 256>>>();
    k_cvt_w2<<<288, 256>>>(conv2_w);
    k_cvt_pw<<<10368, 256>>>(prim_w);
    k_conv1pool<<<1444, 256>>>(data, conv1_w, conv1_b);
    k_conv2mma<<<dim3(12, NB), 256>>>(conv2_b);
    k_pool2n<<<dim3(25, NB), 256>>>();
    k_primmma<<<dim3(72, 2), 256>>>(prim_b);
    k_squash<<<(NB * NR + 255) / 256, 256>>>();
    k_uhat<<<NR, 160>>>(W);

    for (int it = 0; it < 3; it++) {
        k_softmax<<<NC2, 128>>>();
        k_sj<<<dim3(NB, NC2), 256>>>(it == 2 ? out : nullptr);
        if (it < 2) k_aij<<<dim3(NR, NC2), 128>>>();
    }
    k_cls<<<dim3(NB, NC2), 128>>>(cls_w1, cls_b1, cls_w2, cls_b2, out);
}

// round 8
// speedup vs baseline: 1.2077x; 1.0729x over previous
#include <cuda_runtime.h>
#include <cuda_bf16.h>
#include <math.h>
#include <stdint.h>

#define NB 256
#define NR 1152
#define NC2 10
#define LDA 40

__device__ __forceinline__ void mma16816(float* d, unsigned a0, unsigned a1, unsigned a2, unsigned a3,
                                         unsigned b0, unsigned b1) {
    asm volatile("mma.sync.aligned.m16n8k16.row.col.f32.bf16.bf16.f32 "
        "{%0,%1,%2,%3}, {%4,%5,%6,%7}, {%8,%9}, {%0,%1,%2,%3};"
        : "+f"(d[0]), "+f"(d[1]), "+f"(d[2]), "+f"(d[3])
        : "r"(a0), "r"(a1), "r"(a2), "r"(a3), "r"(b0), "r"(b1));
}
__device__ __forceinline__ void ldsm_x4(unsigned* r, uint32_t addr) {
    asm volatile("ldmatrix.sync.aligned.m8n8.x4.shared.b16 {%0,%1,%2,%3}, [%4];"
        : "=r"(r[0]), "=r"(r[1]), "=r"(r[2]), "=r"(r[3]) : "r"(addr));
}
__device__ __forceinline__ void bfsplit(float f, __nv_bfloat16& h, __nv_bfloat16& l) {
    h = __float2bfloat16(f);
    l = __float2bfloat16(f - __bfloat162float(h));
}

// ---- scratch ----
__device__ __nv_bfloat16 g_p1h[(size_t)NB * 64 * 1444];
__device__ __nv_bfloat16 g_p1l[(size_t)NB * 64 * 1444];
__device__ float g_c2[(size_t)NB * 1444 * 128];
__device__ __nv_bfloat16 g_p2h[(size_t)NB * 128 * 400];
__device__ __nv_bfloat16 g_p2l[(size_t)NB * 128 * 400];
__device__ __nv_bfloat16 g_w2h[128 * 576];
__device__ __nv_bfloat16 g_w2l[128 * 576];
__device__ __nv_bfloat16 g_pwh[(size_t)256 * 10368];
__device__ __nv_bfloat16 g_pwl[(size_t)256 * 10368];
__device__ float g_upart[(size_t)3 * NB * 9216];          // prim K-slice partials
__device__ float g_u[(size_t)NB * 9216];
__device__ float g_uhat[(size_t)NB * NR * NC2 * 16];
__device__ float g_bij[NR * NC2];
__device__ float g_cij[NR * NC2];
__device__ float g_v[NB * NC2 * 16];

__global__ void k_zero() {
    int i = blockIdx.x * blockDim.x + threadIdx.x;
    if (i < NR * NC2) g_bij[i] = 0.f;
}

__global__ void k_cvt_w2(const float* __restrict__ w2) {
    int i = blockIdx.x * blockDim.x + threadIdx.x;
    if (i >= 128 * 576) return;
    __nv_bfloat16 h, l; bfsplit(w2[i], h, l);
    g_w2h[i] = h; g_w2l[i] = l;
}
__global__ void k_cvt_pw(const float* __restrict__ pw) {
    int i = blockIdx.x * blockDim.x + threadIdx.x;
    __nv_bfloat16 h, l; bfsplit(pw[i], h, l);
    g_pwh[i] = h; g_pwl[i] = l;
}

// ---- conv1+relu+pool ----
__global__ void __launch_bounds__(256) k_conv1pool(const float* __restrict__ data,
                                                   const float* __restrict__ w1,
                                                   const float* __restrict__ b1) {
    int idx = blockIdx.x * blockDim.x + threadIdx.x;
    int p = idx % 1444, b = idx / 1444;
    int pj = p / 38, pi = p % 38;
    int y0 = 2 * pj - 1, x0 = 2 * pi - 1;
    float iv[3][4][4];
#pragma unroll
    for (int ic = 0; ic < 3; ic++)
#pragma unroll
        for (int dy = 0; dy < 4; dy++) {
            int yy = y0 + dy;
#pragma unroll
            for (int dx = 0; dx < 4; dx++) {
                int xx = x0 + dx;
                float v = 0.f;
                if (yy >= 0 && yy < 76 && xx >= 0 && xx < 76)
                    v = data[((size_t)(b * 3 + ic) * 76 + yy) * 76 + xx];
                iv[ic][dy][dx] = v;
            }
        }
    bool rv0 = (y0 >= 0), rv1 = (y0 + 1 <= 73), cv0 = (x0 >= 0), cv1 = (x0 + 1 <= 73);
    size_t obase = (size_t)b * 64 * 1444 + (size_t)pj * 38 + pi;
#pragma unroll 1
    for (int oc = 0; oc < 64; oc++) {
        const float* wp = w1 + oc * 27;
        float s00 = 0.f, s01 = 0.f, s10 = 0.f, s11 = 0.f;
#pragma unroll
        for (int k = 0; k < 27; k++) {
            int ic = k / 9, r = (k / 3) % 3, c2 = k % 3;
            float w = __ldg(wp + k);
            s00 = fmaf(iv[ic][r][c2], w, s00);
            s01 = fmaf(iv[ic][r][c2 + 1], w, s01);
            s10 = fmaf(iv[ic][r + 1][c2], w, s10);
            s11 = fmaf(iv[ic][r + 1][c2 + 1], w, s11);
        }
        float bo = __ldg(b1 + oc), m = 0.f;
        if (rv0 && cv0) m = fmaxf(m, s00 + bo);
        if (rv0 && cv1) m = fmaxf(m, s01 + bo);
        if (rv1 && cv0) m = fmaxf(m, s10 + bo);
        if (rv1 && cv1) m = fmaxf(m, s11 + bo);
        __nv_bfloat16 h, l; bfsplit(m, h, l);
        g_p1h[obase + (size_t)oc * 1444] = h;
        g_p1l[obase + (size_t)oc * 1444] = l;
    }
}

// ---- shared mainloop chunk: bf16x3 with ldmatrix fragments ----
__device__ __forceinline__ void gemm_chunk(float acc[16][4], uint32_t aH, uint32_t aL,
                                           uint32_t bH, uint32_t bL) {
#pragma unroll
    for (int ks = 0; ks < 2; ks++) {
        unsigned Ah[4], Al[4];
        ldsm_x4(Ah, aH + ks * 32);
        ldsm_x4(Al, aL + ks * 32);
#pragma unroll
        for (int ntp = 0; ntp < 8; ntp++) {
            unsigned Bh[4], Bl[4];
            uint32_t bo = (uint32_t)ntp * (16 * LDA * 2) + ks * 32;
            ldsm_x4(Bh, bH + bo);
            ldsm_x4(Bl, bL + bo);
            mma16816(acc[2 * ntp],     Ah[0], Ah[1], Ah[2], Ah[3], Bh[0], Bh[1]);
            mma16816(acc[2 * ntp],     Al[0], Al[1], Al[2], Al[3], Bh[0], Bh[1]);
            mma16816(acc[2 * ntp],     Ah[0], Ah[1], Ah[2], Ah[3], Bl[0], Bl[1]);
            mma16816(acc[2 * ntp + 1], Ah[0], Ah[1], Ah[2], Ah[3], Bh[2], Bh[3]);
            mma16816(acc[2 * ntp + 1], Al[0], Al[1], Al[2], Al[3], Bh[2], Bh[3]);
            mma16816(acc[2 * ntp + 1], Ah[0], Ah[1], Ah[2], Ah[3], Bl[2], Bl[3]);
        }
    }
}

// ---- conv2 via mma.sync bf16x3 + ldmatrix ----
__global__ void __launch_bounds__(256) k_conv2mma(const float* __restrict__ b2) {
    __shared__ __nv_bfloat16 sm[4 * 128 * LDA];
    __nv_bfloat16* sAh = sm;
    __nv_bfloat16* sAl = sm + 5120;
    __nv_bfloat16* sBh = sm + 10240;
    __nv_bfloat16* sBl = sm + 15360;
    int tid = threadIdx.x;
    int w = tid >> 5, lane = tid & 31;
    int g = lane >> 2, tg = lane & 3;
    int bb = blockIdx.y, strip = blockIdx.x;

    uint32_t smb = (uint32_t)__cvta_generic_to_shared(sm);
    uint32_t aoff = ((unsigned)(w * 16 + (lane & 15)) * LDA + ((lane & 16) ? 8 : 0)) * 2;
    uint32_t boff = ((unsigned)((lane & 7) + ((lane & 16) ? 8 : 0)) * LDA + ((lane & 8) ? 8 : 0)) * 2;
    uint32_t aH = smb + aoff, aL = aH + 10240;
    uint32_t bH = smb + 20480 + boff, bL = bH + 10240;

    float acc[16][4];
#pragma unroll
    for (int n = 0; n < 16; n++)
#pragma unroll
        for (int q = 0; q < 4; q++) acc[n][q] = 0.f;

    int pA = strip * 128 + (tid & 127);
    int yA = pA / 38, xA = pA % 38;
    bool pvA = pA < 1444;

#pragma unroll 1
    for (int kc = 0; kc < 18; kc++) {
        __syncthreads();
        if (tid < 128) {
            int k0 = kc * 32, ic = k0 / 9, r = k0 - ic * 9;
            int ky = r / 3, kx = r - ky * 3;
            const __nv_bfloat16* sh = g_p1h + ((size_t)bb * 64 + ic) * 1444;
            const __nv_bfloat16* sl = g_p1l + ((size_t)bb * 64 + ic) * 1444;
            int m = tid;
#pragma unroll 1
            for (int kk = 0; kk < 32; kk++) {
                int yy = yA + ky - 1, xx = xA + kx - 1;
                bool ok = pvA && yy >= 0 && yy < 38 && xx >= 0 && xx < 38;
                sAh[m * LDA + kk] = ok ? sh[yy * 38 + xx] : __nv_bfloat16(0.f);
                sAl[m * LDA + kk] = ok ? sl[yy * 38 + xx] : __nv_bfloat16(0.f);
                if (++kx == 3) { kx = 0; if (++ky == 3) { ky = 0; sh += 1444; sl += 1444; } }
            }
        } else {
            int n = tid - 128;
            const uint4* wh = (const uint4*)(g_w2h + (size_t)n * 576 + kc * 32);
            const uint4* wl = (const uint4*)(g_w2l + (size_t)n * 576 + kc * 32);
            uint4* dh = (uint4*)(sBh + n * LDA);
            uint4* dl = (uint4*)(sBl + n * LDA);
#pragma unroll
            for (int q = 0; q < 4; q++) { dh[q] = wh[q]; dl[q] = wl[q]; }
        }
        __syncthreads();
        gemm_chunk(acc, aH, aL, bH, bL);
    }

    int p0 = strip * 128 + w * 16 + g;
    int p1 = p0 + 8;
#pragma unroll
    for (int nt = 0; nt < 16; nt++) {
        int col = nt * 8 + tg * 2;
        float bc0 = __ldg(b2 + col), bc1 = __ldg(b2 + col + 1);
        if (p0 < 1444) {
            float2 o; o.x = fmaxf(acc[nt][0] + bc0, 0.f); o.y = fmaxf(acc[nt][1] + bc1, 0.f);
            *(float2*)(g_c2 + ((size_t)bb * 1444 + p0) * 128 + col) = o;
        }
        if (p1 < 1444) {
            float2 o; o.x = fmaxf(acc[nt][2] + bc0, 0.f); o.y = fmaxf(acc[nt][3] + bc1, 0.f);
            *(float2*)(g_c2 + ((size_t)bb * 1444 + p1) * 128 + col) = o;
        }
    }
}

// ---- maxpool -> channel-major bf16 hi/lo ----
__global__ void __launch_bounds__(256) k_pool2n() {
    __shared__ float s[16 * 129];
    int b = blockIdx.y, t0 = blockIdx.x;
    int tid = threadIdx.x;
    for (int i = tid; i < 2048; i += 256) {
        int p2l = i >> 7, oc = i & 127;
        int p2 = t0 * 16 + p2l;
        int pj = p2 / 20, pi = p2 % 20;
        int y0 = 2 * pj - 1, x0 = 2 * pi - 1;
        float m = 0.f;
#pragma unroll
        for (int dy = 0; dy < 2; dy++) {
            int y = y0 + dy; if (y < 0 || y > 37) continue;
#pragma unroll
            for (int dx = 0; dx < 2; dx++) {
                int x = x0 + dx; if (x < 0 || x > 37) continue;
                m = fmaxf(m, g_c2[((size_t)b * 1444 + y * 38 + x) * 128 + oc]);
            }
        }
        s[p2l * 129 + oc] = m;
    }
    __syncthreads();
    for (int i = tid; i < 2048; i += 256) {
        int oc = i >> 4, p2l = i & 15;
        __nv_bfloat16 h, l; bfsplit(s[p2l * 129 + oc], h, l);
        size_t o = ((size_t)(b * 128 + oc)) * 400 + t0 * 16 + p2l;
        g_p2h[o] = h; g_p2l[o] = l;
    }
}

// ---- PrimaryCaps mma, K-split x3: grid (72, 2, 3) ----
__global__ void __launch_bounds__(256) k_primmma() {
    __shared__ __nv_bfloat16 sm[4 * 128 * LDA];
    __nv_bfloat16* sAh = sm;
    __nv_bfloat16* sAl = sm + 5120;
    __nv_bfloat16* sBh = sm + 10240;
    __nv_bfloat16* sBl = sm + 15360;
    int tid = threadIdx.x;
    int w = tid >> 5, lane = tid & 31;
    int g = lane >> 2, tg = lane & 3;
    int mb = blockIdx.x, ny = blockIdx.y, zz = blockIdx.z;

    uint32_t smb = (uint32_t)__cvta_generic_to_shared(sm);
    uint32_t aoff = ((unsigned)(w * 16 + (lane & 15)) * LDA + ((lane & 16) ? 8 : 0)) * 2;
    uint32_t boff = ((unsigned)((lane & 7) + ((lane & 16) ? 8 : 0)) * LDA + ((lane & 8) ? 8 : 0)) * 2;
    uint32_t aH = smb + aoff, aL = aH + 10240;
    uint32_t bH = smb + 20480 + boff, bL = bH + 10240;

    float acc[16][4];
#pragma unroll
    for (int n = 0; n < 16; n++)
#pragma unroll
        for (int q = 0; q < 4; q++) acc[n][q] = 0.f;

    int mA = mb * 128 + (tid & 127);
    int bA = mA / 36, posA = mA % 36;
    int sjA = posA / 6, siA = posA % 6;
    const __nv_bfloat16* p2hB = g_p2h + (size_t)bA * 51200;
    const __nv_bfloat16* p2lB = g_p2l + (size_t)bA * 51200;

    int kc0 = zz * 108;
#pragma unroll 1
    for (int kc = kc0; kc < kc0 + 108; kc++) {
        __syncthreads();
        if (tid < 128) {
            int k0 = kc * 32;
            int ic = k0 / 81, r = k0 - ic * 81;
            int ky = r / 9, kx = r - ky * 9;
            int off = ic * 400 + (2 * sjA + ky) * 20 + 2 * siA + kx;
            int m = tid;
#pragma unroll 1
            for (int kk = 0; kk < 32; kk++) {
                sAh[m * LDA + kk] = p2hB[off];
                sAl[m * LDA + kk] = p2lB[off];
                if (++kx == 9) {
                    kx = 0;
                    if (++ky == 9) { ky = 0; off += 232; }
                    else off += 12;
                } else off++;
            }
        } else {
            int n = tid - 128;
            const uint4* wh = (const uint4*)(g_pwh + (size_t)(ny * 128 + n) * 10368 + kc * 32);
            const uint4* wl = (const uint4*)(g_pwl + (size_t)(ny * 128 + n) * 10368 + kc * 32);
            uint4* dh = (uint4*)(sBh + n * LDA);
            uint4* dl = (uint4*)(sBl + n * LDA);
#pragma unroll
            for (int q = 0; q < 4; q++) { dh[q] = wh[q]; dl[q] = wl[q]; }
        }
        __syncthreads();
        gemm_chunk(acc, aH, aL, bH, bL);
    }

    // write K-slice partials (no bias)
    float* up = g_upart + (size_t)zz * NB * 9216;
    int m0 = mb * 128 + w * 16 + g;
    int m1 = m0 + 8;
    int b0 = m0 / 36, pos0 = m0 % 36;
    int b1i = m1 / 36, pos1 = m1 % 36;
#pragma unroll
    for (int nt = 0; nt < 16; nt++) {
        int col = ny * 128 + nt * 8 + tg * 2;
        up[(size_t)b0 * 9216 + (size_t)col * 36 + pos0] = acc[nt][0];
        up[(size_t)b0 * 9216 + (size_t)(col + 1) * 36 + pos0] = acc[nt][1];
        up[(size_t)b1i * 9216 + (size_t)col * 36 + pos1] = acc[nt][2];
        up[(size_t)b1i * 9216 + (size_t)(col + 1) * 36 + pos1] = acc[nt][3];
    }
}

// ---- squash: sum 3 K-slices + bias, then squash over groups of 8 ----
__global__ void k_squash(const float* __restrict__ pb) {
    int idx = blockIdx.x * blockDim.x + threadIdx.x;
    if (idx >= NB * NR) return;
    int r = idx % NR;
    size_t base = (size_t)idx * 8;
    const size_t UP = (size_t)NB * 9216;
    float e[8];
    float sn = 0.f;
#pragma unroll
    for (int j = 0; j < 8; j++) {
        int oc = (r * 8 + j) / 36;
        float v = g_upart[base + j] + g_upart[UP + base + j] + g_upart[2 * UP + base + j]
                + __ldg(pb + oc);
        e[j] = v;
        sn = fmaf(v, v, sn);
    }
    float f = sqrtf(sn) / (1.0f + sn);
    float4 o0 = make_float4(e[0] * f, e[1] * f, e[2] * f, e[3] * f);
    float4 o1 = make_float4(e[4] * f, e[5] * f, e[6] * f, e[7] * f);
    float4* o = (float4*)(g_u + base);
    o[0] = o0; o[1] = o1;
}

__global__ void __launch_bounds__(160) k_uhat(const float* __restrict__ W) {
    __shared__ float sWT[1280];
    int r = blockIdx.x, t = threadIdx.x;
    for (int j = t; j < 1280; j += 160)
        sWT[j] = W[(size_t)r * 1280 + (j % 160) * 8 + j / 160];
    __syncthreads();
    float w0 = sWT[t], w1 = sWT[160+t], w2 = sWT[320+t], w3 = sWT[480+t];
    float w4 = sWT[640+t], w5 = sWT[800+t], w6 = sWT[960+t], w7 = sWT[1120+t];
#pragma unroll 4
    for (int b = 0; b < NB; b++) {
        const float4* up = (const float4*)(g_u + (size_t)b * 9216 + r * 8);
        float4 ua = up[0], ub = up[1];
        g_uhat[((size_t)b * NR + r) * 160 + t] =
            ua.x*w0 + ua.y*w1 + ua.z*w2 + ua.w*w3 + ub.x*w4 + ub.y*w5 + ub.z*w6 + ub.w*w7;
    }
}

__global__ void k_softmax() {
    __shared__ float sred[128];
    int c = blockIdx.x, t = threadIdx.x;
    float mx = -1e30f;
    for (int r = t; r < NR; r += 128) mx = fmaxf(mx, g_bij[r * NC2 + c]);
    sred[t] = mx; __syncthreads();
    for (int st = 64; st >= 1; st >>= 1) { if (t < st) sred[t] = fmaxf(sred[t], sred[t + st]); __syncthreads(); }
    mx = sred[0]; __syncthreads();
    float sm = 0.f;
    for (int r = t; r < NR; r += 128) sm += expf(g_bij[r * NC2 + c] - mx);
    sred[t] = sm; __syncthreads();
    for (int st = 64; st >= 1; st >>= 1) { if (t < st) sred[t] += sred[t + st]; __syncthreads(); }
    float inv = 1.0f / sred[0];
    for (int r = t; r < NR; r += 128)
        g_cij[r * NC2 + c] = expf(g_bij[r * NC2 + c] - mx) * inv;
}

__global__ void __launch_bounds__(256) k_sj(float* out) {
    __shared__ float sred[256];
    int b = blockIdx.x, c = blockIdx.y, t = threadIdx.x;
    int o = t & 15, rg = t >> 4;
    float acc = 0.f;
    for (int r = rg; r < NR; r += 16)
        acc = fmaf(__ldg(g_cij + r * NC2 + c), g_uhat[(((size_t)b * NR + r) * NC2 + c) * 16 + o], acc);
    sred[t] = acc; __syncthreads();
    for (int st = 8; st >= 1; st >>= 1) { if (rg < st) sred[t] += sred[t + st * 16]; __syncthreads(); }
    if (rg == 0) {
        float s = sred[o];
        float v = s * fabsf(s) / (1.0f + s * s);
        g_v[(b * NC2 + c) * 16 + o] = v;
        if (out) out[(b * NC2 + c) * 16 + o] = v;
    }
}

__global__ void __launch_bounds__(128) k_aij() {
    __shared__ float sred[128];
    int r = blockIdx.x, c = blockIdx.y, t = threadIdx.x;
    int o = t & 15, bg = t >> 4;
    float acc = 0.f;
    for (int b = bg; b < NB; b += 8)
        acc = fmaf(g_uhat[(((size_t)b * NR + r) * NC2 + c) * 16 + o],
                   __ldg(g_v + (b * NC2 + c) * 16 + o), acc);
    sred[t] = acc; __syncthreads();
    for (int st = 64; st >= 1; st >>= 1) { if (t < st) sred[t] += sred[t + st]; __syncthreads(); }
    if (t == 0) g_bij[r * NC2 + c] += sred[0] * (1.0f / NB);
}

__global__ void __launch_bounds__(128) k_cls(const float* __restrict__ w1,
                                             const float* __restrict__ b1,
                                             const float* __restrict__ w2,
                                             const float* __restrict__ b2,
                                             float* out) {
    __shared__ float sfeat[160];
    __shared__ float sred[128];
    int b = blockIdx.x, k = blockIdx.y, t = threadIdx.x;
    for (int j = t; j < 160; j += 128) sfeat[j] = g_v[b * 160 + j];
    __syncthreads();
    float val = 0.f;
    if (t < 100) {
        float acc = __ldg(b1 + k * 100 + t);
        const float* wp = w1 + (size_t)k * 16000 + t;
#pragma unroll 4
        for (int f = 0; f < 160; f++) acc = fmaf(sfeat[f], wp[f * 100], acc);
        val = fmaxf(acc, 0.f) * __ldg(w2 + k * 100 + t);
    }
    sred[t] = val; __syncthreads();
    for (int st = 64; st >= 1; st >>= 1) { if (t < st) sred[t] += sred[t + st]; __syncthreads(); }
    if (t == 0)
        out[40960 + b * NC2 + k] = 1.0f / (1.0f + expf(-(sred[0] + __ldg(b2 + k))));
}

extern "C" void kernel_launch(void* const* d_in, const int* in_sizes, int n_in,
                              void* d_out, int out_size) {
    const float* data    = (const float*)d_in[0];
    const float* conv1_w = (const float*)d_in[1];
    const float* conv1_b = (const float*)d_in[2];
    const float* conv2_w = (const float*)d_in[3];
    const float* conv2_b = (const float*)d_in[4];
    const float* prim_w  = (const float*)d_in[5];
    const float* prim_b  = (const float*)d_in[6];
    const float* W       = (const float*)d_in[7];
    const float* cls_w1  = (const float*)d_in[8];
    const float* cls_b1  = (const float*)d_in[9];
    const float* cls_w2  = (const float*)d_in[10];
    const float* cls_b2  = (const float*)d_in[11];
    float* out = (float*)d_out;

    k_zero<<<45, 256>>>();
    k_cvt_w2<<<288, 256>>>(conv2_w);
    k_cvt_pw<<<10368, 256>>>(prim_w);
    k_conv1pool<<<1444, 256>>>(data, conv1_w, conv1_b);
    k_conv2mma<<<dim3(12, NB), 256>>>(conv2_b);
    k_pool2n<<<dim3(25, NB), 256>>>();
    k_primmma<<<dim3(72, 2, 3), 256>>>();
    k_squash<<<(NB * NR + 255) / 256, 256>>>(prim_b);
    k_uhat<<<NR, 160>>>(W);

    for (int it = 0; it < 3; it++) {
        k_softmax<<<NC2, 128>>>();
        k_sj<<<dim3(NB, NC2), 256>>>(it == 2 ? out : nullptr);
        if (it < 2) k_aij<<<dim3(NR, NC2), 128>>>();
    }
    k_cls<<<dim3(NB, NC2), 128>>>(cls_w1, cls_b1, cls_w2, cls_b2, out);
}

// round 9
// speedup vs baseline: 1.5331x; 1.2694x over previous
#include <cuda_runtime.h>
#include <cuda_bf16.h>
#include <math.h>
#include <stdint.h>

#define NB 256
#define NR 1152
#define NC2 10
#define LDA 40
#define BUFB 40960            // bytes per ping-pong buffer
#define BUFE 20480            // elems per buffer

__device__ __forceinline__ void mma16816(float* d, unsigned a0, unsigned a1, unsigned a2, unsigned a3,
                                         unsigned b0, unsigned b1) {
    asm volatile("mma.sync.aligned.m16n8k16.row.col.f32.bf16.bf16.f32 "
        "{%0,%1,%2,%3}, {%4,%5,%6,%7}, {%8,%9}, {%0,%1,%2,%3};"
        : "+f"(d[0]), "+f"(d[1]), "+f"(d[2]), "+f"(d[3])
        : "r"(a0), "r"(a1), "r"(a2), "r"(a3), "r"(b0), "r"(b1));
}
__device__ __forceinline__ void ldsm_x4(unsigned* r, uint32_t addr) {
    asm volatile("ldmatrix.sync.aligned.m8n8.x4.shared.b16 {%0,%1,%2,%3}, [%4];"
        : "=r"(r[0]), "=r"(r[1]), "=r"(r[2]), "=r"(r[3]) : "r"(addr));
}
__device__ __forceinline__ void bfsplit(float f, __nv_bfloat16& h, __nv_bfloat16& l) {
    h = __float2bfloat16(f);
    l = __float2bfloat16(f - __bfloat162float(h));
}

// ---- scratch ----
__device__ __nv_bfloat16 g_p1h[(size_t)NB * 64 * 1444];
__device__ __nv_bfloat16 g_p1l[(size_t)NB * 64 * 1444];
__device__ float g_c2[(size_t)NB * 1444 * 128];
__device__ __nv_bfloat16 g_p2h[(size_t)NB * 128 * 400];
__device__ __nv_bfloat16 g_p2l[(size_t)NB * 128 * 400];
__device__ __nv_bfloat16 g_w2h[128 * 576];
__device__ __nv_bfloat16 g_w2l[128 * 576];
__device__ __nv_bfloat16 g_pwh[(size_t)256 * 10368];
__device__ __nv_bfloat16 g_pwl[(size_t)256 * 10368];
__device__ float g_upart[(size_t)3 * NB * 9216];
__device__ float g_u[(size_t)NB * 9216];
__device__ float g_uhat[(size_t)NB * NR * NC2 * 16];
__device__ float g_bij[NR * NC2];
__device__ float g_cij[NR * NC2];
__device__ float g_v[NB * NC2 * 16];

__global__ void k_zero() {
    int i = blockIdx.x * blockDim.x + threadIdx.x;
    if (i < NR * NC2) g_bij[i] = 0.f;
}
__global__ void k_cvt_w2(const float* __restrict__ w2) {
    int i = blockIdx.x * blockDim.x + threadIdx.x;
    if (i >= 128 * 576) return;
    __nv_bfloat16 h, l; bfsplit(w2[i], h, l);
    g_w2h[i] = h; g_w2l[i] = l;
}
__global__ void k_cvt_pw(const float* __restrict__ pw) {
    int i = blockIdx.x * blockDim.x + threadIdx.x;
    __nv_bfloat16 h, l; bfsplit(pw[i], h, l);
    g_pwh[i] = h; g_pwl[i] = l;
}

// ---- conv1+relu+pool ----
__global__ void __launch_bounds__(256) k_conv1pool(const float* __restrict__ data,
                                                   const float* __restrict__ w1,
                                                   const float* __restrict__ b1) {
    int idx = blockIdx.x * blockDim.x + threadIdx.x;
    int p = idx % 1444, b = idx / 1444;
    int pj = p / 38, pi = p % 38;
    int y0 = 2 * pj - 1, x0 = 2 * pi - 1;
    float iv[3][4][4];
#pragma unroll
    for (int ic = 0; ic < 3; ic++)
#pragma unroll
        for (int dy = 0; dy < 4; dy++) {
            int yy = y0 + dy;
#pragma unroll
            for (int dx = 0; dx < 4; dx++) {
                int xx = x0 + dx;
                float v = 0.f;
                if (yy >= 0 && yy < 76 && xx >= 0 && xx < 76)
                    v = data[((size_t)(b * 3 + ic) * 76 + yy) * 76 + xx];
                iv[ic][dy][dx] = v;
            }
        }
    bool rv0 = (y0 >= 0), rv1 = (y0 + 1 <= 73), cv0 = (x0 >= 0), cv1 = (x0 + 1 <= 73);
    size_t obase = (size_t)b * 64 * 1444 + (size_t)pj * 38 + pi;
#pragma unroll 1
    for (int oc = 0; oc < 64; oc++) {
        const float* wp = w1 + oc * 27;
        float s00 = 0.f, s01 = 0.f, s10 = 0.f, s11 = 0.f;
#pragma unroll
        for (int k = 0; k < 27; k++) {
            int ic = k / 9, r = (k / 3) % 3, c2 = k % 3;
            float w = __ldg(wp + k);
            s00 = fmaf(iv[ic][r][c2], w, s00);
            s01 = fmaf(iv[ic][r][c2 + 1], w, s01);
            s10 = fmaf(iv[ic][r + 1][c2], w, s10);
            s11 = fmaf(iv[ic][r + 1][c2 + 1], w, s11);
        }
        float bo = __ldg(b1 + oc), m = 0.f;
        if (rv0 && cv0) m = fmaxf(m, s00 + bo);
        if (rv0 && cv1) m = fmaxf(m, s01 + bo);
        if (rv1 && cv0) m = fmaxf(m, s10 + bo);
        if (rv1 && cv1) m = fmaxf(m, s11 + bo);
        __nv_bfloat16 h, l; bfsplit(m, h, l);
        g_p1h[obase + (size_t)oc * 1444] = h;
        g_p1l[obase + (size_t)oc * 1444] = l;
    }
}

// ---- B staging via cp.async: 1024 x 16B, 4 per thread ----
__device__ __forceinline__ void stageB_cp(uint32_t dstb, const __nv_bfloat16* __restrict__ srcH,
                                          const __nv_bfloat16* __restrict__ srcL,
                                          int kc, int tid, int wstride, int nbase) {
#pragma unroll
    for (int q = 0; q < 4; q++) {
        int i = tid * 4 + q;
        int half = i >> 9;
        int n = (i & 511) >> 2;
        int seg = i & 3;
        const __nv_bfloat16* src = (half ? srcL : srcH) + (size_t)(nbase + n) * wstride + kc * 32 + seg * 8;
        uint32_t dst = dstb + (half ? 15360 * 2 : 10240 * 2) + ((unsigned)n * LDA + seg * 8) * 2;
        asm volatile("cp.async.ca.shared.global [%0], [%1], 16;" :: "r"(dst), "l"(src));
    }
    asm volatile("cp.async.commit_group;" ::: "memory");
}
__device__ __forceinline__ void cp_wait() {
    asm volatile("cp.async.wait_group 0;" ::: "memory");
}

// ---- gemm on one buffer ----
__device__ __forceinline__ void gemm_chunk(float acc[16][4], uint32_t aH, uint32_t aL,
                                           uint32_t bH, uint32_t bL) {
#pragma unroll
    for (int ks = 0; ks < 2; ks++) {
        unsigned Ah[4], Al[4];
        ldsm_x4(Ah, aH + ks * 32);
        ldsm_x4(Al, aL + ks * 32);
#pragma unroll
        for (int ntp = 0; ntp < 8; ntp++) {
            unsigned Bh[4], Bl[4];
            uint32_t bo = (uint32_t)ntp * (16 * LDA * 2) + ks * 32;
            ldsm_x4(Bh, bH + bo);
            ldsm_x4(Bl, bL + bo);
            mma16816(acc[2 * ntp],     Ah[0], Ah[1], Ah[2], Ah[3], Bh[0], Bh[1]);
            mma16816(acc[2 * ntp],     Al[0], Al[1], Al[2], Al[3], Bh[0], Bh[1]);
            mma16816(acc[2 * ntp],     Ah[0], Ah[1], Ah[2], Ah[3], Bl[0], Bl[1]);
            mma16816(acc[2 * ntp + 1], Ah[0], Ah[1], Ah[2], Ah[3], Bh[2], Bh[3]);
            mma16816(acc[2 * ntp + 1], Al[0], Al[1], Al[2], Al[3], Bh[2], Bh[3]);
            mma16816(acc[2 * ntp + 1], Ah[0], Ah[1], Ah[2], Ah[3], Bl[2], Bl[3]);
        }
    }
}

// ---- conv2: double-buffered bf16x3 mma ----
__global__ void __launch_bounds__(256) k_conv2mma(const float* __restrict__ b2) {
    extern __shared__ __nv_bfloat16 sm[];          // 2 buffers x 20480 elems
    int tid = threadIdx.x;
    int w = tid >> 5, lane = tid & 31;
    int g = lane >> 2, tg = lane & 3;
    int bb = blockIdx.y, strip = blockIdx.x;

    uint32_t smb = (uint32_t)__cvta_generic_to_shared(sm);
    uint32_t aoff = ((unsigned)(w * 16 + (lane & 15)) * LDA + ((lane & 16) ? 8 : 0)) * 2;
    uint32_t boff = ((unsigned)((lane & 7) + ((lane & 16) ? 8 : 0)) * LDA + ((lane & 8) ? 8 : 0)) * 2;

    float acc[16][4];
#pragma unroll
    for (int n = 0; n < 16; n++)
#pragma unroll
        for (int q = 0; q < 4; q++) acc[n][q] = 0.f;

    int mloc = tid & 127;
    int pA = strip * 128 + mloc;
    int yA = pA / 38, xA = pA % 38;
    bool pvA = pA < 1444;
    int khalf = (tid >> 7) * 16;

    // A staging closure (16 elems)
    auto stageA = [&](__nv_bfloat16* dst, int kc) {
        int k0 = kc * 32 + khalf;
        int ic = k0 / 9, r = k0 - ic * 9;
        int ky = r / 3, kx = r - ky * 3;
        const __nv_bfloat16* sh = g_p1h + ((size_t)bb * 64 + ic) * 1444;
        const __nv_bfloat16* sl = g_p1l + ((size_t)bb * 64 + ic) * 1444;
        __nv_bfloat16* dh = dst + mloc * LDA + khalf;
        __nv_bfloat16* dl = dh + 5120;
#pragma unroll 1
        for (int kk = 0; kk < 16; kk++) {
            int yy = yA + ky - 1, xx = xA + kx - 1;
            bool ok = pvA && yy >= 0 && yy < 38 && xx >= 0 && xx < 38;
            dh[kk] = ok ? sh[yy * 38 + xx] : __nv_bfloat16(0.f);
            dl[kk] = ok ? sl[yy * 38 + xx] : __nv_bfloat16(0.f);
            if (++kx == 3) { kx = 0; if (++ky == 3) { ky = 0; sh += 1444; sl += 1444; } }
        }
    };

    stageA(sm, 0);
    stageB_cp(smb, g_w2h, g_w2l, 0, tid, 576, 0);
    cp_wait();
    __syncthreads();

#pragma unroll 1
    for (int kc = 0; kc < 18; kc++) {
        int par = kc & 1, nxt = kc + 1;
        if (nxt < 18) {
            stageA(sm + (nxt & 1) * BUFE, nxt);
            stageB_cp(smb + (nxt & 1) * BUFB, g_w2h, g_w2l, nxt, tid, 576, 0);
        }
        uint32_t base = smb + par * BUFB;
        gemm_chunk(acc, base + aoff, base + 10240 + aoff,
                        base + 20480 + boff, base + 30720 + boff);
        cp_wait();
        __syncthreads();
    }

    int p0 = strip * 128 + w * 16 + g;
    int p1 = p0 + 8;
#pragma unroll
    for (int nt = 0; nt < 16; nt++) {
        int col = nt * 8 + tg * 2;
        float bc0 = __ldg(b2 + col), bc1 = __ldg(b2 + col + 1);
        if (p0 < 1444) {
            float2 o; o.x = fmaxf(acc[nt][0] + bc0, 0.f); o.y = fmaxf(acc[nt][1] + bc1, 0.f);
            *(float2*)(g_c2 + ((size_t)bb * 1444 + p0) * 128 + col) = o;
        }
        if (p1 < 1444) {
            float2 o; o.x = fmaxf(acc[nt][2] + bc0, 0.f); o.y = fmaxf(acc[nt][3] + bc1, 0.f);
            *(float2*)(g_c2 + ((size_t)bb * 1444 + p1) * 128 + col) = o;
        }
    }
}

// ---- maxpool -> channel-major bf16 hi/lo ----
__global__ void __launch_bounds__(256) k_pool2n() {
    __shared__ float s[16 * 129];
    int b = blockIdx.y, t0 = blockIdx.x;
    int tid = threadIdx.x;
    for (int i = tid; i < 2048; i += 256) {
        int p2l = i >> 7, oc = i & 127;
        int p2 = t0 * 16 + p2l;
        int pj = p2 / 20, pi = p2 % 20;
        int y0 = 2 * pj - 1, x0 = 2 * pi - 1;
        float m = 0.f;
#pragma unroll
        for (int dy = 0; dy < 2; dy++) {
            int y = y0 + dy; if (y < 0 || y > 37) continue;
#pragma unroll
            for (int dx = 0; dx < 2; dx++) {
                int x = x0 + dx; if (x < 0 || x > 37) continue;
                m = fmaxf(m, g_c2[((size_t)b * 1444 + y * 38 + x) * 128 + oc]);
            }
        }
        s[p2l * 129 + oc] = m;
    }
    __syncthreads();
    for (int i = tid; i < 2048; i += 256) {
        int oc = i >> 4, p2l = i & 15;
        __nv_bfloat16 h, l; bfsplit(s[p2l * 129 + oc], h, l);
        size_t o = ((size_t)(b * 128 + oc)) * 400 + t0 * 16 + p2l;
        g_p2h[o] = h; g_p2l[o] = l;
    }
}

// ---- PrimaryCaps: double-buffered, K-split x3 ----
__global__ void __launch_bounds__(256) k_primmma() {
    extern __shared__ __nv_bfloat16 sm[];
    int tid = threadIdx.x;
    int w = tid >> 5, lane = tid & 31;
    int g = lane >> 2, tg = lane & 3;
    int mb = blockIdx.x, ny = blockIdx.y, zz = blockIdx.z;

    uint32_t smb = (uint32_t)__cvta_generic_to_shared(sm);
    uint32_t aoff = ((unsigned)(w * 16 + (lane & 15)) * LDA + ((lane & 16) ? 8 : 0)) * 2;
    uint32_t boff = ((unsigned)((lane & 7) + ((lane & 16) ? 8 : 0)) * LDA + ((lane & 8) ? 8 : 0)) * 2;

    float acc[16][4];
#pragma unroll
    for (int n = 0; n < 16; n++)
#pragma unroll
        for (int q = 0; q < 4; q++) acc[n][q] = 0.f;

    int mloc = tid & 127;
    int mA = mb * 128 + mloc;
    int bA = mA / 36, posA = mA % 36;
    int sjA = posA / 6, siA = posA % 6;
    const __nv_bfloat16* p2hB = g_p2h + (size_t)bA * 51200;
    const __nv_bfloat16* p2lB = g_p2l + (size_t)bA * 51200;
    int khalf = (tid >> 7) * 16;

    auto stageA = [&](__nv_bfloat16* dst, int kc) {
        int k0 = kc * 32 + khalf;
        int ic = k0 / 81, r = k0 - ic * 81;
        int ky = r / 9, kx = r - ky * 9;
        int off = ic * 400 + (2 * sjA + ky) * 20 + 2 * siA + kx;
        __nv_bfloat16* dh = dst + mloc * LDA + khalf;
        __nv_bfloat16* dl = dh + 5120;
#pragma unroll 1
        for (int kk = 0; kk < 16; kk++) {
            dh[kk] = p2hB[off];
            dl[kk] = p2lB[off];
            if (++kx == 9) { kx = 0; if (++ky == 9) { ky = 0; off += 232; } else off += 12; }
            else off++;
        }
    };

    int kc0 = zz * 108, kc1 = kc0 + 108;
    stageA(sm, kc0);
    stageB_cp(smb, g_pwh, g_pwl, kc0, tid, 10368, ny * 128);
    cp_wait();
    __syncthreads();

#pragma unroll 1
    for (int kc = kc0; kc < kc1; kc++) {
        int par = kc & 1, nxt = kc + 1;
        if (nxt < kc1) {
            stageA(sm + (nxt & 1) * BUFE, nxt);
            stageB_cp(smb + (nxt & 1) * BUFB, g_pwh, g_pwl, nxt, tid, 10368, ny * 128);
        }
        uint32_t base = smb + par * BUFB;
        gemm_chunk(acc, base + aoff, base + 10240 + aoff,
                        base + 20480 + boff, base + 30720 + boff);
        cp_wait();
        __syncthreads();
    }

    float* up = g_upart + (size_t)zz * NB * 9216;
    int m0 = mb * 128 + w * 16 + g;
    int m1 = m0 + 8;
    int b0 = m0 / 36, pos0 = m0 % 36;
    int b1i = m1 / 36, pos1 = m1 % 36;
#pragma unroll
    for (int nt = 0; nt < 16; nt++) {
        int col = ny * 128 + nt * 8 + tg * 2;
        up[(size_t)b0 * 9216 + (size_t)col * 36 + pos0] = acc[nt][0];
        up[(size_t)b0 * 9216 + (size_t)(col + 1) * 36 + pos0] = acc[nt][1];
        up[(size_t)b1i * 9216 + (size_t)col * 36 + pos1] = acc[nt][2];
        up[(size_t)b1i * 9216 + (size_t)(col + 1) * 36 + pos1] = acc[nt][3];
    }
}

// ---- squash: sum 3 K-slices + bias ----
__global__ void k_squash(const float* __restrict__ pb) {
    int idx = blockIdx.x * blockDim.x + threadIdx.x;
    if (idx >= NB * NR) return;
    int r = idx % NR;
    size_t base = (size_t)idx * 8;
    const size_t UP = (size_t)NB * 9216;
    float e[8];
    float sn = 0.f;
#pragma unroll
    for (int j = 0; j < 8; j++) {
        int oc = (r * 8 + j) / 36;
        float v = g_upart[base + j] + g_upart[UP + base + j] + g_upart[2 * UP + base + j]
                + __ldg(pb + oc);
        e[j] = v;
        sn = fmaf(v, v, sn);
    }
    float f = sqrtf(sn) / (1.0f + sn);
    float4 o0 = make_float4(e[0] * f, e[1] * f, e[2] * f, e[3] * f);
    float4 o1 = make_float4(e[4] * f, e[5] * f, e[6] * f, e[7] * f);
    float4* o = (float4*)(g_u + base);
    o[0] = o0; o[1] = o1;
}

__global__ void __launch_bounds__(160) k_uhat(const float* __restrict__ W) {
    __shared__ float sWT[1280];
    int r = blockIdx.x, t = threadIdx.x;
    for (int j = t; j < 1280; j += 160)
        sWT[j] = W[(size_t)r * 1280 + (j % 160) * 8 + j / 160];
    __syncthreads();
    float w0 = sWT[t], w1 = sWT[160+t], w2 = sWT[320+t], w3 = sWT[480+t];
    float w4 = sWT[640+t], w5 = sWT[800+t], w6 = sWT[960+t], w7 = sWT[1120+t];
#pragma unroll 4
    for (int b = 0; b < NB; b++) {
        const float4* up = (const float4*)(g_u + (size_t)b * 9216 + r * 8);
        float4 ua = up[0], ub = up[1];
        g_uhat[((size_t)b * NR + r) * 160 + t] =
            ua.x*w0 + ua.y*w1 + ua.z*w2 + ua.w*w3 + ub.x*w4 + ub.y*w5 + ub.z*w6 + ub.w*w7;
    }
}

__global__ void k_softmax() {
    __shared__ float sred[128];
    int c = blockIdx.x, t = threadIdx.x;
    float mx = -1e30f;
    for (int r = t; r < NR; r += 128) mx = fmaxf(mx, g_bij[r * NC2 + c]);
    sred[t] = mx; __syncthreads();
    for (int st = 64; st >= 1; st >>= 1) { if (t < st) sred[t] = fmaxf(sred[t], sred[t + st]); __syncthreads(); }
    mx = sred[0]; __syncthreads();
    float sm = 0.f;
    for (int r = t; r < NR; r += 128) sm += expf(g_bij[r * NC2 + c] - mx);
    sred[t] = sm; __syncthreads();
    for (int st = 64; st >= 1; st >>= 1) { if (t < st) sred[t] += sred[t + st]; __syncthreads(); }
    float inv = 1.0f / sred[0];
    for (int r = t; r < NR; r += 128)
        g_cij[r * NC2 + c] = expf(g_bij[r * NC2 + c] - mx) * inv;
}

__global__ void __launch_bounds__(256) k_sj(float* out) {
    __shared__ float sred[256];
    int b = blockIdx.x, c = blockIdx.y, t = threadIdx.x;
    int o = t & 15, rg = t >> 4;
    float acc = 0.f;
    for (int r = rg; r < NR; r += 16)
        acc = fmaf(__ldg(g_cij + r * NC2 + c), g_uhat[(((size_t)b * NR + r) * NC2 + c) * 16 + o], acc);
    sred[t] = acc; __syncthreads();
    for (int st = 8; st >= 1; st >>= 1) { if (rg < st) sred[t] += sred[t + st * 16]; __syncthreads(); }
    if (rg == 0) {
        float s = sred[o];
        float v = s * fabsf(s) / (1.0f + s * s);
        g_v[(b * NC2 + c) * 16 + o] = v;
        if (out) out[(b * NC2 + c) * 16 + o] = v;
    }
}

__global__ void __launch_bounds__(128) k_aij() {
    __shared__ float sred[128];
    int r = blockIdx.x, c = blockIdx.y, t = threadIdx.x;
    int o = t & 15, bg = t >> 4;
    float acc = 0.f;
    for (int b = bg; b < NB; b += 8)
        acc = fmaf(g_uhat[(((size_t)b * NR + r) * NC2 + c) * 16 + o],
                   __ldg(g_v + (b * NC2 + c) * 16 + o), acc);
    sred[t] = acc; __syncthreads();
    for (int st = 64; st >= 1; st >>= 1) { if (t < st) sred[t] += sred[t + st]; __syncthreads(); }
    if (t == 0) g_bij[r * NC2 + c] += sred[0] * (1.0f / NB);
}

__global__ void __launch_bounds__(128) k_cls(const float* __restrict__ w1,
                                             const float* __restrict__ b1,
                                             const float* __restrict__ w2,
                                             const float* __restrict__ b2,
                                             float* out) {
    __shared__ float sfeat[160];
    __shared__ float sred[128];
    int b = blockIdx.x, k = blockIdx.y, t = threadIdx.x;
    for (int j = t; j < 160; j += 128) sfeat[j] = g_v[b * 160 + j];
    __syncthreads();
    float val = 0.f;
    if (t < 100) {
        float acc = __ldg(b1 + k * 100 + t);
        const float* wp = w1 + (size_t)k * 16000 + t;
#pragma unroll 4
        for (int f = 0; f < 160; f++) acc = fmaf(sfeat[f], wp[f * 100], acc);
        val = fmaxf(acc, 0.f) * __ldg(w2 + k * 100 + t);
    }
    sred[t] = val; __syncthreads();
    for (int st = 64; st >= 1; st >>= 1) { if (t < st) sred[t] += sred[t + st]; __syncthreads(); }
    if (t == 0)
        out[40960 + b * NC2 + k] = 1.0f / (1.0f + expf(-(sred[0] + __ldg(b2 + k))));
}

extern "C" void kernel_launch(void* const* d_in, const int* in_sizes, int n_in,
                              void* d_out, int out_size) {
    const float* data    = (const float*)d_in[0];
    const float* conv1_w = (const float*)d_in[1];
    const float* conv1_b = (const float*)d_in[2];
    const float* conv2_w = (const float*)d_in[3];
    const float* conv2_b = (const float*)d_in[4];
    const float* prim_w  = (const float*)d_in[5];
    const float* prim_b  = (const float*)d_in[6];
    const float* W       = (const float*)d_in[7];
    const float* cls_w1  = (const float*)d_in[8];
    const float* cls_b1  = (const float*)d_in[9];
    const float* cls_w2  = (const float*)d_in[10];
    const float* cls_b2  = (const float*)d_in[11];
    float* out = (float*)d_out;

    static int inited = 0;
    if (!inited) {
        cudaFuncSetAttribute(k_conv2mma, cudaFuncAttributeMaxDynamicSharedMemorySize, 2 * BUFB);
        cudaFuncSetAttribute(k_primmma, cudaFuncAttributeMaxDynamicSharedMemorySize, 2 * BUFB);
        inited = 1;
    }

    // order chosen so k_conv2mma is the 4th launch (ncu capture slot)
    k_cvt_w2<<<288, 256>>>(conv2_w);
    k_cvt_pw<<<10368, 256>>>(prim_w);
    k_conv1pool<<<1444, 256>>>(data, conv1_w, conv1_b);
    k_conv2mma<<<dim3(12, NB), 256, 2 * BUFB>>>(conv2_b);
    k_pool2n<<<dim3(25, NB), 256>>>();
    k_primmma<<<dim3(72, 2, 3), 256, 2 * BUFB>>>();
    k_zero<<<45, 256>>>();
    k_squash<<<(NB * NR + 255) / 256, 256>>>(prim_b);
    k_uhat<<<NR, 160>>>(W);

    for (int it = 0; it < 3; it++) {
        k_softmax<<<NC2, 128>>>();
        k_sj<<<dim3(NB, NC2), 256>>>(it == 2 ? out : nullptr);
        if (it < 2) k_aij<<<dim3(NR, NC2), 128>>>();
    }
    k_cls<<<dim3(NB, NC2), 128>>>(cls_w1, cls_b1, cls_w2, cls_b2, out);
}

// round 10
// speedup vs baseline: 1.6207x; 1.0571x over previous
#include <cuda_runtime.h>
#include <cuda_bf16.h>
#include <math.h>
#include <stdint.h>

#define NB 256
#define NR 1152
#define NC2 10
#define LDA 40
#define BUFB 40960
#define BUFE 20480

__device__ __forceinline__ void mma16816(float* d, unsigned a0, unsigned a1, unsigned a2, unsigned a3,
                                         unsigned b0, unsigned b1) {
    asm volatile("mma.sync.aligned.m16n8k16.row.col.f32.bf16.bf16.f32 "
        "{%0,%1,%2,%3}, {%4,%5,%6,%7}, {%8,%9}, {%0,%1,%2,%3};"
        : "+f"(d[0]), "+f"(d[1]), "+f"(d[2]), "+f"(d[3])
        : "r"(a0), "r"(a1), "r"(a2), "r"(a3), "r"(b0), "r"(b1));
}
__device__ __forceinline__ void ldsm_x4(unsigned* r, uint32_t addr) {
    asm volatile("ldmatrix.sync.aligned.m8n8.x4.shared.b16 {%0,%1,%2,%3}, [%4];"
        : "=r"(r[0]), "=r"(r[1]), "=r"(r[2]), "=r"(r[3]) : "r"(addr));
}
__device__ __forceinline__ void bfsplit(float f, __nv_bfloat16& h, __nv_bfloat16& l) {
    h = __float2bfloat16(f);
    l = __float2bfloat16(f - __bfloat162float(h));
}

// ---- scratch ----
__device__ __nv_bfloat16 g_p1h[(size_t)NB * 64 * 1444];
__device__ __nv_bfloat16 g_p1l[(size_t)NB * 64 * 1444];
__device__ float g_c2[(size_t)NB * 1444 * 128];
__device__ __nv_bfloat16 g_p2h[(size_t)NB * 128 * 400];
__device__ __nv_bfloat16 g_p2l[(size_t)NB * 128 * 400];
__device__ __nv_bfloat16 g_w2h[128 * 576];
__device__ __nv_bfloat16 g_w2l[128 * 576];
__device__ __nv_bfloat16 g_pwh[(size_t)256 * 10368];
__device__ __nv_bfloat16 g_pwl[(size_t)256 * 10368];
__device__ float g_upart[(size_t)3 * NB * 9216];
__device__ float g_u[(size_t)NB * 9216];
__device__ float g_uhat[(size_t)NB * NR * NC2 * 16];
__device__ float g_bij[NR * NC2];
__device__ float g_cij[NR * NC2];
__device__ float g_v[NB * NC2 * 16];

__global__ void k_zero() {
    int i = blockIdx.x * blockDim.x + threadIdx.x;
    if (i < NR * NC2) g_bij[i] = 0.f;
}
__global__ void k_cvt_w2(const float* __restrict__ w2) {
    int i = blockIdx.x * blockDim.x + threadIdx.x;
    if (i >= 128 * 576) return;
    __nv_bfloat16 h, l; bfsplit(w2[i], h, l);
    g_w2h[i] = h; g_w2l[i] = l;
}
__global__ void k_cvt_pw(const float* __restrict__ pw) {
    int i = blockIdx.x * blockDim.x + threadIdx.x;
    __nv_bfloat16 h, l; bfsplit(pw[i], h, l);
    g_pwh[i] = h; g_pwl[i] = l;
}

// ---- conv1+relu+pool ----
__global__ void __launch_bounds__(256) k_conv1pool(const float* __restrict__ data,
                                                   const float* __restrict__ w1,
                                                   const float* __restrict__ b1) {
    int idx = blockIdx.x * blockDim.x + threadIdx.x;
    int p = idx % 1444, b = idx / 1444;
    int pj = p / 38, pi = p % 38;
    int y0 = 2 * pj - 1, x0 = 2 * pi - 1;
    float iv[3][4][4];
#pragma unroll
    for (int ic = 0; ic < 3; ic++)
#pragma unroll
        for (int dy = 0; dy < 4; dy++) {
            int yy = y0 + dy;
#pragma unroll
            for (int dx = 0; dx < 4; dx++) {
                int xx = x0 + dx;
                float v = 0.f;
                if (yy >= 0 && yy < 76 && xx >= 0 && xx < 76)
                    v = data[((size_t)(b * 3 + ic) * 76 + yy) * 76 + xx];
                iv[ic][dy][dx] = v;
            }
        }
    bool rv0 = (y0 >= 0), rv1 = (y0 + 1 <= 73), cv0 = (x0 >= 0), cv1 = (x0 + 1 <= 73);
    size_t obase = (size_t)b * 64 * 1444 + (size_t)pj * 38 + pi;
#pragma unroll 1
    for (int oc = 0; oc < 64; oc++) {
        const float* wp = w1 + oc * 27;
        float s00 = 0.f, s01 = 0.f, s10 = 0.f, s11 = 0.f;
#pragma unroll
        for (int k = 0; k < 27; k++) {
            int ic = k / 9, r = (k / 3) % 3, c2 = k % 3;
            float w = __ldg(wp + k);
            s00 = fmaf(iv[ic][r][c2], w, s00);
            s01 = fmaf(iv[ic][r][c2 + 1], w, s01);
            s10 = fmaf(iv[ic][r + 1][c2], w, s10);
            s11 = fmaf(iv[ic][r + 1][c2 + 1], w, s11);
        }
        float bo = __ldg(b1 + oc), m = 0.f;
        if (rv0 && cv0) m = fmaxf(m, s00 + bo);
        if (rv0 && cv1) m = fmaxf(m, s01 + bo);
        if (rv1 && cv0) m = fmaxf(m, s10 + bo);
        if (rv1 && cv1) m = fmaxf(m, s11 + bo);
        __nv_bfloat16 h, l; bfsplit(m, h, l);
        g_p1h[obase + (size_t)oc * 1444] = h;
        g_p1l[obase + (size_t)oc * 1444] = l;
    }
}

// ---- B staging via cp.async ----
__device__ __forceinline__ void stageB_cp(uint32_t dstb, const __nv_bfloat16* __restrict__ srcH,
                                          const __nv_bfloat16* __restrict__ srcL,
                                          int kc, int tid, int wstride, int nbase) {
#pragma unroll
    for (int q = 0; q < 4; q++) {
        int i = tid * 4 + q;
        int half = i >> 9;
        int n = (i & 511) >> 2;
        int seg = i & 3;
        const __nv_bfloat16* src = (half ? srcL : srcH) + (size_t)(nbase + n) * wstride + kc * 32 + seg * 8;
        uint32_t dst = dstb + (half ? 15360 * 2 : 10240 * 2) + ((unsigned)n * LDA + seg * 8) * 2;
        asm volatile("cp.async.ca.shared.global [%0], [%1], 16;" :: "r"(dst), "l"(src));
    }
    asm volatile("cp.async.commit_group;" ::: "memory");
}
__device__ __forceinline__ void cp_wait() {
    asm volatile("cp.async.wait_group 0;" ::: "memory");
}

// ---- gemm: warp tile M=32 x N=64; B fragments reused across 2 M-tiles ----
__device__ __forceinline__ void gemm_chunk(float acc[16][4], uint32_t aH, uint32_t aL,
                                           uint32_t bH, uint32_t bL) {
#pragma unroll
    for (int ks = 0; ks < 2; ks++) {
        unsigned Ah[2][4], Al[2][4];
        ldsm_x4(Ah[0], aH + ks * 32);
        ldsm_x4(Ah[1], aH + 16 * LDA * 2 + ks * 32);
        ldsm_x4(Al[0], aL + ks * 32);
        ldsm_x4(Al[1], aL + 16 * LDA * 2 + ks * 32);
#pragma unroll
        for (int j = 0; j < 4; j++) {
            unsigned Bh[4], Bl[4];
            uint32_t bo = (uint32_t)j * (16 * LDA * 2) + ks * 32;
            ldsm_x4(Bh, bH + bo);
            ldsm_x4(Bl, bL + bo);
#pragma unroll
            for (int mt = 0; mt < 2; mt++) {
                int t0 = mt * 8 + j * 2;
                mma16816(acc[t0],     Ah[mt][0], Ah[mt][1], Ah[mt][2], Ah[mt][3], Bh[0], Bh[1]);
                mma16816(acc[t0],     Al[mt][0], Al[mt][1], Al[mt][2], Al[mt][3], Bh[0], Bh[1]);
                mma16816(acc[t0],     Ah[mt][0], Ah[mt][1], Ah[mt][2], Ah[mt][3], Bl[0], Bl[1]);
                mma16816(acc[t0 + 1], Ah[mt][0], Ah[mt][1], Ah[mt][2], Ah[mt][3], Bh[2], Bh[3]);
                mma16816(acc[t0 + 1], Al[mt][0], Al[mt][1], Al[mt][2], Al[mt][3], Bh[2], Bh[3]);
                mma16816(acc[t0 + 1], Ah[mt][0], Ah[mt][1], Ah[mt][2], Ah[mt][3], Bl[2], Bl[3]);
            }
        }
    }
}

// ---- conv2: double-buffered bf16x3 mma, 4x2 warp tiling ----
__global__ void __launch_bounds__(256) k_conv2mma(const float* __restrict__ b2) {
    extern __shared__ __nv_bfloat16 sm[];
    int tid = threadIdx.x;
    int w = tid >> 5, lane = tid & 31;
    int g = lane >> 2, tg = lane & 3;
    int wm = w & 3, wn = w >> 2;
    int bb = blockIdx.y, strip = blockIdx.x;

    uint32_t smb = (uint32_t)__cvta_generic_to_shared(sm);
    uint32_t aoff = ((unsigned)(wm * 32 + (lane & 15)) * LDA + ((lane & 16) ? 8 : 0)) * 2;
    uint32_t boff = ((unsigned)(wn * 64 + (lane & 7) + ((lane & 16) ? 8 : 0)) * LDA + ((lane & 8) ? 8 : 0)) * 2;

    float acc[16][4];
#pragma unroll
    for (int n = 0; n < 16; n++)
#pragma unroll
        for (int q = 0; q < 4; q++) acc[n][q] = 0.f;

    int mloc = tid & 127;
    int pA = strip * 128 + mloc;
    int yA = pA / 38, xA = pA % 38;
    bool pvA = pA < 1444;
    int khalf = (tid >> 7) * 16;

    auto stageA = [&](__nv_bfloat16* dst, int kc) {
        int k0 = kc * 32 + khalf;
        int ic = k0 / 9, r = k0 - ic * 9;
        int ky = r / 3, kx = r - ky * 3;
        const __nv_bfloat16* sh = g_p1h + ((size_t)bb * 64 + ic) * 1444;
        const __nv_bfloat16* sl = g_p1l + ((size_t)bb * 64 + ic) * 1444;
        __nv_bfloat16* dh = dst + mloc * LDA + khalf;
        __nv_bfloat16* dl = dh + 5120;
#pragma unroll 1
        for (int kk = 0; kk < 16; kk++) {
            int yy = yA + ky - 1, xx = xA + kx - 1;
            bool ok = pvA && yy >= 0 && yy < 38 && xx >= 0 && xx < 38;
            dh[kk] = ok ? sh[yy * 38 + xx] : __nv_bfloat16(0.f);
            dl[kk] = ok ? sl[yy * 38 + xx] : __nv_bfloat16(0.f);
            if (++kx == 3) { kx = 0; if (++ky == 3) { ky = 0; sh += 1444; sl += 1444; } }
        }
    };

    stageA(sm, 0);
    stageB_cp(smb, g_w2h, g_w2l, 0, tid, 576, 0);
    cp_wait();
    __syncthreads();

#pragma unroll 1
    for (int kc = 0; kc < 18; kc++) {
        int par = kc & 1, nxt = kc + 1;
        if (nxt < 18) {
            stageA(sm + (nxt & 1) * BUFE, nxt);
            stageB_cp(smb + (nxt & 1) * BUFB, g_w2h, g_w2l, nxt, tid, 576, 0);
        }
        uint32_t base = smb + par * BUFB;
        gemm_chunk(acc, base + aoff, base + 10240 + aoff,
                        base + 20480 + boff, base + 30720 + boff);
        cp_wait();
        __syncthreads();
    }

#pragma unroll
    for (int mt = 0; mt < 2; mt++) {
        int p0 = strip * 128 + wm * 32 + mt * 16 + g;
        int p1 = p0 + 8;
#pragma unroll
        for (int j = 0; j < 4; j++)
#pragma unroll
            for (int h = 0; h < 2; h++) {
                int t = mt * 8 + j * 2 + h;
                int col = wn * 64 + j * 16 + h * 8 + tg * 2;
                float bc0 = __ldg(b2 + col), bc1 = __ldg(b2 + col + 1);
                if (p0 < 1444) {
                    float2 o; o.x = fmaxf(acc[t][0] + bc0, 0.f); o.y = fmaxf(acc[t][1] + bc1, 0.f);
                    *(float2*)(g_c2 + ((size_t)bb * 1444 + p0) * 128 + col) = o;
                }
                if (p1 < 1444) {
                    float2 o; o.x = fmaxf(acc[t][2] + bc0, 0.f); o.y = fmaxf(acc[t][3] + bc1, 0.f);
                    *(float2*)(g_c2 + ((size_t)bb * 1444 + p1) * 128 + col) = o;
                }
            }
    }
}

// ---- maxpool -> channel-major bf16 hi/lo ----
__global__ void __launch_bounds__(256) k_pool2n() {
    __shared__ float s[16 * 129];
    int b = blockIdx.y, t0 = blockIdx.x;
    int tid = threadIdx.x;
    for (int i = tid; i < 2048; i += 256) {
        int p2l = i >> 7, oc = i & 127;
        int p2 = t0 * 16 + p2l;
        int pj = p2 / 20, pi = p2 % 20;
        int y0 = 2 * pj - 1, x0 = 2 * pi - 1;
        float m = 0.f;
#pragma unroll
        for (int dy = 0; dy < 2; dy++) {
            int y = y0 + dy; if (y < 0 || y > 37) continue;
#pragma unroll
            for (int dx = 0; dx < 2; dx++) {
                int x = x0 + dx; if (x < 0 || x > 37) continue;
                m = fmaxf(m, g_c2[((size_t)b * 1444 + y * 38 + x) * 128 + oc]);
            }
        }
        s[p2l * 129 + oc] = m;
    }
    __syncthreads();
    for (int i = tid; i < 2048; i += 256) {
        int oc = i >> 4, p2l = i & 15;
        __nv_bfloat16 h, l; bfsplit(s[p2l * 129 + oc], h, l);
        size_t o = ((size_t)(b * 128 + oc)) * 400 + t0 * 16 + p2l;
        g_p2h[o] = h; g_p2l[o] = l;
    }
}

// ---- PrimaryCaps: double-buffered, K-split x3, 4x2 warp tiling ----
__global__ void __launch_bounds__(256) k_primmma() {
    extern __shared__ __nv_bfloat16 sm[];
    int tid = threadIdx.x;
    int w = tid >> 5, lane = tid & 31;
    int g = lane >> 2, tg = lane & 3;
    int wm = w & 3, wn = w >> 2;
    int mb = blockIdx.x, ny = blockIdx.y, zz = blockIdx.z;

    uint32_t smb = (uint32_t)__cvta_generic_to_shared(sm);
    uint32_t aoff = ((unsigned)(wm * 32 + (lane & 15)) * LDA + ((lane & 16) ? 8 : 0)) * 2;
    uint32_t boff = ((unsigned)(wn * 64 + (lane & 7) + ((lane & 16) ? 8 : 0)) * LDA + ((lane & 8) ? 8 : 0)) * 2;

    float acc[16][4];
#pragma unroll
    for (int n = 0; n < 16; n++)
#pragma unroll
        for (int q = 0; q < 4; q++) acc[n][q] = 0.f;

    int mloc = tid & 127;
    int mA = mb * 128 + mloc;
    int bA = mA / 36, posA = mA % 36;
    int sjA = posA / 6, siA = posA % 6;
    const __nv_bfloat16* p2hB = g_p2h + (size_t)bA * 51200;
    const __nv_bfloat16* p2lB = g_p2l + (size_t)bA * 51200;
    int khalf = (tid >> 7) * 16;

    auto stageA = [&](__nv_bfloat16* dst, int kc) {
        int k0 = kc * 32 + khalf;
        int ic = k0 / 81, r = k0 - ic * 81;
        int ky = r / 9, kx = r - ky * 9;
        int off = ic * 400 + (2 * sjA + ky) * 20 + 2 * siA + kx;
        __nv_bfloat16* dh = dst + mloc * LDA + khalf;
        __nv_bfloat16* dl = dh + 5120;
#pragma unroll 1
        for (int kk = 0; kk < 16; kk++) {
            dh[kk] = p2hB[off];
            dl[kk] = p2lB[off];
            if (++kx == 9) { kx = 0; if (++ky == 9) { ky = 0; off += 232; } else off += 12; }
            else off++;
        }
    };

    int kc0 = zz * 108, kc1 = kc0 + 108;
    stageA(sm, kc0);
    stageB_cp(smb, g_pwh, g_pwl, kc0, tid, 10368, ny * 128);
    cp_wait();
    __syncthreads();

#pragma unroll 1
    for (int kc = kc0; kc < kc1; kc++) {
        int par = kc & 1, nxt = kc + 1;
        if (nxt < kc1) {
            stageA(sm + (nxt & 1) * BUFE, nxt);
            stageB_cp(smb + (nxt & 1) * BUFB, g_pwh, g_pwl, nxt, tid, 10368, ny * 128);
        }
        uint32_t base = smb + par * BUFB;
        gemm_chunk(acc, base + aoff, base + 10240 + aoff,
                        base + 20480 + boff, base + 30720 + boff);
        cp_wait();
        __syncthreads();
    }

    float* up = g_upart + (size_t)zz * NB * 9216;
#pragma unroll
    for (int mt = 0; mt < 2; mt++) {
        int m0 = mb * 128 + wm * 32 + mt * 16 + g;
        int m1 = m0 + 8;
        int b0 = m0 / 36, pos0 = m0 % 36;
        int b1i = m1 / 36, pos1 = m1 % 36;
#pragma unroll
        for (int j = 0; j < 4; j++)
#pragma unroll
            for (int h = 0; h < 2; h++) {
                int t = mt * 8 + j * 2 + h;
                int col = ny * 128 + wn * 64 + j * 16 + h * 8 + tg * 2;
                up[(size_t)b0 * 9216 + (size_t)col * 36 + pos0] = acc[t][0];
                up[(size_t)b0 * 9216 + (size_t)(col + 1) * 36 + pos0] = acc[t][1];
                up[(size_t)b1i * 9216 + (size_t)col * 36 + pos1] = acc[t][2];
                up[(size_t)b1i * 9216 + (size_t)(col + 1) * 36 + pos1] = acc[t][3];
            }
    }
}

// ---- squash ----
__global__ void k_squash(const float* __restrict__ pb) {
    int idx = blockIdx.x * blockDim.x + threadIdx.x;
    if (idx >= NB * NR) return;
    int r = idx % NR;
    size_t base = (size_t)idx * 8;
    const size_t UP = (size_t)NB * 9216;
    float e[8];
    float sn = 0.f;
#pragma unroll
    for (int j = 0; j < 8; j++) {
        int oc = (r * 8 + j) / 36;
        float v = g_upart[base + j] + g_upart[UP + base + j] + g_upart[2 * UP + base + j]
                + __ldg(pb + oc);
        e[j] = v;
        sn = fmaf(v, v, sn);
    }
    float f = sqrtf(sn) / (1.0f + sn);
    float4 o0 = make_float4(e[0] * f, e[1] * f, e[2] * f, e[3] * f);
    float4 o1 = make_float4(e[4] * f, e[5] * f, e[6] * f, e[7] * f);
    float4* o = (float4*)(g_u + base);
    o[0] = o0; o[1] = o1;
}

__global__ void __launch_bounds__(160) k_uhat(const float* __restrict__ W) {
    __shared__ float sWT[1280];
    int r = blockIdx.x, t = threadIdx.x;
    for (int j = t; j < 1280; j += 160)
        sWT[j] = W[(size_t)r * 1280 + (j % 160) * 8 + j / 160];
    __syncthreads();
    float w0 = sWT[t], w1 = sWT[160+t], w2 = sWT[320+t], w3 = sWT[480+t];
    float w4 = sWT[640+t], w5 = sWT[800+t], w6 = sWT[960+t], w7 = sWT[1120+t];
#pragma unroll 4
    for (int b = 0; b < NB; b++) {
        const float4* up = (const float4*)(g_u + (size_t)b * 9216 + r * 8);
        float4 ua = up[0], ub = up[1];
        g_uhat[((size_t)b * NR + r) * 160 + t] =
            ua.x*w0 + ua.y*w1 + ua.z*w2 + ua.w*w3 + ub.x*w4 + ub.y*w5 + ub.z*w6 + ub.w*w7;
    }
}

__global__ void k_softmax() {
    __shared__ float sred[128];
    int c = blockIdx.x, t = threadIdx.x;
    float mx = -1e30f;
    for (int r = t; r < NR; r += 128) mx = fmaxf(mx, g_bij[r * NC2 + c]);
    sred[t] = mx; __syncthreads();
    for (int st = 64; st >= 1; st >>= 1) { if (t < st) sred[t] = fmaxf(sred[t], sred[t + st]); __syncthreads(); }
    mx = sred[0]; __syncthreads();
    float sm = 0.f;
    for (int r = t; r < NR; r += 128) sm += expf(g_bij[r * NC2 + c] - mx);
    sred[t] = sm; __syncthreads();
    for (int st = 64; st >= 1; st >>= 1) { if (t < st) sred[t] += sred[t + st]; __syncthreads(); }
    float inv = 1.0f / sred[0];
    for (int r = t; r < NR; r += 128)
        g_cij[r * NC2 + c] = expf(g_bij[r * NC2 + c] - mx) * inv;
}

__global__ void __launch_bounds__(256) k_sj(float* out) {
    __shared__ float sred[256];
    int b = blockIdx.x, c = blockIdx.y, t = threadIdx.x;
    int o = t & 15, rg = t >> 4;
    float acc = 0.f;
    for (int r = rg; r < NR; r += 16)
        acc = fmaf(__ldg(g_cij + r * NC2 + c), g_uhat[(((size_t)b * NR + r) * NC2 + c) * 16 + o], acc);
    sred[t] = acc; __syncthreads();
    for (int st = 8; st >= 1; st >>= 1) { if (rg < st) sred[t] += sred[t + st * 16]; __syncthreads(); }
    if (rg == 0) {
        float s = sred[o];
        float v = s * fabsf(s) / (1.0f + s * s);
        g_v[(b * NC2 + c) * 16 + o] = v;
        if (out) out[(b * NC2 + c) * 16 + o] = v;
    }
}

__global__ void __launch_bounds__(128) k_aij() {
    __shared__ float sred[128];
    int r = blockIdx.x, c = blockIdx.y, t = threadIdx.x;
    int o = t & 15, bg = t >> 4;
    float acc = 0.f;
    for (int b = bg; b < NB; b += 8)
        acc = fmaf(g_uhat[(((size_t)b * NR + r) * NC2 + c) * 16 + o],
                   __ldg(g_v + (b * NC2 + c) * 16 + o), acc);
    sred[t] = acc; __syncthreads();
    for (int st = 64; st >= 1; st >>= 1) { if (t < st) sred[t] += sred[t + st]; __syncthreads(); }
    if (t == 0) g_bij[r * NC2 + c] += sred[0] * (1.0f / NB);
}

__global__ void __launch_bounds__(128) k_cls(const float* __restrict__ w1,
                                             const float* __restrict__ b1,
                                             const float* __restrict__ w2,
                                             const float* __restrict__ b2,
                                             float* out) {
    __shared__ float sfeat[160];
    __shared__ float sred[128];
    int b = blockIdx.x, k = blockIdx.y, t = threadIdx.x;
    for (int j = t; j < 160; j += 128) sfeat[j] = g_v[b * 160 + j];
    __syncthreads();
    float val = 0.f;
    if (t < 100) {
        float acc = __ldg(b1 + k * 100 + t);
        const float* wp = w1 + (size_t)k * 16000 + t;
#pragma unroll 4
        for (int f = 0; f < 160; f++) acc = fmaf(sfeat[f], wp[f * 100], acc);
        val = fmaxf(acc, 0.f) * __ldg(w2 + k * 100 + t);
    }
    sred[t] = val; __syncthreads();
    for (int st = 64; st >= 1; st >>= 1) { if (t < st) sred[t] += sred[t + st]; __syncthreads(); }
    if (t == 0)
        out[40960 + b * NC2 + k] = 1.0f / (1.0f + expf(-(sred[0] + __ldg(b2 + k))));
}

extern "C" void kernel_launch(void* const* d_in, const int* in_sizes, int n_in,
                              void* d_out, int out_size) {
    const float* data    = (const float*)d_in[0];
    const float* conv1_w = (const float*)d_in[1];
    const float* conv1_b = (const float*)d_in[2];
    const float* conv2_w = (const float*)d_in[3];
    const float* conv2_b = (const float*)d_in[4];
    const float* prim_w  = (const float*)d_in[5];
    const float* prim_b  = (const float*)d_in[6];
    const float* W       = (const float*)d_in[7];
    const float* cls_w1  = (const float*)d_in[8];
    const float* cls_b1  = (const float*)d_in[9];
    const float* cls_w2  = (const float*)d_in[10];
    const float* cls_b2  = (const float*)d_in[11];
    float* out = (float*)d_out;

    static int inited = 0;
    if (!inited) {
        cudaFuncSetAttribute(k_conv2mma, cudaFuncAttributeMaxDynamicSharedMemorySize, 2 * BUFB);
        cudaFuncSetAttribute(k_primmma, cudaFuncAttributeMaxDynamicSharedMemorySize, 2 * BUFB);
        inited = 1;
    }

    k_cvt_w2<<<288, 256>>>(conv2_w);
    k_cvt_pw<<<10368, 256>>>(prim_w);
    k_conv1pool<<<1444, 256>>>(data, conv1_w, conv1_b);
    k_conv2mma<<<dim3(12, NB), 256, 2 * BUFB>>>(conv2_b);
    k_pool2n<<<dim3(25, NB), 256>>>();
    k_primmma<<<dim3(72, 2, 3), 256, 2 * BUFB>>>();
    k_zero<<<45, 256>>>();
    k_squash<<<(NB * NR + 255) / 256, 256>>>(prim_b);
    k_uhat<<<NR, 160>>>(W);

    for (int it = 0; it < 3; it++) {
        k_softmax<<<NC2, 128>>>();
        k_sj<<<dim3(NB, NC2), 256>>>(it == 2 ? out : nullptr);
        if (it < 2) k_aij<<<dim3(NR, NC2), 128>>>();
    }
    k_cls<<<dim3(NB, NC2), 128>>>(cls_w1, cls_b1, cls_w2, cls_b2, out);
}

// round 11
// speedup vs baseline: 1.7960x; 1.1082x over previous
#include <cuda_runtime.h>
#include <cuda_bf16.h>
#include <math.h>
#include <stdint.h>

#define NB 256
#define NR 1152
#define NC2 10
#define LDA 40
#define BUFB 40960
#define BUFE 20480

__device__ __forceinline__ void mma16816(float* d, unsigned a0, unsigned a1, unsigned a2, unsigned a3,
                                         unsigned b0, unsigned b1) {
    asm volatile("mma.sync.aligned.m16n8k16.row.col.f32.bf16.bf16.f32 "
        "{%0,%1,%2,%3}, {%4,%5,%6,%7}, {%8,%9}, {%0,%1,%2,%3};"
        : "+f"(d[0]), "+f"(d[1]), "+f"(d[2]), "+f"(d[3])
        : "r"(a0), "r"(a1), "r"(a2), "r"(a3), "r"(b0), "r"(b1));
}
__device__ __forceinline__ void ldsm_x4(unsigned* r, uint32_t addr) {
    asm volatile("ldmatrix.sync.aligned.m8n8.x4.shared.b16 {%0,%1,%2,%3}, [%4];"
        : "=r"(r[0]), "=r"(r[1]), "=r"(r[2]), "=r"(r[3]) : "r"(addr));
}
__device__ __forceinline__ void bfsplit(float f, __nv_bfloat16& h, __nv_bfloat16& l) {
    h = __float2bfloat16(f);
    l = __float2bfloat16(f - __bfloat162float(h));
}
__device__ __forceinline__ unsigned packhl(float f) {
    __nv_bfloat16 h, l; bfsplit(f, h, l);
    return (unsigned)__bfloat16_as_ushort(h) | ((unsigned)__bfloat16_as_ushort(l) << 16);
}

// ---- scratch ----
__device__ unsigned g_p1p[(size_t)NB * 64 * 1444];        // conv1 out packed h|l<<16
__device__ float g_c2[(size_t)NB * 1444 * 128];
__device__ unsigned g_p2p[(size_t)NB * 128 * 400];        // pool2 packed, channel-major
__device__ __nv_bfloat16 g_w2h[128 * 576];
__device__ __nv_bfloat16 g_w2l[128 * 576];
__device__ __nv_bfloat16 g_pwh[(size_t)256 * 10368];
__device__ __nv_bfloat16 g_pwl[(size_t)256 * 10368];
__device__ float g_upart[(size_t)3 * NB * 9216];
__device__ float g_u[(size_t)NB * 9216];
__device__ float g_uhat[(size_t)NB * NR * NC2 * 16];
__device__ float g_bij[NR * NC2];
__device__ float g_cij[NR * NC2];
__device__ float g_v[NB * NC2 * 16];

__global__ void k_zero() {
    int i = blockIdx.x * blockDim.x + threadIdx.x;
    if (i < NR * NC2) g_bij[i] = 0.f;
}
__global__ void k_cvt_w2(const float* __restrict__ w2) {
    int i = blockIdx.x * blockDim.x + threadIdx.x;
    if (i >= 128 * 576) return;
    __nv_bfloat16 h, l; bfsplit(w2[i], h, l);
    g_w2h[i] = h; g_w2l[i] = l;
}
__global__ void k_cvt_pw(const float* __restrict__ pw) {
    int i = blockIdx.x * blockDim.x + threadIdx.x;
    __nv_bfloat16 h, l; bfsplit(pw[i], h, l);
    g_pwh[i] = h; g_pwl[i] = l;
}

// ---- conv1+relu+pool, packed output ----
__global__ void __launch_bounds__(256) k_conv1pool(const float* __restrict__ data,
                                                   const float* __restrict__ w1,
                                                   const float* __restrict__ b1) {
    int idx = blockIdx.x * blockDim.x + threadIdx.x;
    int p = idx % 1444, b = idx / 1444;
    int pj = p / 38, pi = p % 38;
    int y0 = 2 * pj - 1, x0 = 2 * pi - 1;
    float iv[3][4][4];
#pragma unroll
    for (int ic = 0; ic < 3; ic++)
#pragma unroll
        for (int dy = 0; dy < 4; dy++) {
            int yy = y0 + dy;
#pragma unroll
            for (int dx = 0; dx < 4; dx++) {
                int xx = x0 + dx;
                float v = 0.f;
                if (yy >= 0 && yy < 76 && xx >= 0 && xx < 76)
                    v = data[((size_t)(b * 3 + ic) * 76 + yy) * 76 + xx];
                iv[ic][dy][dx] = v;
            }
        }
    bool rv0 = (y0 >= 0), rv1 = (y0 + 1 <= 73), cv0 = (x0 >= 0), cv1 = (x0 + 1 <= 73);
    size_t obase = (size_t)b * 64 * 1444 + (size_t)pj * 38 + pi;
#pragma unroll 1
    for (int oc = 0; oc < 64; oc++) {
        const float* wp = w1 + oc * 27;
        float s00 = 0.f, s01 = 0.f, s10 = 0.f, s11 = 0.f;
#pragma unroll
        for (int k = 0; k < 27; k++) {
            int ic = k / 9, r = (k / 3) % 3, c2 = k % 3;
            float w = __ldg(wp + k);
            s00 = fmaf(iv[ic][r][c2], w, s00);
            s01 = fmaf(iv[ic][r][c2 + 1], w, s01);
            s10 = fmaf(iv[ic][r + 1][c2], w, s10);
            s11 = fmaf(iv[ic][r + 1][c2 + 1], w, s11);
        }
        float bo = __ldg(b1 + oc), m = 0.f;
        if (rv0 && cv0) m = fmaxf(m, s00 + bo);
        if (rv0 && cv1) m = fmaxf(m, s01 + bo);
        if (rv1 && cv0) m = fmaxf(m, s10 + bo);
        if (rv1 && cv1) m = fmaxf(m, s11 + bo);
        g_p1p[obase + (size_t)oc * 1444] = packhl(m);
    }
}

// ---- B staging via cp.async ----
__device__ __forceinline__ void stageB_cp(uint32_t dstb, const __nv_bfloat16* __restrict__ srcH,
                                          const __nv_bfloat16* __restrict__ srcL,
                                          int kc, int tid, int wstride, int nbase) {
#pragma unroll
    for (int q = 0; q < 4; q++) {
        int i = tid * 4 + q;
        int half = i >> 9;
        int n = (i & 511) >> 2;
        int seg = i & 3;
        const __nv_bfloat16* src = (half ? srcL : srcH) + (size_t)(nbase + n) * wstride + kc * 32 + seg * 8;
        uint32_t dst = dstb + (half ? 15360 * 2 : 10240 * 2) + ((unsigned)n * LDA + seg * 8) * 2;
        asm volatile("cp.async.ca.shared.global [%0], [%1], 16;" :: "r"(dst), "l"(src));
    }
    asm volatile("cp.async.commit_group;" ::: "memory");
}
__device__ __forceinline__ void cp_wait() {
    asm volatile("cp.async.wait_group 0;" ::: "memory");
}

// ---- gemm: warp tile M=32 x N=64 ----
__device__ __forceinline__ void gemm_chunk(float acc[16][4], uint32_t aH, uint32_t aL,
                                           uint32_t bH, uint32_t bL) {
#pragma unroll
    for (int ks = 0; ks < 2; ks++) {
        unsigned Ah[2][4], Al[2][4];
        ldsm_x4(Ah[0], aH + ks * 32);
        ldsm_x4(Ah[1], aH + 16 * LDA * 2 + ks * 32);
        ldsm_x4(Al[0], aL + ks * 32);
        ldsm_x4(Al[1], aL + 16 * LDA * 2 + ks * 32);
#pragma unroll
        for (int j = 0; j < 4; j++) {
            unsigned Bh[4], Bl[4];
            uint32_t bo = (uint32_t)j * (16 * LDA * 2) + ks * 32;
            ldsm_x4(Bh, bH + bo);
            ldsm_x4(Bl, bL + bo);
#pragma unroll
            for (int mt = 0; mt < 2; mt++) {
                int t0 = mt * 8 + j * 2;
                mma16816(acc[t0],     Ah[mt][0], Ah[mt][1], Ah[mt][2], Ah[mt][3], Bh[0], Bh[1]);
                mma16816(acc[t0],     Al[mt][0], Al[mt][1], Al[mt][2], Al[mt][3], Bh[0], Bh[1]);
                mma16816(acc[t0],     Ah[mt][0], Ah[mt][1], Ah[mt][2], Ah[mt][3], Bl[0], Bl[1]);
                mma16816(acc[t0 + 1], Ah[mt][0], Ah[mt][1], Ah[mt][2], Ah[mt][3], Bh[2], Bh[3]);
                mma16816(acc[t0 + 1], Al[mt][0], Al[mt][1], Al[mt][2], Al[mt][3], Bh[2], Bh[3]);
                mma16816(acc[t0 + 1], Ah[mt][0], Ah[mt][1], Ah[mt][2], Ah[mt][3], Bl[2], Bl[3]);
            }
        }
    }
}

// ---- conv2: double-buffered bf16x3 mma, packed A staging w/ STS.128 ----
__global__ void __launch_bounds__(256) k_conv2mma(const float* __restrict__ b2) {
    extern __shared__ __nv_bfloat16 sm[];
    int tid = threadIdx.x;
    int w = tid >> 5, lane = tid & 31;
    int g = lane >> 2, tg = lane & 3;
    int wm = w & 3, wn = w >> 2;
    int bb = blockIdx.y, strip = blockIdx.x;

    uint32_t smb = (uint32_t)__cvta_generic_to_shared(sm);
    uint32_t aoff = ((unsigned)(wm * 32 + (lane & 15)) * LDA + ((lane & 16) ? 8 : 0)) * 2;
    uint32_t boff = ((unsigned)(wn * 64 + (lane & 7) + ((lane & 16) ? 8 : 0)) * LDA + ((lane & 8) ? 8 : 0)) * 2;

    float acc[16][4];
#pragma unroll
    for (int n = 0; n < 16; n++)
#pragma unroll
        for (int q = 0; q < 4; q++) acc[n][q] = 0.f;

    int mloc = tid & 127;
    int ubase = (tid >> 7) * 2;
    int pA = strip * 128 + mloc;
    int yA = pA / 38, xA = pA % 38;
    bool pvA = pA < 1444;
    const unsigned* srcp = g_p1p + (size_t)bb * 64 * 1444;

    auto stageA = [&](__nv_bfloat16* dst, int kc) {
        char* db = (char*)dst;
#pragma unroll
        for (int uu = 0; uu < 2; uu++) {
            int u = ubase + uu;
            int k = kc * 32 + u * 8;
            int ic = k / 9, r = k - ic * 9;
            int ky = r / 3, kx = r - ky * 3;
            unsigned hw[4], lw[4];
#pragma unroll
            for (int jj = 0; jj < 4; jj++) {
                unsigned p0 = 0, p1 = 0;
                {
                    int yy = yA + ky - 1, xx = xA + kx - 1;
                    if (pvA && yy >= 0 && yy < 38 && xx >= 0 && xx < 38)
                        p0 = srcp[ic * 1444 + yy * 38 + xx];
                    if (++kx == 3) { kx = 0; if (++ky == 3) { ky = 0; ic++; } }
                }
                {
                    int yy = yA + ky - 1, xx = xA + kx - 1;
                    if (pvA && yy >= 0 && yy < 38 && xx >= 0 && xx < 38)
                        p1 = srcp[ic * 1444 + yy * 38 + xx];
                    if (++kx == 3) { kx = 0; if (++ky == 3) { ky = 0; ic++; } }
                }
                hw[jj] = __byte_perm(p0, p1, 0x5410);
                lw[jj] = __byte_perm(p0, p1, 0x7632);
            }
            *(uint4*)(db + mloc * 80 + u * 16) = make_uint4(hw[0], hw[1], hw[2], hw[3]);
            *(uint4*)(db + 10240 + mloc * 80 + u * 16) = make_uint4(lw[0], lw[1], lw[2], lw[3]);
        }
    };

    stageA(sm, 0);
    stageB_cp(smb, g_w2h, g_w2l, 0, tid, 576, 0);
    cp_wait();
    __syncthreads();

#pragma unroll 1
    for (int kc = 0; kc < 18; kc++) {
        int par = kc & 1, nxt = kc + 1;
        if (nxt < 18) {
            stageA(sm + (nxt & 1) * BUFE, nxt);
            stageB_cp(smb + (nxt & 1) * BUFB, g_w2h, g_w2l, nxt, tid, 576, 0);
        }
        uint32_t base = smb + par * BUFB;
        gemm_chunk(acc, base + aoff, base + 10240 + aoff,
                        base + 20480 + boff, base + 30720 + boff);
        cp_wait();
        __syncthreads();
    }

#pragma unroll
    for (int mt = 0; mt < 2; mt++) {
        int p0 = strip * 128 + wm * 32 + mt * 16 + g;
        int p1 = p0 + 8;
#pragma unroll
        for (int j = 0; j < 4; j++)
#pragma unroll
            for (int h = 0; h < 2; h++) {
                int t = mt * 8 + j * 2 + h;
                int col = wn * 64 + j * 16 + h * 8 + tg * 2;
                float bc0 = __ldg(b2 + col), bc1 = __ldg(b2 + col + 1);
                if (p0 < 1444) {
                    float2 o; o.x = fmaxf(acc[t][0] + bc0, 0.f); o.y = fmaxf(acc[t][1] + bc1, 0.f);
                    *(float2*)(g_c2 + ((size_t)bb * 1444 + p0) * 128 + col) = o;
                }
                if (p1 < 1444) {
                    float2 o; o.x = fmaxf(acc[t][2] + bc0, 0.f); o.y = fmaxf(acc[t][3] + bc1, 0.f);
                    *(float2*)(g_c2 + ((size_t)bb * 1444 + p1) * 128 + col) = o;
                }
            }
    }
}

// ---- maxpool -> channel-major packed ----
__global__ void __launch_bounds__(256) k_pool2n() {
    __shared__ float s[16 * 129];
    int b = blockIdx.y, t0 = blockIdx.x;
    int tid = threadIdx.x;
    for (int i = tid; i < 2048; i += 256) {
        int p2l = i >> 7, oc = i & 127;
        int p2 = t0 * 16 + p2l;
        int pj = p2 / 20, pi = p2 % 20;
        int y0 = 2 * pj - 1, x0 = 2 * pi - 1;
        float m = 0.f;
#pragma unroll
        for (int dy = 0; dy < 2; dy++) {
            int y = y0 + dy; if (y < 0 || y > 37) continue;
#pragma unroll
            for (int dx = 0; dx < 2; dx++) {
                int x = x0 + dx; if (x < 0 || x > 37) continue;
                m = fmaxf(m, g_c2[((size_t)b * 1444 + y * 38 + x) * 128 + oc]);
            }
        }
        s[p2l * 129 + oc] = m;
    }
    __syncthreads();
    for (int i = tid; i < 2048; i += 256) {
        int oc = i >> 4, p2l = i & 15;
        g_p2p[((size_t)(b * 128 + oc)) * 400 + t0 * 16 + p2l] = packhl(s[p2l * 129 + oc]);
    }
}

// ---- PrimaryCaps: double-buffered, K-split x3, packed A staging ----
__global__ void __launch_bounds__(256) k_primmma() {
    extern __shared__ __nv_bfloat16 sm[];
    int tid = threadIdx.x;
    int w = tid >> 5, lane = tid & 31;
    int g = lane >> 2, tg = lane & 3;
    int wm = w & 3, wn = w >> 2;
    int mb = blockIdx.x, ny = blockIdx.y, zz = blockIdx.z;

    uint32_t smb = (uint32_t)__cvta_generic_to_shared(sm);
    uint32_t aoff = ((unsigned)(wm * 32 + (lane & 15)) * LDA + ((lane & 16) ? 8 : 0)) * 2;
    uint32_t boff = ((unsigned)(wn * 64 + (lane & 7) + ((lane & 16) ? 8 : 0)) * LDA + ((lane & 8) ? 8 : 0)) * 2;

    float acc[16][4];
#pragma unroll
    for (int n = 0; n < 16; n++)
#pragma unroll
        for (int q = 0; q < 4; q++) acc[n][q] = 0.f;

    int mloc = tid & 127;
    int ubase = (tid >> 7) * 2;
    int mA = mb * 128 + mloc;
    int bA = mA / 36, posA = mA % 36;
    int sjA = posA / 6, siA = posA % 6;
    const unsigned* p2p = g_p2p + (size_t)bA * 51200;

    auto stageA = [&](__nv_bfloat16* dst, int kc) {
        char* db = (char*)dst;
#pragma unroll
        for (int uu = 0; uu < 2; uu++) {
            int u = ubase + uu;
            int k = kc * 32 + u * 8;
            int ic = k / 81, r = k - ic * 81;
            int ky = r / 9, kx = r - ky * 9;
            int off = ic * 400 + (2 * sjA + ky) * 20 + 2 * siA + kx;
            unsigned hw[4], lw[4];
#pragma unroll
            for (int jj = 0; jj < 4; jj++) {
                unsigned p0 = p2p[off];
                if (++kx == 9) { kx = 0; if (++ky == 9) { ky = 0; off += 232; } else off += 12; }
                else off++;
                unsigned p1 = p2p[off];
                if (++kx == 9) { kx = 0; if (++ky == 9) { ky = 0; off += 232; } else off += 12; }
                else off++;
                hw[jj] = __byte_perm(p0, p1, 0x5410);
                lw[jj] = __byte_perm(p0, p1, 0x7632);
            }
            *(uint4*)(db + mloc * 80 + u * 16) = make_uint4(hw[0], hw[1], hw[2], hw[3]);
            *(uint4*)(db + 10240 + mloc * 80 + u * 16) = make_uint4(lw[0], lw[1], lw[2], lw[3]);
        }
    };

    int kc0 = zz * 108, kc1 = kc0 + 108;
    stageA(sm, kc0);
    stageB_cp(smb, g_pwh, g_pwl, kc0, tid, 10368, ny * 128);
    cp_wait();
    __syncthreads();

#pragma unroll 1
    for (int kc = kc0; kc < kc1; kc++) {
        int par = kc & 1, nxt = kc + 1;
        if (nxt < kc1) {
            stageA(sm + (nxt & 1) * BUFE, nxt);
            stageB_cp(smb + (nxt & 1) * BUFB, g_pwh, g_pwl, nxt, tid, 10368, ny * 128);
        }
        uint32_t base = smb + par * BUFB;
        gemm_chunk(acc, base + aoff, base + 10240 + aoff,
                        base + 20480 + boff, base + 30720 + boff);
        cp_wait();
        __syncthreads();
    }

    float* up = g_upart + (size_t)zz * NB * 9216;
#pragma unroll
    for (int mt = 0; mt < 2; mt++) {
        int m0 = mb * 128 + wm * 32 + mt * 16 + g;
        int m1 = m0 + 8;
        int b0 = m0 / 36, pos0 = m0 % 36;
        int b1i = m1 / 36, pos1 = m1 % 36;
#pragma unroll
        for (int j = 0; j < 4; j++)
#pragma unroll
            for (int h = 0; h < 2; h++) {
                int t = mt * 8 + j * 2 + h;
                int col = ny * 128 + wn * 64 + j * 16 + h * 8 + tg * 2;
                up[(size_t)b0 * 9216 + (size_t)col * 36 + pos0] = acc[t][0];
                up[(size_t)b0 * 9216 + (size_t)(col + 1) * 36 + pos0] = acc[t][1];
                up[(size_t)b1i * 9216 + (size_t)col * 36 + pos1] = acc[t][2];
                up[(size_t)b1i * 9216 + (size_t)(col + 1) * 36 + pos1] = acc[t][3];
            }
    }
}

// ---- squash ----
__global__ void k_squash(const float* __restrict__ pb) {
    int idx = blockIdx.x * blockDim.x + threadIdx.x;
    if (idx >= NB * NR) return;
    int r = idx % NR;
    size_t base = (size_t)idx * 8;
    const size_t UP = (size_t)NB * 9216;
    float e[8];
    float sn = 0.f;
#pragma unroll
    for (int j = 0; j < 8; j++) {
        int oc = (r * 8 + j) / 36;
        float v = g_upart[base + j] + g_upart[UP + base + j] + g_upart[2 * UP + base + j]
                + __ldg(pb + oc);
        e[j] = v;
        sn = fmaf(v, v, sn);
    }
    float f = sqrtf(sn) / (1.0f + sn);
    float4 o0 = make_float4(e[0] * f, e[1] * f, e[2] * f, e[3] * f);
    float4 o1 = make_float4(e[4] * f, e[5] * f, e[6] * f, e[7] * f);
    float4* o = (float4*)(g_u + base);
    o[0] = o0; o[1] = o1;
}

__global__ void __launch_bounds__(160) k_uhat(const float* __restrict__ W) {
    __shared__ float sWT[1280];
    int r = blockIdx.x, t = threadIdx.x;
    for (int j = t; j < 1280; j += 160)
        sWT[j] = W[(size_t)r * 1280 + (j % 160) * 8 + j / 160];
    __syncthreads();
    float w0 = sWT[t], w1 = sWT[160+t], w2 = sWT[320+t], w3 = sWT[480+t];
    float w4 = sWT[640+t], w5 = sWT[800+t], w6 = sWT[960+t], w7 = sWT[1120+t];
#pragma unroll 4
    for (int b = 0; b < NB; b++) {
        const float4* up = (const float4*)(g_u + (size_t)b * 9216 + r * 8);
        float4 ua = up[0], ub = up[1];
        g_uhat[((size_t)b * NR + r) * 160 + t] =
            ua.x*w0 + ua.y*w1 + ua.z*w2 + ua.w*w3 + ub.x*w4 + ub.y*w5 + ub.z*w6 + ub.w*w7;
    }
}

__global__ void k_softmax() {
    __shared__ float sred[128];
    int c = blockIdx.x, t = threadIdx.x;
    float mx = -1e30f;
    for (int r = t; r < NR; r += 128) mx = fmaxf(mx, g_bij[r * NC2 + c]);
    sred[t] = mx; __syncthreads();
    for (int st = 64; st >= 1; st >>= 1) { if (t < st) sred[t] = fmaxf(sred[t], sred[t + st]); __syncthreads(); }
    mx = sred[0]; __syncthreads();
    float sm = 0.f;
    for (int r = t; r < NR; r += 128) sm += expf(g_bij[r * NC2 + c] - mx);
    sred[t] = sm; __syncthreads();
    for (int st = 64; st >= 1; st >>= 1) { if (t < st) sred[t] += sred[t + st]; __syncthreads(); }
    float inv = 1.0f / sred[0];
    for (int r = t; r < NR; r += 128)
        g_cij[r * NC2 + c] = expf(g_bij[r * NC2 + c] - mx) * inv;
}

__global__ void __launch_bounds__(256) k_sj(float* out) {
    __shared__ float sred[256];
    int b = blockIdx.x, c = blockIdx.y, t = threadIdx.x;
    int o = t & 15, rg = t >> 4;
    float acc = 0.f;
    for (int r = rg; r < NR; r += 16)
        acc = fmaf(__ldg(g_cij + r * NC2 + c), g_uhat[(((size_t)b * NR + r) * NC2 + c) * 16 + o], acc);
    sred[t] = acc; __syncthreads();
    for (int st = 8; st >= 1; st >>= 1) { if (rg < st) sred[t] += sred[t + st * 16]; __syncthreads(); }
    if (rg == 0) {
        float s = sred[o];
        float v = s * fabsf(s) / (1.0f + s * s);
        g_v[(b * NC2 + c) * 16 + o] = v;
        if (out) out[(b * NC2 + c) * 16 + o] = v;
    }
}

__global__ void __launch_bounds__(128) k_aij() {
    __shared__ float sred[128];
    int r = blockIdx.x, c = blockIdx.y, t = threadIdx.x;
    int o = t & 15, bg = t >> 4;
    float acc = 0.f;
    for (int b = bg; b < NB; b += 8)
        acc = fmaf(g_uhat[(((size_t)b * NR + r) * NC2 + c) * 16 + o],
                   __ldg(g_v + (b * NC2 + c) * 16 + o), acc);
    sred[t] = acc; __syncthreads();
    for (int st = 64; st >= 1; st >>= 1) { if (t < st) sred[t] += sred[t + st]; __syncthreads(); }
    if (t == 0) g_bij[r * NC2 + c] += sred[0] * (1.0f / NB);
}

__global__ void __launch_bounds__(128) k_cls(const float* __restrict__ w1,
                                             const float* __restrict__ b1,
                                             const float* __restrict__ w2,
                                             const float* __restrict__ b2,
                                             float* out) {
    __shared__ float sfeat[160];
    __shared__ float sred[128];
    int b = blockIdx.x, k = blockIdx.y, t = threadIdx.x;
    for (int j = t; j < 160; j += 128) sfeat[j] = g_v[b * 160 + j];
    __syncthreads();
    float val = 0.f;
    if (t < 100) {
        float acc = __ldg(b1 + k * 100 + t);
        const float* wp = w1 + (size_t)k * 16000 + t;
#pragma unroll 4
        for (int f = 0; f < 160; f++) acc = fmaf(sfeat[f], wp[f * 100], acc);
        val = fmaxf(acc, 0.f) * __ldg(w2 + k * 100 + t);
    }
    sred[t] = val; __syncthreads();
    for (int st = 64; st >= 1; st >>= 1) { if (t < st) sred[t] += sred[t + st]; __syncthreads(); }
    if (t == 0)
        out[40960 + b * NC2 + k] = 1.0f / (1.0f + expf(-(sred[0] + __ldg(b2 + k))));
}

extern "C" void kernel_launch(void* const* d_in, const int* in_sizes, int n_in,
                              void* d_out, int out_size) {
    const float* data    = (const float*)d_in[0];
    const float* conv1_w = (const float*)d_in[1];
    const float* conv1_b = (const float*)d_in[2];
    const float* conv2_w = (const float*)d_in[3];
    const float* conv2_b = (const float*)d_in[4];
    const float* prim_w  = (const float*)d_in[5];
    const float* prim_b  = (const float*)d_in[6];
    const float* W       = (const float*)d_in[7];
    const float* cls_w1  = (const float*)d_in[8];
    const float* cls_b1  = (const float*)d_in[9];
    const float* cls_w2  = (const float*)d_in[10];
    const float* cls_b2  = (const float*)d_in[11];
    float* out = (float*)d_out;

    static int inited = 0;
    if (!inited) {
        cudaFuncSetAttribute(k_conv2mma, cudaFuncAttributeMaxDynamicSharedMemorySize, 2 * BUFB);
        cudaFuncSetAttribute(k_primmma, cudaFuncAttributeMaxDynamicSharedMemorySize, 2 * BUFB);
        inited = 1;
    }

    k_cvt_w2<<<288, 256>>>(conv2_w);
    k_cvt_pw<<<10368, 256>>>(prim_w);
    k_conv1pool<<<1444, 256>>>(data, conv1_w, conv1_b);
    k_conv2mma<<<dim3(12, NB), 256, 2 * BUFB>>>(conv2_b);
    k_pool2n<<<dim3(25, NB), 256>>>();
    k_primmma<<<dim3(72, 2, 3), 256, 2 * BUFB>>>();
    k_zero<<<45, 256>>>();
    k_squash<<<(NB * NR + 255) / 256, 256>>>(prim_b);
    k_uhat<<<NR, 160>>>(W);

    for (int it = 0; it < 3; it++) {
        k_softmax<<<NC2, 128>>>();
        k_sj<<<dim3(NB, NC2), 256>>>(it == 2 ? out : nullptr);
        if (it < 2) k_aij<<<dim3(NR, NC2), 128>>>();
    }
    k_cls<<<dim3(NB, NC2), 128>>>(cls_w1, cls_b1, cls_w2, cls_b2, out);
}

// round 12
// speedup vs baseline: 2.2246x; 1.2387x over previous
#include <cuda_runtime.h>
#include <cuda_bf16.h>
#include <math.h>
#include <stdint.h>

#define NB 256
#define NR 1152
#define NC2 10
#define LDA 40
#define BUFB 40960
#define BUFE 20480

__device__ __forceinline__ void mma16816(float* d, unsigned a0, unsigned a1, unsigned a2, unsigned a3,
                                         unsigned b0, unsigned b1) {
    asm volatile("mma.sync.aligned.m16n8k16.row.col.f32.bf16.bf16.f32 "
        "{%0,%1,%2,%3}, {%4,%5,%6,%7}, {%8,%9}, {%0,%1,%2,%3};"
        : "+f"(d[0]), "+f"(d[1]), "+f"(d[2]), "+f"(d[3])
        : "r"(a0), "r"(a1), "r"(a2), "r"(a3), "r"(b0), "r"(b1));
}
__device__ __forceinline__ void ldsm_x4(unsigned* r, uint32_t addr) {
    asm volatile("ldmatrix.sync.aligned.m8n8.x4.shared.b16 {%0,%1,%2,%3}, [%4];"
        : "=r"(r[0]), "=r"(r[1]), "=r"(r[2]), "=r"(r[3]) : "r"(addr));
}
__device__ __forceinline__ void bfsplit(float f, __nv_bfloat16& h, __nv_bfloat16& l) {
    h = __float2bfloat16(f);
    l = __float2bfloat16(f - __bfloat162float(h));
}
__device__ __forceinline__ unsigned packhl(float f) {
    __nv_bfloat16 h, l; bfsplit(f, h, l);
    return (unsigned)__bfloat16_as_ushort(h) | ((unsigned)__bfloat16_as_ushort(l) << 16);
}

// ---- scratch ----
__device__ unsigned g_p1p[(size_t)NB * 64 * 1444];
__device__ float g_c2[(size_t)NB * 1444 * 128];
__device__ unsigned g_p2p[(size_t)NB * 128 * 400];
__device__ __nv_bfloat16 g_w2h[128 * 576];
__device__ __nv_bfloat16 g_w2l[128 * 576];
__device__ __nv_bfloat16 g_pwh[(size_t)256 * 10368];
__device__ __nv_bfloat16 g_pwl[(size_t)256 * 10368];
__device__ float g_upart[(size_t)3 * NB * 9216];
__device__ float g_u[(size_t)NB * 9216];
__device__ float g_uhat[(size_t)NB * NR * NC2 * 16];
__device__ float g_bij[NR * NC2];
__device__ float g_cij[NR * NC2];
__device__ float g_v[NB * NC2 * 16];

__global__ void k_zero() {
    int i = blockIdx.x * blockDim.x + threadIdx.x;
    if (i < NR * NC2) g_bij[i] = 0.f;
}
__global__ void k_cvt_w2(const float* __restrict__ w2) {
    int i = blockIdx.x * blockDim.x + threadIdx.x;
    if (i >= 128 * 576) return;
    __nv_bfloat16 h, l; bfsplit(w2[i], h, l);
    g_w2h[i] = h; g_w2l[i] = l;
}
__global__ void k_cvt_pw(const float* __restrict__ pw) {
    int i = blockIdx.x * blockDim.x + threadIdx.x;
    __nv_bfloat16 h, l; bfsplit(pw[i], h, l);
    g_pwh[i] = h; g_pwl[i] = l;
}

// ---- conv1+relu+pool, packed output ----
__global__ void __launch_bounds__(256) k_conv1pool(const float* __restrict__ data,
                                                   const float* __restrict__ w1,
                                                   const float* __restrict__ b1) {
    int idx = blockIdx.x * blockDim.x + threadIdx.x;
    int p = idx % 1444, b = idx / 1444;
    int pj = p / 38, pi = p % 38;
    int y0 = 2 * pj - 1, x0 = 2 * pi - 1;
    float iv[3][4][4];
#pragma unroll
    for (int ic = 0; ic < 3; ic++)
#pragma unroll
        for (int dy = 0; dy < 4; dy++) {
            int yy = y0 + dy;
#pragma unroll
            for (int dx = 0; dx < 4; dx++) {
                int xx = x0 + dx;
                float v = 0.f;
                if (yy >= 0 && yy < 76 && xx >= 0 && xx < 76)
                    v = data[((size_t)(b * 3 + ic) * 76 + yy) * 76 + xx];
                iv[ic][dy][dx] = v;
            }
        }
    bool rv0 = (y0 >= 0), rv1 = (y0 + 1 <= 73), cv0 = (x0 >= 0), cv1 = (x0 + 1 <= 73);
    size_t obase = (size_t)b * 64 * 1444 + (size_t)pj * 38 + pi;
#pragma unroll 1
    for (int oc = 0; oc < 64; oc++) {
        const float* wp = w1 + oc * 27;
        float s00 = 0.f, s01 = 0.f, s10 = 0.f, s11 = 0.f;
#pragma unroll
        for (int k = 0; k < 27; k++) {
            int ic = k / 9, r = (k / 3) % 3, c2 = k % 3;
            float w = __ldg(wp + k);
            s00 = fmaf(iv[ic][r][c2], w, s00);
            s01 = fmaf(iv[ic][r][c2 + 1], w, s01);
            s10 = fmaf(iv[ic][r + 1][c2], w, s10);
            s11 = fmaf(iv[ic][r + 1][c2 + 1], w, s11);
        }
        float bo = __ldg(b1 + oc), m = 0.f;
        if (rv0 && cv0) m = fmaxf(m, s00 + bo);
        if (rv0 && cv1) m = fmaxf(m, s01 + bo);
        if (rv1 && cv0) m = fmaxf(m, s10 + bo);
        if (rv1 && cv1) m = fmaxf(m, s11 + bo);
        g_p1p[obase + (size_t)oc * 1444] = packhl(m);
    }
}

// ---- B staging via cp.async ----
__device__ __forceinline__ void stageB_cp(uint32_t dstb, const __nv_bfloat16* __restrict__ srcH,
                                          const __nv_bfloat16* __restrict__ srcL,
                                          int kc, int tid, int wstride, int nbase) {
#pragma unroll
    for (int q = 0; q < 4; q++) {
        int i = tid * 4 + q;
        int half = i >> 9;
        int n = (i & 511) >> 2;
        int seg = i & 3;
        const __nv_bfloat16* src = (half ? srcL : srcH) + (size_t)(nbase + n) * wstride + kc * 32 + seg * 8;
        uint32_t dst = dstb + (half ? 15360 * 2 : 10240 * 2) + ((unsigned)n * LDA + seg * 8) * 2;
        asm volatile("cp.async.ca.shared.global [%0], [%1], 16;" :: "r"(dst), "l"(src));
    }
    asm volatile("cp.async.commit_group;" ::: "memory");
}
__device__ __forceinline__ void cp_wait() {
    asm volatile("cp.async.wait_group 0;" ::: "memory");
}

// ---- gemm: warp tile M=32 x N=64 ----
__device__ __forceinline__ void gemm_chunk(float acc[16][4], uint32_t aH, uint32_t aL,
                                           uint32_t bH, uint32_t bL) {
#pragma unroll
    for (int ks = 0; ks < 2; ks++) {
        unsigned Ah[2][4], Al[2][4];
        ldsm_x4(Ah[0], aH + ks * 32);
        ldsm_x4(Ah[1], aH + 16 * LDA * 2 + ks * 32);
        ldsm_x4(Al[0], aL + ks * 32);
        ldsm_x4(Al[1], aL + 16 * LDA * 2 + ks * 32);
#pragma unroll
        for (int j = 0; j < 4; j++) {
            unsigned Bh[4], Bl[4];
            uint32_t bo = (uint32_t)j * (16 * LDA * 2) + ks * 32;
            ldsm_x4(Bh, bH + bo);
            ldsm_x4(Bl, bL + bo);
#pragma unroll
            for (int mt = 0; mt < 2; mt++) {
                int t0 = mt * 8 + j * 2;
                mma16816(acc[t0],     Ah[mt][0], Ah[mt][1], Ah[mt][2], Ah[mt][3], Bh[0], Bh[1]);
                mma16816(acc[t0],     Al[mt][0], Al[mt][1], Al[mt][2], Al[mt][3], Bh[0], Bh[1]);
                mma16816(acc[t0],     Ah[mt][0], Ah[mt][1], Ah[mt][2], Ah[mt][3], Bl[0], Bl[1]);
                mma16816(acc[t0 + 1], Ah[mt][0], Ah[mt][1], Ah[mt][2], Ah[mt][3], Bh[2], Bh[3]);
                mma16816(acc[t0 + 1], Al[mt][0], Al[mt][1], Al[mt][2], Al[mt][3], Bh[2], Bh[3]);
                mma16816(acc[t0 + 1], Ah[mt][0], Ah[mt][1], Ah[mt][2], Ah[mt][3], Bl[2], Bl[3]);
            }
        }
    }
}

// ---- conv2: double-buffered bf16x3 mma, 2 blocks/SM ----
__global__ void __launch_bounds__(256, 2) k_conv2mma(const float* __restrict__ b2) {
    extern __shared__ __nv_bfloat16 sm[];
    int tid = threadIdx.x;
    int w = tid >> 5, lane = tid & 31;
    int g = lane >> 2, tg = lane & 3;
    int wm = w & 3, wn = w >> 2;
    int bb = blockIdx.y, strip = blockIdx.x;

    uint32_t smb = (uint32_t)__cvta_generic_to_shared(sm);
    uint32_t aoff = ((unsigned)(wm * 32 + (lane & 15)) * LDA + ((lane & 16) ? 8 : 0)) * 2;
    uint32_t boff = ((unsigned)(wn * 64 + (lane & 7) + ((lane & 16) ? 8 : 0)) * LDA + ((lane & 8) ? 8 : 0)) * 2;

    float acc[16][4];
#pragma unroll
    for (int n = 0; n < 16; n++)
#pragma unroll
        for (int q = 0; q < 4; q++) acc[n][q] = 0.f;

    int mloc = tid & 127;
    int ubase = (tid >> 7) * 2;
    int pA = strip * 128 + mloc;
    int yA = pA / 38, xA = pA % 38;
    bool pvA = pA < 1444;
    const unsigned* srcp = g_p1p + (size_t)bb * 64 * 1444;

    auto stageA = [&](__nv_bfloat16* dst, int kc) {
        char* db = (char*)dst;
#pragma unroll
        for (int uu = 0; uu < 2; uu++) {
            int u = ubase + uu;
            int k = kc * 32 + u * 8;
            int ic = k / 9, r = k - ic * 9;
            int ky = r / 3, kx = r - ky * 3;
            unsigned hw[4], lw[4];
#pragma unroll
            for (int jj = 0; jj < 4; jj++) {
                unsigned p0 = 0, p1 = 0;
                {
                    int yy = yA + ky - 1, xx = xA + kx - 1;
                    if (pvA && yy >= 0 && yy < 38 && xx >= 0 && xx < 38)
                        p0 = srcp[ic * 1444 + yy * 38 + xx];
                    if (++kx == 3) { kx = 0; if (++ky == 3) { ky = 0; ic++; } }
                }
                {
                    int yy = yA + ky - 1, xx = xA + kx - 1;
                    if (pvA && yy >= 0 && yy < 38 && xx >= 0 && xx < 38)
                        p1 = srcp[ic * 1444 + yy * 38 + xx];
                    if (++kx == 3) { kx = 0; if (++ky == 3) { ky = 0; ic++; } }
                }
                hw[jj] = __byte_perm(p0, p1, 0x5410);
                lw[jj] = __byte_perm(p0, p1, 0x7632);
            }
            *(uint4*)(db + mloc * 80 + u * 16) = make_uint4(hw[0], hw[1], hw[2], hw[3]);
            *(uint4*)(db + 10240 + mloc * 80 + u * 16) = make_uint4(lw[0], lw[1], lw[2], lw[3]);
        }
    };

    stageA(sm, 0);
    stageB_cp(smb, g_w2h, g_w2l, 0, tid, 576, 0);
    cp_wait();
    __syncthreads();

#pragma unroll 1
    for (int kc = 0; kc < 18; kc++) {
        int par = kc & 1, nxt = kc + 1;
        if (nxt < 18) {
            stageA(sm + (nxt & 1) * BUFE, nxt);
            stageB_cp(smb + (nxt & 1) * BUFB, g_w2h, g_w2l, nxt, tid, 576, 0);
        }
        uint32_t base = smb + par * BUFB;
        gemm_chunk(acc, base + aoff, base + 10240 + aoff,
                        base + 20480 + boff, base + 30720 + boff);
        cp_wait();
        __syncthreads();
    }

#pragma unroll
    for (int mt = 0; mt < 2; mt++) {
        int p0 = strip * 128 + wm * 32 + mt * 16 + g;
        int p1 = p0 + 8;
#pragma unroll
        for (int j = 0; j < 4; j++)
#pragma unroll
            for (int h = 0; h < 2; h++) {
                int t = mt * 8 + j * 2 + h;
                int col = wn * 64 + j * 16 + h * 8 + tg * 2;
                float bc0 = __ldg(b2 + col), bc1 = __ldg(b2 + col + 1);
                if (p0 < 1444) {
                    float2 o; o.x = fmaxf(acc[t][0] + bc0, 0.f); o.y = fmaxf(acc[t][1] + bc1, 0.f);
                    *(float2*)(g_c2 + ((size_t)bb * 1444 + p0) * 128 + col) = o;
                }
                if (p1 < 1444) {
                    float2 o; o.x = fmaxf(acc[t][2] + bc0, 0.f); o.y = fmaxf(acc[t][3] + bc1, 0.f);
                    *(float2*)(g_c2 + ((size_t)bb * 1444 + p1) * 128 + col) = o;
                }
            }
    }
}

// ---- maxpool -> channel-major packed ----
__global__ void __launch_bounds__(256) k_pool2n() {
    __shared__ float s[16 * 129];
    int b = blockIdx.y, t0 = blockIdx.x;
    int tid = threadIdx.x;
    for (int i = tid; i < 2048; i += 256) {
        int p2l = i >> 7, oc = i & 127;
        int p2 = t0 * 16 + p2l;
        int pj = p2 / 20, pi = p2 % 20;
        int y0 = 2 * pj - 1, x0 = 2 * pi - 1;
        float m = 0.f;
#pragma unroll
        for (int dy = 0; dy < 2; dy++) {
            int y = y0 + dy; if (y < 0 || y > 37) continue;
#pragma unroll
            for (int dx = 0; dx < 2; dx++) {
                int x = x0 + dx; if (x < 0 || x > 37) continue;
                m = fmaxf(m, g_c2[((size_t)b * 1444 + y * 38 + x) * 128 + oc]);
            }
        }
        s[p2l * 129 + oc] = m;
    }
    __syncthreads();
    for (int i = tid; i < 2048; i += 256) {
        int oc = i >> 4, p2l = i & 15;
        g_p2p[((size_t)(b * 128 + oc)) * 400 + t0 * 16 + p2l] = packhl(s[p2l * 129 + oc]);
    }
}

// ---- PrimaryCaps: double-buffered, K-split x3, 2 blocks/SM ----
__global__ void __launch_bounds__(256, 2) k_primmma() {
    extern __shared__ __nv_bfloat16 sm[];
    int tid = threadIdx.x;
    int w = tid >> 5, lane = tid & 31;
    int g = lane >> 2, tg = lane & 3;
    int wm = w & 3, wn = w >> 2;
    int mb = blockIdx.x, ny = blockIdx.y, zz = blockIdx.z;

    uint32_t smb = (uint32_t)__cvta_generic_to_shared(sm);
    uint32_t aoff = ((unsigned)(wm * 32 + (lane & 15)) * LDA + ((lane & 16) ? 8 : 0)) * 2;
    uint32_t boff = ((unsigned)(wn * 64 + (lane & 7) + ((lane & 16) ? 8 : 0)) * LDA + ((lane & 8) ? 8 : 0)) * 2;

    float acc[16][4];
#pragma unroll
    for (int n = 0; n < 16; n++)
#pragma unroll
        for (int q = 0; q < 4; q++) acc[n][q] = 0.f;

    int mloc = tid & 127;
    int ubase = (tid >> 7) * 2;
    int mA = mb * 128 + mloc;
    int bA = mA / 36, posA = mA % 36;
    int sjA = posA / 6, siA = posA % 6;
    const unsigned* p2p = g_p2p + (size_t)bA * 51200;

    auto stageA = [&](__nv_bfloat16* dst, int kc) {
        char* db = (char*)dst;
#pragma unroll
        for (int uu = 0; uu < 2; uu++) {
            int u = ubase + uu;
            int k = kc * 32 + u * 8;
            int ic = k / 81, r = k - ic * 81;
            int ky = r / 9, kx = r - ky * 9;
            int off = ic * 400 + (2 * sjA + ky) * 20 + 2 * siA + kx;
            unsigned hw[4], lw[4];
#pragma unroll
            for (int jj = 0; jj < 4; jj++) {
                unsigned p0 = p2p[off];
                if (++kx == 9) { kx = 0; if (++ky == 9) { ky = 0; off += 232; } else off += 12; }
                else off++;
                unsigned p1 = p2p[off];
                if (++kx == 9) { kx = 0; if (++ky == 9) { ky = 0; off += 232; } else off += 12; }
                else off++;
                hw[jj] = __byte_perm(p0, p1, 0x5410);
                lw[jj] = __byte_perm(p0, p1, 0x7632);
            }
            *(uint4*)(db + mloc * 80 + u * 16) = make_uint4(hw[0], hw[1], hw[2], hw[3]);
            *(uint4*)(db + 10240 + mloc * 80 + u * 16) = make_uint4(lw[0], lw[1], lw[2], lw[3]);
        }
    };

    int kc0 = zz * 108, kc1 = kc0 + 108;
    stageA(sm, kc0);
    stageB_cp(smb, g_pwh, g_pwl, kc0, tid, 10368, ny * 128);
    cp_wait();
    __syncthreads();

#pragma unroll 1
    for (int kc = kc0; kc < kc1; kc++) {
        int par = kc & 1, nxt = kc + 1;
        if (nxt < kc1) {
            stageA(sm + (nxt & 1) * BUFE, nxt);
            stageB_cp(smb + (nxt & 1) * BUFB, g_pwh, g_pwl, nxt, tid, 10368, ny * 128);
        }
        uint32_t base = smb + par * BUFB;
        gemm_chunk(acc, base + aoff, base + 10240 + aoff,
                        base + 20480 + boff, base + 30720 + boff);
        cp_wait();
        __syncthreads();
    }

    float* up = g_upart + (size_t)zz * NB * 9216;
#pragma unroll
    for (int mt = 0; mt < 2; mt++) {
        int m0 = mb * 128 + wm * 32 + mt * 16 + g;
        int m1 = m0 + 8;
        int b0 = m0 / 36, pos0 = m0 % 36;
        int b1i = m1 / 36, pos1 = m1 % 36;
#pragma unroll
        for (int j = 0; j < 4; j++)
#pragma unroll
            for (int h = 0; h < 2; h++) {
                int t = mt * 8 + j * 2 + h;
                int col = ny * 128 + wn * 64 + j * 16 + h * 8 + tg * 2;
                up[(size_t)b0 * 9216 + (size_t)col * 36 + pos0] = acc[t][0];
                up[(size_t)b0 * 9216 + (size_t)(col + 1) * 36 + pos0] = acc[t][1];
                up[(size_t)b1i * 9216 + (size_t)col * 36 + pos1] = acc[t][2];
                up[(size_t)b1i * 9216 + (size_t)(col + 1) * 36 + pos1] = acc[t][3];
            }
    }
}

// ---- squash ----
__global__ void k_squash(const float* __restrict__ pb) {
    int idx = blockIdx.x * blockDim.x + threadIdx.x;
    if (idx >= NB * NR) return;
    int r = idx % NR;
    size_t base = (size_t)idx * 8;
    const size_t UP = (size_t)NB * 9216;
    float e[8];
    float sn = 0.f;
#pragma unroll
    for (int j = 0; j < 8; j++) {
        int oc = (r * 8 + j) / 36;
        float v = g_upart[base + j] + g_upart[UP + base + j] + g_upart[2 * UP + base + j]
                + __ldg(pb + oc);
        e[j] = v;
        sn = fmaf(v, v, sn);
    }
    float f = sqrtf(sn) / (1.0f + sn);
    float4 o0 = make_float4(e[0] * f, e[1] * f, e[2] * f, e[3] * f);
    float4 o1 = make_float4(e[4] * f, e[5] * f, e[6] * f, e[7] * f);
    float4* o = (float4*)(g_u + base);
    o[0] = o0; o[1] = o1;
}

__global__ void __launch_bounds__(160) k_uhat(const float* __restrict__ W) {
    __shared__ float sWT[1280];
    int r = blockIdx.x, t = threadIdx.x;
    for (int j = t; j < 1280; j += 160)
        sWT[j] = W[(size_t)r * 1280 + (j % 160) * 8 + j / 160];
    __syncthreads();
    float w0 = sWT[t], w1 = sWT[160+t], w2 = sWT[320+t], w3 = sWT[480+t];
    float w4 = sWT[640+t], w5 = sWT[800+t], w6 = sWT[960+t], w7 = sWT[1120+t];
#pragma unroll 4
    for (int b = 0; b < NB; b++) {
        const float4* up = (const float4*)(g_u + (size_t)b * 9216 + r * 8);
        float4 ua = up[0], ub = up[1];
        g_uhat[((size_t)b * NR + r) * 160 + t] =
            ua.x*w0 + ua.y*w1 + ua.z*w2 + ua.w*w3 + ub.x*w4 + ub.y*w5 + ub.z*w6 + ub.w*w7;
    }
}

__global__ void k_softmax() {
    __shared__ float sred[128];
    int c = blockIdx.x, t = threadIdx.x;
    float mx = -1e30f;
    for (int r = t; r < NR; r += 128) mx = fmaxf(mx, g_bij[r * NC2 + c]);
    sred[t] = mx; __syncthreads();
    for (int st = 64; st >= 1; st >>= 1) { if (t < st) sred[t] = fmaxf(sred[t], sred[t + st]); __syncthreads(); }
    mx = sred[0]; __syncthreads();
    float sm = 0.f;
    for (int r = t; r < NR; r += 128) sm += expf(g_bij[r * NC2 + c] - mx);
    sred[t] = sm; __syncthreads();
    for (int st = 64; st >= 1; st >>= 1) { if (t < st) sred[t] += sred[t + st]; __syncthreads(); }
    float inv = 1.0f / sred[0];
    for (int r = t; r < NR; r += 128)
        g_cij[r * NC2 + c] = expf(g_bij[r * NC2 + c] - mx) * inv;
}

__global__ void __launch_bounds__(256) k_sj(float* out) {
    __shared__ float sred[256];
    int b = blockIdx.x, c = blockIdx.y, t = threadIdx.x;
    int o = t & 15, rg = t >> 4;
    float acc = 0.f;
    for (int r = rg; r < NR; r += 16)
        acc = fmaf(__ldg(g_cij + r * NC2 + c), g_uhat[(((size_t)b * NR + r) * NC2 + c) * 16 + o], acc);
    sred[t] = acc; __syncthreads();
    for (int st = 8; st >= 1; st >>= 1) { if (rg < st) sred[t] += sred[t + st * 16]; __syncthreads(); }
    if (rg == 0) {
        float s = sred[o];
        float v = s * fabsf(s) / (1.0f + s * s);
        g_v[(b * NC2 + c) * 16 + o] = v;
        if (out) out[(b * NC2 + c) * 16 + o] = v;
    }
}

__global__ void __launch_bounds__(128) k_aij() {
    __shared__ float sred[128];
    int r = blockIdx.x, c = blockIdx.y, t = threadIdx.x;
    int o = t & 15, bg = t >> 4;
    float acc = 0.f;
    for (int b = bg; b < NB; b += 8)
        acc = fmaf(g_uhat[(((size_t)b * NR + r) * NC2 + c) * 16 + o],
                   __ldg(g_v + (b * NC2 + c) * 16 + o), acc);
    sred[t] = acc; __syncthreads();
    for (int st = 64; st >= 1; st >>= 1) { if (t < st) sred[t] += sred[t + st]; __syncthreads(); }
    if (t == 0) g_bij[r * NC2 + c] += sred[0] * (1.0f / NB);
}

__global__ void __launch_bounds__(128) k_cls(const float* __restrict__ w1,
                                             const float* __restrict__ b1,
                                             const float* __restrict__ w2,
                                             const float* __restrict__ b2,
                                             float* out) {
    __shared__ float sfeat[160];
    __shared__ float sred[128];
    int b = blockIdx.x, k = blockIdx.y, t = threadIdx.x;
    for (int j = t; j < 160; j += 128) sfeat[j] = g_v[b * 160 + j];
    __syncthreads();
    float val = 0.f;
    if (t < 100) {
        float acc = __ldg(b1 + k * 100 + t);
        const float* wp = w1 + (size_t)k * 16000 + t;
#pragma unroll 4
        for (int f = 0; f < 160; f++) acc = fmaf(sfeat[f], wp[f * 100], acc);
        val = fmaxf(acc, 0.f) * __ldg(w2 + k * 100 + t);
    }
    sred[t] = val; __syncthreads();
    for (int st = 64; st >= 1; st >>= 1) { if (t < st) sred[t] += sred[t + st]; __syncthreads(); }
    if (t == 0)
        out[40960 + b * NC2 + k] = 1.0f / (1.0f + expf(-(sred[0] + __ldg(b2 + k))));
}

extern "C" void kernel_launch(void* const* d_in, const int* in_sizes, int n_in,
                              void* d_out, int out_size) {
    const float* data    = (const float*)d_in[0];
    const float* conv1_w = (const float*)d_in[1];
    const float* conv1_b = (const float*)d_in[2];
    const float* conv2_w = (const float*)d_in[3];
    const float* conv2_b = (const float*)d_in[4];
    const float* prim_w  = (const float*)d_in[5];
    const float* prim_b  = (const float*)d_in[6];
    const float* W       = (const float*)d_in[7];
    const float* cls_w1  = (const float*)d_in[8];
    const float* cls_b1  = (const float*)d_in[9];
    const float* cls_w2  = (const float*)d_in[10];
    const float* cls_b2  = (const float*)d_in[11];
    float* out = (float*)d_out;

    static int inited = 0;
    if (!inited) {
        cudaFuncSetAttribute(k_conv2mma, cudaFuncAttributeMaxDynamicSharedMemorySize, 2 * BUFB);
        cudaFuncSetAttribute(k_primmma, cudaFuncAttributeMaxDynamicSharedMemorySize, 2 * BUFB);
        inited = 1;
    }

    k_cvt_w2<<<288, 256>>>(conv2_w);
    k_cvt_pw<<<10368, 256>>>(prim_w);
    k_conv1pool<<<1444, 256>>>(data, conv1_w, conv1_b);
    k_conv2mma<<<dim3(12, NB), 256, 2 * BUFB>>>(conv2_b);
    k_pool2n<<<dim3(25, NB), 256>>>();
    k_primmma<<<dim3(72, 2, 3), 256, 2 * BUFB>>>();
    k_zero<<<45, 256>>>();
    k_squash<<<(NB * NR + 255) / 256, 256>>>(prim_b);
    k_uhat<<<NR, 160>>>(W);

    for (int it = 0; it < 3; it++) {
        k_softmax<<<NC2, 128>>>();
        k_sj<<<dim3(NB, NC2), 256>>>(it == 2 ? out : nullptr);
        if (it < 2) k_aij<<<dim3(NR, NC2), 128>>>();
    }
    k_cls<<<dim3(NB, NC2), 128>>>(cls_w1, cls_b1, cls_w2, cls_b2, out);
}

// round 13
// speedup vs baseline: 2.3174x; 1.0417x over previous
#include <cuda_runtime.h>
#include <cuda_bf16.h>
#include <math.h>
#include <stdint.h>

#define NB 256
#define NR 1152
#define NC2 10
#define LDA 40
#define BUFB 40960
#define BUFE 20480

__device__ __forceinline__ void mma16816(float* d, unsigned a0, unsigned a1, unsigned a2, unsigned a3,
                                         unsigned b0, unsigned b1) {
    asm volatile("mma.sync.aligned.m16n8k16.row.col.f32.bf16.bf16.f32 "
        "{%0,%1,%2,%3}, {%4,%5,%6,%7}, {%8,%9}, {%0,%1,%2,%3};"
        : "+f"(d[0]), "+f"(d[1]), "+f"(d[2]), "+f"(d[3])
        : "r"(a0), "r"(a1), "r"(a2), "r"(a3), "r"(b0), "r"(b1));
}
__device__ __forceinline__ void ldsm_x4(unsigned* r, uint32_t addr) {
    asm volatile("ldmatrix.sync.aligned.m8n8.x4.shared.b16 {%0,%1,%2,%3}, [%4];"
        : "=r"(r[0]), "=r"(r[1]), "=r"(r[2]), "=r"(r[3]) : "r"(addr));
}
__device__ __forceinline__ void bfsplit(float f, __nv_bfloat16& h, __nv_bfloat16& l) {
    h = __float2bfloat16(f);
    l = __float2bfloat16(f - __bfloat162float(h));
}
__device__ __forceinline__ unsigned packhl(float f) {
    __nv_bfloat16 h, l; bfsplit(f, h, l);
    return (unsigned)__bfloat16_as_ushort(h) | ((unsigned)__bfloat16_as_ushort(l) << 16);
}

// ---- scratch ----
__device__ unsigned g_p1p[(size_t)NB * 64 * 1444];
__device__ float g_c2[(size_t)NB * 1444 * 128];
__device__ unsigned g_p2p[(size_t)NB * 128 * 400];
__device__ __nv_bfloat16 g_w2h[128 * 576];
__device__ __nv_bfloat16 g_w2l[128 * 576];
__device__ __nv_bfloat16 g_pwh[(size_t)256 * 10368];
__device__ __nv_bfloat16 g_pwl[(size_t)256 * 10368];
__device__ float g_upart[(size_t)4 * NB * 9216];
__device__ float g_u[(size_t)NB * 9216];
__device__ float4 g_uhat4[(size_t)NB * NR * NC2 * 4];
__device__ float g_bij[NR * NC2];
__device__ float g_cij[NR * NC2];
__device__ float4 g_v4[NB * NC2 * 4];
#define G_UHAT ((float*)g_uhat4)
#define G_V ((float*)g_v4)

__global__ void k_cvt_w2(const float* __restrict__ w2) {
    int i = blockIdx.x * blockDim.x + threadIdx.x;
    if (i >= 128 * 576) return;
    __nv_bfloat16 h, l; bfsplit(w2[i], h, l);
    g_w2h[i] = h; g_w2l[i] = l;
}
__global__ void k_cvt_pw(const float* __restrict__ pw) {
    int i = blockIdx.x * blockDim.x + threadIdx.x;
    __nv_bfloat16 h, l; bfsplit(pw[i], h, l);
    g_pwh[i] = h; g_pwl[i] = l;
}

// ---- conv1+relu+pool: smem weights, oc x2 unroll ----
__global__ void __launch_bounds__(256) k_conv1pool(const float* __restrict__ data,
                                                   const float* __restrict__ w1,
                                                   const float* __restrict__ b1) {
    __shared__ float sw[1728];
    __shared__ float sb[64];
    int tid = threadIdx.x;
    for (int i = tid; i < 1728; i += 256) sw[i] = w1[i];
    if (tid < 64) sb[tid] = b1[tid];
    __syncthreads();

    int idx = blockIdx.x * blockDim.x + tid;
    int p = idx % 1444, b = idx / 1444;
    int pj = p / 38, pi = p % 38;
    int y0 = 2 * pj - 1, x0 = 2 * pi - 1;
    float iv[3][4][4];
#pragma unroll
    for (int ic = 0; ic < 3; ic++)
#pragma unroll
        for (int dy = 0; dy < 4; dy++) {
            int yy = y0 + dy;
#pragma unroll
            for (int dx = 0; dx < 4; dx++) {
                int xx = x0 + dx;
                float v = 0.f;
                if (yy >= 0 && yy < 76 && xx >= 0 && xx < 76)
                    v = data[((size_t)(b * 3 + ic) * 76 + yy) * 76 + xx];
                iv[ic][dy][dx] = v;
            }
        }
    bool rv0 = (y0 >= 0), rv1 = (y0 + 1 <= 73), cv0 = (x0 >= 0), cv1 = (x0 + 1 <= 73);
    size_t obase = (size_t)b * 64 * 1444 + (size_t)pj * 38 + pi;
#pragma unroll 1
    for (int oc = 0; oc < 64; oc += 2) {
        const float* wa = sw + oc * 27;
        const float* wb = wa + 27;
        float a00 = 0.f, a01 = 0.f, a10 = 0.f, a11 = 0.f;
        float c00 = 0.f, c01 = 0.f, c10 = 0.f, c11 = 0.f;
#pragma unroll
        for (int k = 0; k < 27; k++) {
            int ic = k / 9, r = (k / 3) % 3, c2 = k % 3;
            float v00 = iv[ic][r][c2], v01 = iv[ic][r][c2 + 1];
            float v10 = iv[ic][r + 1][c2], v11 = iv[ic][r + 1][c2 + 1];
            float wA = wa[k], wB = wb[k];
            a00 = fmaf(v00, wA, a00); a01 = fmaf(v01, wA, a01);
            a10 = fmaf(v10, wA, a10); a11 = fmaf(v11, wA, a11);
            c00 = fmaf(v00, wB, c00); c01 = fmaf(v01, wB, c01);
            c10 = fmaf(v10, wB, c10); c11 = fmaf(v11, wB, c11);
        }
        float boA = sb[oc], boB = sb[oc + 1];
        float mA = 0.f, mB = 0.f;
        if (rv0 && cv0) { mA = fmaxf(mA, a00 + boA); mB = fmaxf(mB, c00 + boB); }
        if (rv0 && cv1) { mA = fmaxf(mA, a01 + boA); mB = fmaxf(mB, c01 + boB); }
        if (rv1 && cv0) { mA = fmaxf(mA, a10 + boA); mB = fmaxf(mB, c10 + boB); }
        if (rv1 && cv1) { mA = fmaxf(mA, a11 + boA); mB = fmaxf(mB, c11 + boB); }
        g_p1p[obase + (size_t)oc * 1444] = packhl(mA);
        g_p1p[obase + (size_t)(oc + 1) * 1444] = packhl(mB);
    }
}

// ---- B staging via cp.async ----
__device__ __forceinline__ void stageB_cp(uint32_t dstb, const __nv_bfloat16* __restrict__ srcH,
                                          const __nv_bfloat16* __restrict__ srcL,
                                          int kc, int tid, int wstride, int nbase) {
#pragma unroll
    for (int q = 0; q < 4; q++) {
        int i = tid * 4 + q;
        int half = i >> 9;
        int n = (i & 511) >> 2;
        int seg = i & 3;
        const __nv_bfloat16* src = (half ? srcL : srcH) + (size_t)(nbase + n) * wstride + kc * 32 + seg * 8;
        uint32_t dst = dstb + (half ? 15360 * 2 : 10240 * 2) + ((unsigned)n * LDA + seg * 8) * 2;
        asm volatile("cp.async.ca.shared.global [%0], [%1], 16;" :: "r"(dst), "l"(src));
    }
    asm volatile("cp.async.commit_group;" ::: "memory");
}
__device__ __forceinline__ void cp_wait() {
    asm volatile("cp.async.wait_group 0;" ::: "memory");
}

// ---- gemm: warp tile M=32 x N=64 ----
__device__ __forceinline__ void gemm_chunk(float acc[16][4], uint32_t aH, uint32_t aL,
                                           uint32_t bH, uint32_t bL) {
#pragma unroll
    for (int ks = 0; ks < 2; ks++) {
        unsigned Ah[2][4], Al[2][4];
        ldsm_x4(Ah[0], aH + ks * 32);
        ldsm_x4(Ah[1], aH + 16 * LDA * 2 + ks * 32);
        ldsm_x4(Al[0], aL + ks * 32);
        ldsm_x4(Al[1], aL + 16 * LDA * 2 + ks * 32);
#pragma unroll
        for (int j = 0; j < 4; j++) {
            unsigned Bh[4], Bl[4];
            uint32_t bo = (uint32_t)j * (16 * LDA * 2) + ks * 32;
            ldsm_x4(Bh, bH + bo);
            ldsm_x4(Bl, bL + bo);
#pragma unroll
            for (int mt = 0; mt < 2; mt++) {
                int t0 = mt * 8 + j * 2;
                mma16816(acc[t0],     Ah[mt][0], Ah[mt][1], Ah[mt][2], Ah[mt][3], Bh[0], Bh[1]);
                mma16816(acc[t0],     Al[mt][0], Al[mt][1], Al[mt][2], Al[mt][3], Bh[0], Bh[1]);
                mma16816(acc[t0],     Ah[mt][0], Ah[mt][1], Ah[mt][2], Ah[mt][3], Bl[0], Bl[1]);
                mma16816(acc[t0 + 1], Ah[mt][0], Ah[mt][1], Ah[mt][2], Ah[mt][3], Bh[2], Bh[3]);
                mma16816(acc[t0 + 1], Al[mt][0], Al[mt][1], Al[mt][2], Al[mt][3], Bh[2], Bh[3]);
                mma16816(acc[t0 + 1], Ah[mt][0], Ah[mt][1], Ah[mt][2], Ah[mt][3], Bl[2], Bl[3]);
            }
        }
    }
}

// ---- conv2: double-buffered bf16x3 mma, 2 blocks/SM ----
__global__ void __launch_bounds__(256, 2) k_conv2mma(const float* __restrict__ b2) {
    extern __shared__ __nv_bfloat16 sm[];
    int tid = threadIdx.x;
    int w = tid >> 5, lane = tid & 31;
    int g = lane >> 2, tg = lane & 3;
    int wm = w & 3, wn = w >> 2;
    int bb = blockIdx.y, strip = blockIdx.x;

    uint32_t smb = (uint32_t)__cvta_generic_to_shared(sm);
    uint32_t aoff = ((unsigned)(wm * 32 + (lane & 15)) * LDA + ((lane & 16) ? 8 : 0)) * 2;
    uint32_t boff = ((unsigned)(wn * 64 + (lane & 7) + ((lane & 16) ? 8 : 0)) * LDA + ((lane & 8) ? 8 : 0)) * 2;

    float acc[16][4];
#pragma unroll
    for (int n = 0; n < 16; n++)
#pragma unroll
        for (int q = 0; q < 4; q++) acc[n][q] = 0.f;

    int mloc = tid & 127;
    int ubase = (tid >> 7) * 2;
    int pA = strip * 128 + mloc;
    int yA = pA / 38, xA = pA % 38;
    bool pvA = pA < 1444;
    const unsigned* srcp = g_p1p + (size_t)bb * 64 * 1444;

    auto stageA = [&](__nv_bfloat16* dst, int kc) {
        char* db = (char*)dst;
#pragma unroll
        for (int uu = 0; uu < 2; uu++) {
            int u = ubase + uu;
            int k = kc * 32 + u * 8;
            int ic = k / 9, r = k - ic * 9;
            int ky = r / 3, kx = r - ky * 3;
            unsigned hw[4], lw[4];
#pragma unroll
            for (int jj = 0; jj < 4; jj++) {
                unsigned p0 = 0, p1 = 0;
                {
                    int yy = yA + ky - 1, xx = xA + kx - 1;
                    if (pvA && yy >= 0 && yy < 38 && xx >= 0 && xx < 38)
                        p0 = srcp[ic * 1444 + yy * 38 + xx];
                    if (++kx == 3) { kx = 0; if (++ky == 3) { ky = 0; ic++; } }
                }
                {
                    int yy = yA + ky - 1, xx = xA + kx - 1;
                    if (pvA && yy >= 0 && yy < 38 && xx >= 0 && xx < 38)
                        p1 = srcp[ic * 1444 + yy * 38 + xx];
                    if (++kx == 3) { kx = 0; if (++ky == 3) { ky = 0; ic++; } }
                }
                hw[jj] = __byte_perm(p0, p1, 0x5410);
                lw[jj] = __byte_perm(p0, p1, 0x7632);
            }
            *(uint4*)(db + mloc * 80 + u * 16) = make_uint4(hw[0], hw[1], hw[2], hw[3]);
            *(uint4*)(db + 10240 + mloc * 80 + u * 16) = make_uint4(lw[0], lw[1], lw[2], lw[3]);
        }
    };

    stageA(sm, 0);
    stageB_cp(smb, g_w2h, g_w2l, 0, tid, 576, 0);
    cp_wait();
    __syncthreads();

#pragma unroll 1
    for (int kc = 0; kc < 18; kc++) {
        int par = kc & 1, nxt = kc + 1;
        if (nxt < 18) {
            stageA(sm + (nxt & 1) * BUFE, nxt);
            stageB_cp(smb + (nxt & 1) * BUFB, g_w2h, g_w2l, nxt, tid, 576, 0);
        }
        uint32_t base = smb + par * BUFB;
        gemm_chunk(acc, base + aoff, base + 10240 + aoff,
                        base + 20480 + boff, base + 30720 + boff);
        cp_wait();
        __syncthreads();
    }

#pragma unroll
    for (int mt = 0; mt < 2; mt++) {
        int p0 = strip * 128 + wm * 32 + mt * 16 + g;
        int p1 = p0 + 8;
#pragma unroll
        for (int j = 0; j < 4; j++)
#pragma unroll
            for (int h = 0; h < 2; h++) {
                int t = mt * 8 + j * 2 + h;
                int col = wn * 64 + j * 16 + h * 8 + tg * 2;
                float bc0 = __ldg(b2 + col), bc1 = __ldg(b2 + col + 1);
                if (p0 < 1444) {
                    float2 o; o.x = fmaxf(acc[t][0] + bc0, 0.f); o.y = fmaxf(acc[t][1] + bc1, 0.f);
                    *(float2*)(g_c2 + ((size_t)bb * 1444 + p0) * 128 + col) = o;
                }
                if (p1 < 1444) {
                    float2 o; o.x = fmaxf(acc[t][2] + bc0, 0.f); o.y = fmaxf(acc[t][3] + bc1, 0.f);
                    *(float2*)(g_c2 + ((size_t)bb * 1444 + p1) * 128 + col) = o;
                }
            }
    }
}

// ---- maxpool -> channel-major packed ----
__global__ void __launch_bounds__(256) k_pool2n() {
    __shared__ float s[16 * 129];
    int b = blockIdx.y, t0 = blockIdx.x;
    int tid = threadIdx.x;
    for (int i = tid; i < 2048; i += 256) {
        int p2l = i >> 7, oc = i & 127;
        int p2 = t0 * 16 + p2l;
        int pj = p2 / 20, pi = p2 % 20;
        int y0 = 2 * pj - 1, x0 = 2 * pi - 1;
        float m = 0.f;
#pragma unroll
        for (int dy = 0; dy < 2; dy++) {
            int y = y0 + dy; if (y < 0 || y > 37) continue;
#pragma unroll
            for (int dx = 0; dx < 2; dx++) {
                int x = x0 + dx; if (x < 0 || x > 37) continue;
                m = fmaxf(m, g_c2[((size_t)b * 1444 + y * 38 + x) * 128 + oc]);
            }
        }
        s[p2l * 129 + oc] = m;
    }
    __syncthreads();
    for (int i = tid; i < 2048; i += 256) {
        int oc = i >> 4, p2l = i & 15;
        g_p2p[((size_t)(b * 128 + oc)) * 400 + t0 * 16 + p2l] = packhl(s[p2l * 129 + oc]);
    }
}

// ---- PrimaryCaps: double-buffered, K-split x4, 2 blocks/SM ----
__global__ void __launch_bounds__(256, 2) k_primmma() {
    extern __shared__ __nv_bfloat16 sm[];
    int tid = threadIdx.x;
    int w = tid >> 5, lane = tid & 31;
    int g = lane >> 2, tg = lane & 3;
    int wm = w & 3, wn = w >> 2;
    int mb = blockIdx.x, ny = blockIdx.y, zz = blockIdx.z;

    uint32_t smb = (uint32_t)__cvta_generic_to_shared(sm);
    uint32_t aoff = ((unsigned)(wm * 32 + (lane & 15)) * LDA + ((lane & 16) ? 8 : 0)) * 2;
    uint32_t boff = ((unsigned)(wn * 64 + (lane & 7) + ((lane & 16) ? 8 : 0)) * LDA + ((lane & 8) ? 8 : 0)) * 2;

    float acc[16][4];
#pragma unroll
    for (int n = 0; n < 16; n++)
#pragma unroll
        for (int q = 0; q < 4; q++) acc[n][q] = 0.f;

    int mloc = tid & 127;
    int ubase = (tid >> 7) * 2;
    int mA = mb * 128 + mloc;
    int bA = mA / 36, posA = mA % 36;
    int sjA = posA / 6, siA = posA % 6;
    const unsigned* p2p = g_p2p + (size_t)bA * 51200;

    auto stageA = [&](__nv_bfloat16* dst, int kc) {
        char* db = (char*)dst;
#pragma unroll
        for (int uu = 0; uu < 2; uu++) {
            int u = ubase + uu;
            int k = kc * 32 + u * 8;
            int ic = k / 81, r = k - ic * 81;
            int ky = r / 9, kx = r - ky * 9;
            int off = ic * 400 + (2 * sjA + ky) * 20 + 2 * siA + kx;
            unsigned hw[4], lw[4];
#pragma unroll
            for (int jj = 0; jj < 4; jj++) {
                unsigned p0 = p2p[off];
                if (++kx == 9) { kx = 0; if (++ky == 9) { ky = 0; off += 232; } else off += 12; }
                else off++;
                unsigned p1 = p2p[off];
                if (++kx == 9) { kx = 0; if (++ky == 9) { ky = 0; off += 232; } else off += 12; }
                else off++;
                hw[jj] = __byte_perm(p0, p1, 0x5410);
                lw[jj] = __byte_perm(p0, p1, 0x7632);
            }
            *(uint4*)(db + mloc * 80 + u * 16) = make_uint4(hw[0], hw[1], hw[2], hw[3]);
            *(uint4*)(db + 10240 + mloc * 80 + u * 16) = make_uint4(lw[0], lw[1], lw[2], lw[3]);
        }
    };

    int kc0 = zz * 81, kc1 = kc0 + 81;
    stageA(sm, kc0);
    stageB_cp(smb, g_pwh, g_pwl, kc0, tid, 10368, ny * 128);
    cp_wait();
    __syncthreads();

#pragma unroll 1
    for (int kc = kc0; kc < kc1; kc++) {
        int par = (kc - kc0) & 1, nxt = kc + 1;
        if (nxt < kc1) {
            stageA(sm + ((nxt - kc0) & 1) * BUFE, nxt);
            stageB_cp(smb + ((nxt - kc0) & 1) * BUFB, g_pwh, g_pwl, nxt, tid, 10368, ny * 128);
        }
        uint32_t base = smb + par * BUFB;
        gemm_chunk(acc, base + aoff, base + 10240 + aoff,
                        base + 20480 + boff, base + 30720 + boff);
        cp_wait();
        __syncthreads();
    }

    float* up = g_upart + (size_t)zz * NB * 9216;
#pragma unroll
    for (int mt = 0; mt < 2; mt++) {
        int m0 = mb * 128 + wm * 32 + mt * 16 + g;
        int m1 = m0 + 8;
        int b0 = m0 / 36, pos0 = m0 % 36;
        int b1i = m1 / 36, pos1 = m1 % 36;
#pragma unroll
        for (int j = 0; j < 4; j++)
#pragma unroll
            for (int h = 0; h < 2; h++) {
                int t = mt * 8 + j * 2 + h;
                int col = ny * 128 + wn * 64 + j * 16 + h * 8 + tg * 2;
                up[(size_t)b0 * 9216 + (size_t)col * 36 + pos0] = acc[t][0];
                up[(size_t)b0 * 9216 + (size_t)(col + 1) * 36 + pos0] = acc[t][1];
                up[(size_t)b1i * 9216 + (size_t)col * 36 + pos1] = acc[t][2];
                up[(size_t)b1i * 9216 + (size_t)(col + 1) * 36 + pos1] = acc[t][3];
            }
    }
}

// ---- squash: sum 4 K-slices + bias ----
__global__ void k_squash(const float* __restrict__ pb) {
    int idx = blockIdx.x * blockDim.x + threadIdx.x;
    if (idx >= NB * NR) return;
    int r = idx % NR;
    size_t base = (size_t)idx * 8;
    const size_t UP = (size_t)NB * 9216;
    float e[8];
    float sn = 0.f;
#pragma unroll
    for (int j = 0; j < 8; j++) {
        int oc = (r * 8 + j) / 36;
        float v = g_upart[base + j] + g_upart[UP + base + j]
                + g_upart[2 * UP + base + j] + g_upart[3 * UP + base + j]
                + __ldg(pb + oc);
        e[j] = v;
        sn = fmaf(v, v, sn);
    }
    float f = sqrtf(sn) / (1.0f + sn);
    float4 o0 = make_float4(e[0] * f, e[1] * f, e[2] * f, e[3] * f);
    float4 o1 = make_float4(e[4] * f, e[5] * f, e[6] * f, e[7] * f);
    float4* o = (float4*)(g_u + base);
    o[0] = o0; o[1] = o1;
}

__global__ void __launch_bounds__(160) k_uhat(const float* __restrict__ W) {
    __shared__ float sWT[1280];
    int r = blockIdx.x, t = threadIdx.x;
    for (int j = t; j < 1280; j += 160)
        sWT[j] = W[(size_t)r * 1280 + (j % 160) * 8 + j / 160];
    __syncthreads();
    float w0 = sWT[t], w1 = sWT[160+t], w2 = sWT[320+t], w3 = sWT[480+t];
    float w4 = sWT[640+t], w5 = sWT[800+t], w6 = sWT[960+t], w7 = sWT[1120+t];
#pragma unroll 4
    for (int b = 0; b < NB; b++) {
        const float4* up = (const float4*)(g_u + (size_t)b * 9216 + r * 8);
        float4 ua = up[0], ub = up[1];
        G_UHAT[((size_t)b * NR + r) * 160 + t] =
            ua.x*w0 + ua.y*w1 + ua.z*w2 + ua.w*w3 + ub.x*w4 + ub.y*w5 + ub.z*w6 + ub.w*w7;
    }
}

__global__ void k_softmax() {
    __shared__ float sred[128];
    int c = blockIdx.x, t = threadIdx.x;
    float mx = -1e30f;
    for (int r = t; r < NR; r += 128) mx = fmaxf(mx, g_bij[r * NC2 + c]);
    sred[t] = mx; __syncthreads();
    for (int st = 64; st >= 1; st >>= 1) { if (t < st) sred[t] = fmaxf(sred[t], sred[t + st]); __syncthreads(); }
    mx = sred[0]; __syncthreads();
    float sm = 0.f;
    for (int r = t; r < NR; r += 128) sm += expf(g_bij[r * NC2 + c] - mx);
    sred[t] = sm; __syncthreads();
    for (int st = 64; st >= 1; st >>= 1) { if (t < st) sred[t] += sred[t + st]; __syncthreads(); }
    float inv = 1.0f / sred[0];
    for (int r = t; r < NR; r += 128)
        g_cij[r * NC2 + c] = expf(g_bij[r * NC2 + c] - mx) * inv;
}

// ---- s_j + elementwise squash -> v; float4 loads; iter0 uniform c ----
__global__ void __launch_bounds__(256) k_sj(float* out, int it) {
    __shared__ float4 sred[64][4];
    int b = blockIdx.x, c = blockIdx.y, t = threadIdx.x;
    int og = t & 3, rg = t >> 2;                 // rg 0..63
    float4 acc = make_float4(0.f, 0.f, 0.f, 0.f);
    if (it == 0) {
        for (int r = rg; r < NR; r += 64) {
            float4 u4 = g_uhat4[(((size_t)b * NR + r) * NC2 + c) * 4 + og];
            acc.x += u4.x; acc.y += u4.y; acc.z += u4.z; acc.w += u4.w;
        }
        const float s = 1.0f / NR;
        acc.x *= s; acc.y *= s; acc.z *= s; acc.w *= s;
    } else {
        for (int r = rg; r < NR; r += 64) {
            float cij = __ldg(g_cij + r * NC2 + c);
            float4 u4 = g_uhat4[(((size_t)b * NR + r) * NC2 + c) * 4 + og];
            acc.x = fmaf(cij, u4.x, acc.x); acc.y = fmaf(cij, u4.y, acc.y);
            acc.z = fmaf(cij, u4.z, acc.z); acc.w = fmaf(cij, u4.w, acc.w);
        }
    }
    sred[rg][og] = acc;
    __syncthreads();
    for (int st = 32; st >= 1; st >>= 1) {
        if (rg < st) {
            float4 o4 = sred[rg + st][og];
            acc.x += o4.x; acc.y += o4.y; acc.z += o4.z; acc.w += o4.w;
            sred[rg][og] = acc;
        }
        __syncthreads();
    }
    if (rg == 0) {
        float4 v;
        v.x = acc.x * fabsf(acc.x) / (1.f + acc.x * acc.x);
        v.y = acc.y * fabsf(acc.y) / (1.f + acc.y * acc.y);
        v.z = acc.z * fabsf(acc.z) / (1.f + acc.z * acc.z);
        v.w = acc.w * fabsf(acc.w) / (1.f + acc.w * acc.w);
        g_v4[(b * NC2 + c) * 4 + og] = v;
        if (out) ((float4*)out)[(b * NC2 + c) * 4 + og] = v;
    }
}

// ---- a_ij via float4; first call overwrites b_ij ----
__global__ void __launch_bounds__(256) k_aij(int first) {
    __shared__ float sred[256];
    int r = blockIdx.x, c = blockIdx.y, t = threadIdx.x;
    int og = t & 3, bg = t >> 2;                 // bg 0..63
    float acc = 0.f;
    for (int b = bg; b < NB; b += 64) {
        float4 u4 = g_uhat4[(((size_t)b * NR + r) * NC2 + c) * 4 + og];
        float4 v4 = g_v4[(b * NC2 + c) * 4 + og];
        acc += u4.x * v4.x + u4.y * v4.y + u4.z * v4.z + u4.w * v4.w;
    }
    sred[t] = acc; __syncthreads();
    for (int st = 128; st >= 1; st >>= 1) { if (t < st) sred[t] += sred[t + st]; __syncthreads(); }
    if (t == 0) {
        float a = sred[0] * (1.0f / NB);
        if (first) g_bij[r * NC2 + c] = a;
        else g_bij[r * NC2 + c] += a;
    }
}

__global__ void __launch_bounds__(128) k_cls(const float* __restrict__ w1,
                                             const float* __restrict__ b1,
                                             const float* __restrict__ w2,
                                             const float* __restrict__ b2,
                                             float* out) {
    __shared__ float sfeat[160];
    __shared__ float sred[128];
    int b = blockIdx.x, k = blockIdx.y, t = threadIdx.x;
    for (int j = t; j < 160; j += 128) sfeat[j] = G_V[b * 160 + j];
    __syncthreads();
    float val = 0.f;
    if (t < 100) {
        float acc = __ldg(b1 + k * 100 + t);
        const float* wp = w1 + (size_t)k * 16000 + t;
#pragma unroll 4
        for (int f = 0; f < 160; f++) acc = fmaf(sfeat[f], wp[f * 100], acc);
        val = fmaxf(acc, 0.f) * __ldg(w2 + k * 100 + t);
    }
    sred[t] = val; __syncthreads();
    for (int st = 64; st >= 1; st >>= 1) { if (t < st) sred[t] += sred[t + st]; __syncthreads(); }
    if (t == 0)
        out[40960 + b * NC2 + k] = 1.0f / (1.0f + expf(-(sred[0] + __ldg(b2 + k))));
}

extern "C" void kernel_launch(void* const* d_in, const int* in_sizes, int n_in,
                              void* d_out, int out_size) {
    const float* data    = (const float*)d_in[0];
    const float* conv1_w = (const float*)d_in[1];
    const float* conv1_b = (const float*)d_in[2];
    const float* conv2_w = (const float*)d_in[3];
    const float* conv2_b = (const float*)d_in[4];
    const float* prim_w  = (const float*)d_in[5];
    const float* prim_b  = (const float*)d_in[6];
    const float* W       = (const float*)d_in[7];
    const float* cls_w1  = (const float*)d_in[8];
    const float* cls_b1  = (const float*)d_in[9];
    const float* cls_w2  = (const float*)d_in[10];
    const float* cls_b2  = (const float*)d_in[11];
    float* out = (float*)d_out;

    static int inited = 0;
    if (!inited) {
        cudaFuncSetAttribute(k_conv2mma, cudaFuncAttributeMaxDynamicSharedMemorySize, 2 * BUFB);
        cudaFuncSetAttribute(k_primmma, cudaFuncAttributeMaxDynamicSharedMemorySize, 2 * BUFB);
        inited = 1;
    }

    k_cvt_w2<<<288, 256>>>(conv2_w);
    k_cvt_pw<<<10368, 256>>>(prim_w);
    k_conv1pool<<<1444, 256>>>(data, conv1_w, conv1_b);
    k_conv2mma<<<dim3(12, NB), 256, 2 * BUFB>>>(conv2_b);
    k_pool2n<<<dim3(25, NB), 256>>>();
    k_primmma<<<dim3(72, 2, 4), 256, 2 * BUFB>>>();
    k_squash<<<(NB * NR + 255) / 256, 256>>>(prim_b);
    k_uhat<<<NR, 160>>>(W);

    for (int it = 0; it < 3; it++) {
        if (it > 0) k_softmax<<<NC2, 128>>>();
        k_sj<<<dim3(NB, NC2), 256>>>(it == 2 ? out : nullptr, it);
        if (it < 2) k_aij<<<dim3(NR, NC2), 256>>>(it == 0 ? 1 : 0);
    }
    k_cls<<<dim3(NB, NC2), 128>>>(cls_w1, cls_b1, cls_w2, cls_b2, out);
}